// round 4
// baseline (speedup 1.0000x reference)
#include <cuda_runtime.h>
#include <math.h>
#include <stdint.h>

constexpr long MTOK  = 16 * 512;     // 8192 tokens

// ---------------------------------------------------------------------------
// Scratch arena
// ---------------------------------------------------------------------------
constexpr long OFF_X    = 0;
constexpr long OFF_LN   = OFF_X    + MTOK * 256;
constexpr long OFF_B256 = OFF_LN   + MTOK * 256;
constexpr long OFF_U    = OFF_B256 + MTOK * 256;
constexpr long OFF_XZ   = OFF_U    + 2 * MTOK * 128;
constexpr long OFF_XC   = OFF_XZ   + 2 * MTOK * 512;
constexpr long OFF_DBC  = OFF_XC   + 2 * MTOK * 256;
constexpr long OFF_DT   = OFF_DBC  + 2 * MTOK * 40;
constexpr long OFF_Y    = OFF_DT   + 2 * MTOK * 256;
constexpr long OFF_CAT  = OFF_Y    + 2 * MTOK * 256;
constexpr long OFF_FF   = OFF_CAT  + MTOK * 256;
constexpr long TOTAL_F  = OFF_FF   + MTOK * 1024;

__device__ float g_buf[TOTAL_F];

// ---------------------------------------------------------------------------
// Block-wide sum over 256 threads
// ---------------------------------------------------------------------------
__device__ __forceinline__ float blockSum256(float v, float* sbuf)
{
#pragma unroll
    for (int o = 16; o > 0; o >>= 1)
        v += __shfl_xor_sync(0xffffffffu, v, o);
    __syncthreads();
    if ((threadIdx.x & 31) == 0) sbuf[threadIdx.x >> 5] = v;
    __syncthreads();
    float s = sbuf[0];
#pragma unroll
    for (int i = 1; i < 8; i++) s += sbuf[i];
    return s;
}

// ---------------------------------------------------------------------------
// Embedding: x = LN(ids @ proj_w + proj_b)
// ---------------------------------------------------------------------------
__global__ void embed_ln_kernel(const float* __restrict__ ids,
                                const float* __restrict__ pw,
                                const float* __restrict__ pb,
                                const float* __restrict__ gam,
                                const float* __restrict__ bet,
                                float* __restrict__ x)
{
    __shared__ float sin[32];
    __shared__ float sred[8];
    int m = blockIdx.x, d = threadIdx.x;
    if (d < 32) sin[d] = ids[(long)m * 32 + d];
    __syncthreads();
    float v = pb[d];
#pragma unroll
    for (int e = 0; e < 32; e++)
        v = fmaf(sin[e], pw[e * 256 + d], v);
    float mean = blockSum256(v, sred) * (1.f / 256.f);
    float c = v - mean;
    float var = blockSum256(c * c, sred) * (1.f / 256.f);
    x[(long)m * 256 + d] = c * rsqrtf(var + 1e-5f) * gam[d] + bet[d];
}

// ---------------------------------------------------------------------------
// LayerNorm over D=256, optional residual
// ---------------------------------------------------------------------------
__global__ void ln_kernel(const float* __restrict__ in,
                          const float* __restrict__ res,
                          const float* __restrict__ gam,
                          const float* __restrict__ bet,
                          float* __restrict__ out)
{
    __shared__ float sred[8];
    int m = blockIdx.x, d = threadIdx.x;
    float v = in[(long)m * 256 + d];
    if (res) v += res[(long)m * 256 + d];
    float mean = blockSum256(v, sred) * (1.f / 256.f);
    float c = v - mean;
    float var = blockSum256(c * c, sred) * (1.f / 256.f);
    out[(long)m * 256 + d] = c * rsqrtf(var + 1e-5f) * gam[d] + bet[d];
}

// ---------------------------------------------------------------------------
// TF32 tensor-core GEMM (Round-2 proven core, template-specialized epilogue).
// M%128==0, N%128==0, K%16==0, lda==K.
// ACT: 0=none, 2=exact GELU
// SMODE: 0=plain C (+g*sCg), 1=split+reverse into U, 2=concat+unreverse into CAT
// ---------------------------------------------------------------------------
template<int ACT, int SMODE>
__global__ void __launch_bounds__(256)
tf32gemm_kernel(const float* __restrict__ A,
                const float* __restrict__ W,
                const float* __restrict__ bias,
                float* __restrict__ C,
                int M, int N, int K,
                long sAg, long sWg, long sCg)
{
    int g = blockIdx.z;
    A += (long)g * sAg;
    W += (long)g * sWg;
    if (SMODE == 0) C += (long)g * sCg;

    __shared__ uint32_t As[128][20];   // [m][k], pad 16->20
    __shared__ uint32_t Bs[16][136];   // [k][n], pad 128->136

    int tid  = threadIdx.x;
    int warp = tid >> 5;
    int lane = tid & 31;
    int wm = (warp & 1) * 64;
    int wn = (warp >> 1) * 32;
    int gID = lane >> 2;
    int tig = lane & 3;
    int rowBase = blockIdx.y * 128;
    int colBase = blockIdx.x * 128;

    float acc[4][4][4];
#pragma unroll
    for (int a = 0; a < 4; a++)
#pragma unroll
        for (int b = 0; b < 4; b++)
#pragma unroll
            for (int c = 0; c < 4; c++) acc[a][b][c] = 0.f;

    for (int k0 = 0; k0 < K; k0 += 16) {
        // stage A tile 128x16 (cvt fp32 -> tf32)
#pragma unroll
        for (int it = 0; it < 2; it++) {
            int f = tid + it * 256;            // 0..511
            int r = f >> 2;
            int k4 = (f & 3) * 4;
            float4 v = *(const float4*)&A[(long)(rowBase + r) * K + k0 + k4];
            uint4 u;
            asm("cvt.rna.tf32.f32 %0, %1;" : "=r"(u.x) : "f"(v.x));
            asm("cvt.rna.tf32.f32 %0, %1;" : "=r"(u.y) : "f"(v.y));
            asm("cvt.rna.tf32.f32 %0, %1;" : "=r"(u.z) : "f"(v.z));
            asm("cvt.rna.tf32.f32 %0, %1;" : "=r"(u.w) : "f"(v.w));
            *(uint4*)&As[r][k4] = u;
        }
        // stage B tile 16x128
#pragma unroll
        for (int it = 0; it < 2; it++) {
            int f = tid + it * 256;
            int kr = f >> 5;
            int n4 = (f & 31) * 4;
            float4 v = *(const float4*)&W[(long)(k0 + kr) * N + colBase + n4];
            uint4 u;
            asm("cvt.rna.tf32.f32 %0, %1;" : "=r"(u.x) : "f"(v.x));
            asm("cvt.rna.tf32.f32 %0, %1;" : "=r"(u.y) : "f"(v.y));
            asm("cvt.rna.tf32.f32 %0, %1;" : "=r"(u.z) : "f"(v.z));
            asm("cvt.rna.tf32.f32 %0, %1;" : "=r"(u.w) : "f"(v.w));
            *(uint4*)&Bs[kr][n4] = u;
        }
        __syncthreads();

#pragma unroll
        for (int ks = 0; ks < 16; ks += 8) {
            uint32_t bf[4][2];
#pragma unroll
            for (int nt = 0; nt < 4; nt++) {
                int col = wn + nt * 8 + gID;
                bf[nt][0] = Bs[ks + tig][col];
                bf[nt][1] = Bs[ks + tig + 4][col];
            }
#pragma unroll
            for (int mt = 0; mt < 4; mt++) {
                int row = wm + mt * 16 + gID;
                uint32_t a0 = As[row][ks + tig];
                uint32_t a1 = As[row + 8][ks + tig];
                uint32_t a2 = As[row][ks + tig + 4];
                uint32_t a3 = As[row + 8][ks + tig + 4];
#pragma unroll
                for (int nt = 0; nt < 4; nt++) {
                    asm volatile(
                        "mma.sync.aligned.m16n8k8.row.col.f32.tf32.tf32.f32 "
                        "{%0,%1,%2,%3}, {%4,%5,%6,%7}, {%8,%9}, {%0,%1,%2,%3};\n"
                        : "+f"(acc[mt][nt][0]), "+f"(acc[mt][nt][1]),
                          "+f"(acc[mt][nt][2]), "+f"(acc[mt][nt][3])
                        : "r"(a0), "r"(a1), "r"(a2), "r"(a3),
                          "r"(bf[nt][0]), "r"(bf[nt][1]));
                }
            }
        }
        __syncthreads();
    }

    // epilogue
#pragma unroll
    for (int mt = 0; mt < 4; mt++) {
        int row0 = rowBase + wm + mt * 16 + gID;
#pragma unroll
        for (int nt = 0; nt < 4; nt++) {
            int col = colBase + wn + nt * 8 + tig * 2;
            float b0 = 0.f, b1 = 0.f;
            if (bias) { b0 = bias[col]; b1 = bias[col + 1]; }
            float v[4];
            v[0] = acc[mt][nt][0] + b0;
            v[1] = acc[mt][nt][1] + b1;
            v[2] = acc[mt][nt][2] + b0;
            v[3] = acc[mt][nt][3] + b1;
            if (ACT == 2) {
#pragma unroll
                for (int q = 0; q < 4; q++)
                    v[q] = 0.5f * v[q] * (1.f + erff(v[q] * 0.70710678118654752f));
            }
#pragma unroll
            for (int h = 0; h < 2; h++) {
                int row = row0 + h * 8;
                float2 val = make_float2(v[h * 2], v[h * 2 + 1]);
                if (SMODE == 0) {
                    *(float2*)&C[(long)row * N + col] = val;
                } else if (SMODE == 1) {
                    // split + reverse: cols<128 -> U0, cols>=128 -> U1 reversed
                    if (col < 128) {
                        *(float2*)&C[(long)row * 128 + col] = val;
                    } else {
                        long b = row >> 9, t = row & 511;
                        *(float2*)&C[MTOK * 128 + ((b << 9) + 511 - t) * 128 + (col - 128)] = val;
                    }
                } else {
                    // concat + un-reverse (N==128, batched g)
                    if (g == 0) {
                        *(float2*)&C[(long)row * 256 + col] = val;
                    } else {
                        long b = row >> 9, t = row & 511;
                        *(float2*)&C[((b << 9) + 511 - t) * 256 + 128 + col] = val;
                    }
                }
            }
        }
    }
}

// ---------------------------------------------------------------------------
// fp32 fallback SGEMM (N=40 / K=8 GEMMs): C = act(A @ W + bias)
// act: 0=none, 1=softplus
// ---------------------------------------------------------------------------
__global__ void sgemm_kernel(const float* __restrict__ A,
                             const float* __restrict__ W,
                             const float* __restrict__ bias,
                             float* __restrict__ C,
                             int M, int N, int K, int lda, int act,
                             long sAg, long sWg, long sCg, long sBg)
{
    int g = blockIdx.z;
    A += (long)g * sAg;
    W += (long)g * sWg;
    C += (long)g * sCg;
    if (bias) bias += (long)g * sBg;

    __shared__ __align__(16) float As[16][128];
    __shared__ __align__(16) float Ws[16][64];

    int tid = threadIdx.x;
    int tx = tid & 15;
    int ty = tid >> 4;
    int rowBase = blockIdx.y * 128;
    int colBase = blockIdx.x * 64;

    float acc[8][4];
#pragma unroll
    for (int i = 0; i < 8; i++)
#pragma unroll
        for (int j = 0; j < 4; j++) acc[i][j] = 0.f;

    for (int k0 = 0; k0 < K; k0 += 16) {
#pragma unroll
        for (int it = 0; it < 8; it++) {
            int idx = tid + it * 256;
            int m = idx >> 4;
            int kk = idx & 15;
            int gr = rowBase + m, gk = k0 + kk;
            As[kk][m] = (gr < M && gk < K) ? A[(long)gr * lda + gk] : 0.f;
        }
#pragma unroll
        for (int it = 0; it < 4; it++) {
            int idx = tid + it * 256;
            int kk = idx >> 6;
            int n = idx & 63;
            int gk = k0 + kk, gn = colBase + n;
            Ws[kk][n] = (gk < K && gn < N) ? W[(long)gk * N + gn] : 0.f;
        }
        __syncthreads();
#pragma unroll
        for (int k = 0; k < 16; k++) {
            float a[8], w[4];
            float4 a0 = *(const float4*)&As[k][ty * 8];
            float4 a1 = *(const float4*)&As[k][ty * 8 + 4];
            a[0] = a0.x; a[1] = a0.y; a[2] = a0.z; a[3] = a0.w;
            a[4] = a1.x; a[5] = a1.y; a[6] = a1.z; a[7] = a1.w;
            float4 w0 = *(const float4*)&Ws[k][tx * 4];
            w[0] = w0.x; w[1] = w0.y; w[2] = w0.z; w[3] = w0.w;
#pragma unroll
            for (int i = 0; i < 8; i++)
#pragma unroll
                for (int j = 0; j < 4; j++)
                    acc[i][j] = fmaf(a[i], w[j], acc[i][j]);
        }
        __syncthreads();
    }

#pragma unroll
    for (int i = 0; i < 8; i++) {
        int gr = rowBase + ty * 8 + i;
        if (gr >= M) continue;
#pragma unroll
        for (int j = 0; j < 4; j++) {
            int gn = colBase + tx * 4 + j;
            if (gn >= N) continue;
            float v = acc[i][j];
            if (bias) v += bias[gn];
            if (act == 1) v = (v > 20.f) ? v : log1pf(expf(v));
            C[(long)gr * N + gn] = v;
        }
    }
}

// ---------------------------------------------------------------------------
// depthwise causal conv (K=4) + bias + silu
// ---------------------------------------------------------------------------
__global__ void conv_silu_kernel(const float* __restrict__ xz,
                                 const float* __restrict__ convw,
                                 const float* __restrict__ convb,
                                 float* __restrict__ xc)
{
    long i = (long)blockIdx.x * 256 + threadIdx.x;
    if (i >= 2 * MTOK * 256) return;
    int d = (int)(i & 255);
    long gm = i >> 8;
    int g = (int)(gm / MTOK);
    long m = gm % MTOK;
    int t = (int)(m & 511);

    const float* w = convw + ((long)g * 256 + d) * 4;
    const float* xp = xz + ((long)g * MTOK + m) * 512 + d;
    float acc = convb[(long)g * 256 + d];
#pragma unroll
    for (int k = 0; k < 4; k++) {
        int tt = t - 3 + k;
        if (tt >= 0) acc = fmaf(xp[(long)(k - 3) * 512], w[k], acc);
    }
    xc[i] = acc / (1.f + __expf(-acc));
}

// ---------------------------------------------------------------------------
// Selective scan (+ fused output gate y *= silu(z))
// ---------------------------------------------------------------------------
__global__ void scan_kernel(const float* __restrict__ dt,
                            const float* __restrict__ xc,
                            const float* __restrict__ dbc,
                            const float* __restrict__ xz,
                            const float* __restrict__ alog,
                            const float* __restrict__ dpar,
                            float* __restrict__ y)
{
    int grp = blockIdx.x * 16 + (threadIdx.x >> 4);
    int n = threadIdx.x & 15;
    int g = grp >> 12;
    int bd = grp & 4095;
    int b = bd >> 8;
    int d = bd & 255;

    float A = -__expf(alog[((long)(g * 256 + d)) * 16 + n]);
    float dp = dpar[(long)g * 256 + d];

    long mbase = (long)g * MTOK + (long)b * 512;
    const float* dtp = dt + mbase * 256 + d;
    const float* xcp = xc + mbase * 256 + d;
    const float* dbp = dbc + mbase * 40;
    const float* zp  = xz + mbase * 512 + 256 + d;
    float* yp = y + mbase * 256 + d;

    float h = 0.f;
    for (int t = 0; t < 512; t++) {
        float dtv = dtp[(long)t * 256];
        float xv = xcp[(long)t * 256];
        float Bn = dbp[(long)t * 40 + 8 + n];
        float Cn = dbp[(long)t * 40 + 24 + n];
        h = __expf(dtv * A) * h + dtv * Bn * xv;
        float p = h * Cn;
        p += __shfl_xor_sync(0xffffffffu, p, 8);
        p += __shfl_xor_sync(0xffffffffu, p, 4);
        p += __shfl_xor_sync(0xffffffffu, p, 2);
        p += __shfl_xor_sync(0xffffffffu, p, 1);
        if (n == 0) {
            float z = zp[(long)t * 512];
            float sz = z / (1.f + __expf(-z));
            yp[(long)t * 256] = (p + dp * xv) * sz;
        }
    }
}

// ---------------------------------------------------------------------------
// Launch helpers
// ---------------------------------------------------------------------------
template<int ACT, int SMODE>
static void launch_tf32(const float* A, const float* W, const float* bias, float* C,
                        int M, int N, int K, int G,
                        long sAg, long sWg, long sCg)
{
    dim3 grid(N / 128, M / 128, G);
    tf32gemm_kernel<ACT, SMODE><<<grid, 256>>>(A, W, bias, C, M, N, K, sAg, sWg, sCg);
}

static void launch_sgemm(const float* A, const float* W, const float* bias, float* C,
                         int M, int N, int K, int lda, int act, int G,
                         long sAg, long sWg, long sCg, long sBg)
{
    dim3 grid((N + 63) / 64, (M + 127) / 128, G);
    sgemm_kernel<<<grid, 256>>>(A, W, bias, C, M, N, K, lda, act, sAg, sWg, sCg, sBg);
}

extern "C" void kernel_launch(void* const* d_in, const int* in_sizes, int n_in,
                              void* d_out, int out_size)
{
    const float* input_ids = (const float*)d_in[0];
    const float* proj_w    = (const float*)d_in[1];
    const float* proj_b    = (const float*)d_in[2];
    const float* ln0_g     = (const float*)d_in[3];
    const float* ln0_b     = (const float*)d_in[4];
    const float* ln1_g     = (const float*)d_in[5];
    const float* ln1_b     = (const float*)d_in[6];
    const float* ip_w      = (const float*)d_in[7];
    const float* ip_b      = (const float*)d_in[8];
    const float* s_inw     = (const float*)d_in[9];
    const float* s_convw   = (const float*)d_in[10];
    const float* s_convb   = (const float*)d_in[11];
    const float* s_xw      = (const float*)d_in[12];
    const float* s_dtw     = (const float*)d_in[13];
    const float* s_dtb     = (const float*)d_in[14];
    const float* s_alog    = (const float*)d_in[15];
    const float* s_d       = (const float*)d_in[16];
    const float* s_outw    = (const float*)d_in[17];
    const float* op_w      = (const float*)d_in[18];
    const float* op_b      = (const float*)d_in[19];
    const float* ln2_g     = (const float*)d_in[20];
    const float* ln2_b     = (const float*)d_in[21];
    const float* f_w1      = (const float*)d_in[22];
    const float* f_b1      = (const float*)d_in[23];
    const float* f_w2      = (const float*)d_in[24];
    const float* f_b2      = (const float*)d_in[25];
    const float* ln3_g     = (const float*)d_in[26];
    const float* ln3_b     = (const float*)d_in[27];

    float* base = nullptr;
    cudaGetSymbolAddress((void**)&base, g_buf);

    float* X    = base + OFF_X;
    float* LNb  = base + OFF_LN;
    float* B256 = base + OFF_B256;
    float* U    = base + OFF_U;
    float* XZ   = base + OFF_XZ;
    float* XC   = base + OFF_XC;
    float* DBC  = base + OFF_DBC;
    float* DT   = base + OFF_DT;
    float* Y    = base + OFF_Y;
    float* CAT  = base + OFF_CAT;
    float* FF   = base + OFF_FF;

    const int M = (int)MTOK;
    const long EW2 = 2 * MTOK * 256;
    const int EW2_BLOCKS = (int)((EW2 + 255) / 256);

    embed_ln_kernel<<<M, 256>>>(input_ids, proj_w, proj_b, ln0_g, ln0_b, X);

    for (int l = 0; l < 12; l++) {
        // LN1
        ln_kernel<<<M, 256>>>(X, nullptr, ln1_g + l * 256, ln1_b + l * 256, LNb);
        // in-proj -> fused split+reverse into U
        launch_tf32<0, 1>(LNb, ip_w + (long)l * 256 * 256, ip_b + l * 256, U,
                          M, 256, 256, 1, 0, 0, 0);
        // xz = u @ inw (batched 2)
        launch_tf32<0, 0>(U, s_inw + (long)l * 2 * 128 * 512, nullptr, XZ,
                          M, 512, 128, 2, MTOK * 128, 128 * 512, MTOK * 512);
        // conv + silu
        conv_silu_kernel<<<EW2_BLOCKS, 256>>>(XZ, s_convw + (long)l * 2 * 256 * 4,
                                              s_convb + (long)l * 2 * 256, XC);
        // dbc = xc @ xw (fp32, N=40)
        launch_sgemm(XC, s_xw + (long)l * 2 * 256 * 40, nullptr, DBC,
                     M, 40, 256, 256, 0, 2, MTOK * 256, 256 * 40, MTOK * 40, 0);
        // dt = softplus(dbc[:, :8] @ dtw + dtb)
        launch_sgemm(DBC, s_dtw + (long)l * 2 * 8 * 256, s_dtb + (long)l * 2 * 256, DT,
                     M, 256, 8, 40, 1, 2, MTOK * 40, 8 * 256, MTOK * 256, 256);
        // selective scan + fused silu(z) gate
        scan_kernel<<<512, 256>>>(DT, XC, DBC, XZ,
                                  s_alog + (long)l * 2 * 256 * 16,
                                  s_d + (long)l * 2 * 256, Y);
        // so = y @ outw (batched 2) -> fused concat+unreverse into CAT
        launch_tf32<0, 2>(Y, s_outw + (long)l * 2 * 256 * 128, nullptr, CAT,
                          M, 128, 256, 2, MTOK * 256, 256 * 128, 0);
        // out-proj
        launch_tf32<0, 0>(CAT, op_w + (long)l * 256 * 256, op_b + l * 256, B256,
                          M, 256, 256, 1, 0, 0, 0);
        // LN2 (residual)
        ln_kernel<<<M, 256>>>(B256, X, ln2_g + l * 256, ln2_b + l * 256, X);
        // ff = gelu(x @ w1 + b1)
        launch_tf32<2, 0>(X, f_w1 + (long)l * 256 * 1024, f_b1 + l * 1024, FF,
                          M, 1024, 256, 1, 0, 0, 0);
        // f = ff @ w2 + b2
        launch_tf32<0, 0>(FF, f_w2 + (long)l * 1024 * 256, f_b2 + l * 256, B256,
                          M, 256, 1024, 1, 0, 0, 0);
        // LN3 (residual); last layer -> d_out
        float* dst = (l == 11) ? (float*)d_out : X;
        ln_kernel<<<M, 256>>>(B256, X, ln3_g + l * 256, ln3_b + l * 256, dst);
    }
}

// round 5
// speedup vs baseline: 1.4742x; 1.4742x over previous
#include <cuda_runtime.h>
#include <math.h>
#include <stdint.h>

constexpr long MTOK  = 16 * 512;     // 8192 tokens

// ---------------------------------------------------------------------------
// Scratch arena
// ---------------------------------------------------------------------------
constexpr long OFF_X    = 0;
constexpr long OFF_LN   = OFF_X    + MTOK * 256;
constexpr long OFF_B256 = OFF_LN   + MTOK * 256;
constexpr long OFF_U    = OFF_B256 + MTOK * 256;
constexpr long OFF_XZ   = OFF_U    + 2 * MTOK * 128;
constexpr long OFF_XC   = OFF_XZ   + 2 * MTOK * 512;
constexpr long OFF_DBC  = OFF_XC   + 2 * MTOK * 256;
constexpr long OFF_DT   = OFF_DBC  + 2 * MTOK * 40;
constexpr long OFF_Y    = OFF_DT   + 2 * MTOK * 256;
constexpr long OFF_CAT  = OFF_Y    + 2 * MTOK * 256;
constexpr long OFF_FF   = OFF_CAT  + MTOK * 256;
constexpr long TOTAL_F  = OFF_FF   + MTOK * 1024;

__device__ float g_buf[TOTAL_F];

__device__ __forceinline__ uint32_t smem_u32(const void* p)
{
    return (uint32_t)__cvta_generic_to_shared(p);
}

// ---------------------------------------------------------------------------
// Block-wide sum over 256 threads
// ---------------------------------------------------------------------------
__device__ __forceinline__ float blockSum256(float v, float* sbuf)
{
#pragma unroll
    for (int o = 16; o > 0; o >>= 1)
        v += __shfl_xor_sync(0xffffffffu, v, o);
    __syncthreads();
    if ((threadIdx.x & 31) == 0) sbuf[threadIdx.x >> 5] = v;
    __syncthreads();
    float s = sbuf[0];
#pragma unroll
    for (int i = 1; i < 8; i++) s += sbuf[i];
    return s;
}

// ---------------------------------------------------------------------------
// Embedding: x = LN(ids @ proj_w + proj_b)
// ---------------------------------------------------------------------------
__global__ void embed_ln_kernel(const float* __restrict__ ids,
                                const float* __restrict__ pw,
                                const float* __restrict__ pb,
                                const float* __restrict__ gam,
                                const float* __restrict__ bet,
                                float* __restrict__ x)
{
    __shared__ float sin[32];
    __shared__ float sred[8];
    int m = blockIdx.x, d = threadIdx.x;
    if (d < 32) sin[d] = ids[(long)m * 32 + d];
    __syncthreads();
    float v = pb[d];
#pragma unroll
    for (int e = 0; e < 32; e++)
        v = fmaf(sin[e], pw[e * 256 + d], v);
    float mean = blockSum256(v, sred) * (1.f / 256.f);
    float c = v - mean;
    float var = blockSum256(c * c, sred) * (1.f / 256.f);
    x[(long)m * 256 + d] = c * rsqrtf(var + 1e-5f) * gam[d] + bet[d];
}

// ---------------------------------------------------------------------------
// LayerNorm over D=256, optional residual
// ---------------------------------------------------------------------------
__global__ void ln_kernel(const float* __restrict__ in,
                          const float* __restrict__ res,
                          const float* __restrict__ gam,
                          const float* __restrict__ bet,
                          float* __restrict__ out)
{
    __shared__ float sred[8];
    int m = blockIdx.x, d = threadIdx.x;
    float v = in[(long)m * 256 + d];
    if (res) v += res[(long)m * 256 + d];
    float mean = blockSum256(v, sred) * (1.f / 256.f);
    float c = v - mean;
    float var = blockSum256(c * c, sred) * (1.f / 256.f);
    out[(long)m * 256 + d] = c * rsqrtf(var + 1e-5f) * gam[d] + bet[d];
}

// ---------------------------------------------------------------------------
// TF32 tensor-core GEMM, cp.async.ca 3-stage pipeline, dynamic smem.
// M%128==0, K%16==0 (K/16 >= 2), lda==K.
// ACT: 0=none, 2=exact GELU
// SMODE: 0=plain C (+g*sCg), 1=split+reverse into U, 2=concat+unreverse into CAT
// NG: true -> N not multiple of 128 (guarded B loads / stores), colBase==0
// +0x1000 bit-rounding on fragment reads restores ~rna quality.
// ---------------------------------------------------------------------------
template<int ACT, int SMODE, bool NG>
__global__ void __launch_bounds__(256, 2)
tf32gemm_kernel(const float* __restrict__ A,
                const float* __restrict__ W,
                const float* __restrict__ bias,
                float* __restrict__ C,
                int M, int N, int K,
                long sAg, long sWg, long sCg)
{
    extern __shared__ uint32_t dyn[];
    constexpr int SW = 4736;            // words per stage: A 128*20 + B 16*136

    int g = blockIdx.z;
    A += (long)g * sAg;
    W += (long)g * sWg;
    if (SMODE == 0) C += (long)g * sCg;

    int tid  = threadIdx.x;
    int warp = tid >> 5;
    int lane = tid & 31;
    int wm = (warp & 1) * 64;
    int wn = (warp >> 1) * 32;
    int gID = lane >> 2;
    int tig = lane & 3;
    int rowBase = blockIdx.y * 128;
    int colBase = blockIdx.x * 128;

    const float* Abase = A + (long)rowBase * K;
    const float* Wbase = W + colBase;

    // NG: zero-fill the pad region of all 3 B stages once
    if (NG) {
        for (int s = 0; s < 3; s++) {
            uint32_t* Bs = dyn + s * SW + 2560;
            for (int idx = tid; idx < 512; idx += 256) {
                int kr = idx >> 5, n4 = (idx & 31) * 4;
                if (colBase + n4 + 4 > N) {
                    uint4 z = make_uint4(0, 0, 0, 0);
                    *(uint4*)&Bs[kr * 136 + n4] = z;
                }
            }
        }
        __syncthreads();
    }

    auto stage = [&](int buf, int k0) {
        uint32_t* As = dyn + buf * SW;
        uint32_t* Bs = dyn + buf * SW + 2560;
#pragma unroll
        for (int it = 0; it < 2; it++) {
            int f = tid + it * 256;
            int r = f >> 2, k4 = (f & 3) * 4;
            uint32_t s = smem_u32(&As[r * 20 + k4]);
            const float* gp = Abase + (long)r * K + k0 + k4;
            asm volatile("cp.async.ca.shared.global [%0], [%1], 16;\n"
                         :: "r"(s), "l"(gp));
        }
#pragma unroll
        for (int it = 0; it < 2; it++) {
            int f = tid + it * 256;
            int kr = f >> 5, n4 = (f & 31) * 4;
            if (!NG || colBase + n4 + 4 <= N) {
                uint32_t s = smem_u32(&Bs[kr * 136 + n4]);
                const float* gp = Wbase + (long)(k0 + kr) * N + n4;
                asm volatile("cp.async.ca.shared.global [%0], [%1], 16;\n"
                             :: "r"(s), "l"(gp));
            }
        }
        asm volatile("cp.async.commit_group;\n");
    };

    float acc[4][4][4];
#pragma unroll
    for (int a = 0; a < 4; a++)
#pragma unroll
        for (int b = 0; b < 4; b++)
#pragma unroll
            for (int c = 0; c < 4; c++) acc[a][b][c] = 0.f;

    auto compute = [&](int buf) {
        uint32_t* As = dyn + buf * SW;
        uint32_t* Bs = dyn + buf * SW + 2560;
#pragma unroll
        for (int ks = 0; ks < 16; ks += 8) {
            uint32_t bf[4][2];
#pragma unroll
            for (int nt = 0; nt < 4; nt++) {
                int col = wn + nt * 8 + gID;
                bf[nt][0] = Bs[(ks + tig) * 136 + col] + 0x1000u;
                bf[nt][1] = Bs[(ks + tig + 4) * 136 + col] + 0x1000u;
            }
#pragma unroll
            for (int mt = 0; mt < 4; mt++) {
                int row = wm + mt * 16 + gID;
                uint32_t a0 = As[row * 20 + ks + tig] + 0x1000u;
                uint32_t a1 = As[(row + 8) * 20 + ks + tig] + 0x1000u;
                uint32_t a2 = As[row * 20 + ks + tig + 4] + 0x1000u;
                uint32_t a3 = As[(row + 8) * 20 + ks + tig + 4] + 0x1000u;
#pragma unroll
                for (int nt = 0; nt < 4; nt++) {
                    asm volatile(
                        "mma.sync.aligned.m16n8k8.row.col.f32.tf32.tf32.f32 "
                        "{%0,%1,%2,%3}, {%4,%5,%6,%7}, {%8,%9}, {%0,%1,%2,%3};\n"
                        : "+f"(acc[mt][nt][0]), "+f"(acc[mt][nt][1]),
                          "+f"(acc[mt][nt][2]), "+f"(acc[mt][nt][3])
                        : "r"(a0), "r"(a1), "r"(a2), "r"(a3),
                          "r"(bf[nt][0]), "r"(bf[nt][1]));
                }
            }
        }
    };

    int nk = K >> 4;                   // assumed >= 2
    stage(0, 0);
    stage(1, 16);
    for (int ki = 0; ki < nk; ki++) {
        if (ki >= nk - 1) {
            asm volatile("cp.async.wait_group 0;\n");
        } else {
            asm volatile("cp.async.wait_group 1;\n");
        }
        __syncthreads();
        compute(ki % 3);
        __syncthreads();
        int kn = ki + 2;
        if (kn < nk) stage(kn % 3, kn * 16);
    }

    // epilogue
#pragma unroll
    for (int mt = 0; mt < 4; mt++) {
        int row0 = rowBase + wm + mt * 16 + gID;
#pragma unroll
        for (int nt = 0; nt < 4; nt++) {
            int col = colBase + wn + nt * 8 + tig * 2;
            if (NG && col >= N) continue;
            float b0 = 0.f, b1 = 0.f;
            if (bias) { b0 = bias[col]; b1 = bias[col + 1]; }
            float v[4];
            v[0] = acc[mt][nt][0] + b0;
            v[1] = acc[mt][nt][1] + b1;
            v[2] = acc[mt][nt][2] + b0;
            v[3] = acc[mt][nt][3] + b1;
            if (ACT == 2) {
#pragma unroll
                for (int q = 0; q < 4; q++)
                    v[q] = 0.5f * v[q] * (1.f + erff(v[q] * 0.70710678118654752f));
            }
#pragma unroll
            for (int h = 0; h < 2; h++) {
                int row = row0 + h * 8;
                float2 val = make_float2(v[h * 2], v[h * 2 + 1]);
                if (SMODE == 0) {
                    *(float2*)&C[(long)row * N + col] = val;
                } else if (SMODE == 1) {
                    if (col < 128) {
                        *(float2*)&C[(long)row * 128 + col] = val;
                    } else {
                        long b = row >> 9, t = row & 511;
                        *(float2*)&C[MTOK * 128 + ((b << 9) + 511 - t) * 128 + (col - 128)] = val;
                    }
                } else {
                    if (g == 0) {
                        *(float2*)&C[(long)row * 256 + col] = val;
                    } else {
                        long b = row >> 9, t = row & 511;
                        *(float2*)&C[((b << 9) + 511 - t) * 256 + 128 + col] = val;
                    }
                }
            }
        }
    }
}

// ---------------------------------------------------------------------------
// fp32 SGEMM (dt projection: K=8, fused softplus). act: 0=none, 1=softplus
// ---------------------------------------------------------------------------
__global__ void sgemm_kernel(const float* __restrict__ A,
                             const float* __restrict__ W,
                             const float* __restrict__ bias,
                             float* __restrict__ C,
                             int M, int N, int K, int lda, int act,
                             long sAg, long sWg, long sCg, long sBg)
{
    int g = blockIdx.z;
    A += (long)g * sAg;
    W += (long)g * sWg;
    C += (long)g * sCg;
    if (bias) bias += (long)g * sBg;

    __shared__ __align__(16) float As[16][128];
    __shared__ __align__(16) float Ws[16][64];

    int tid = threadIdx.x;
    int tx = tid & 15;
    int ty = tid >> 4;
    int rowBase = blockIdx.y * 128;
    int colBase = blockIdx.x * 64;

    float acc[8][4];
#pragma unroll
    for (int i = 0; i < 8; i++)
#pragma unroll
        for (int j = 0; j < 4; j++) acc[i][j] = 0.f;

    for (int k0 = 0; k0 < K; k0 += 16) {
#pragma unroll
        for (int it = 0; it < 8; it++) {
            int idx = tid + it * 256;
            int m = idx >> 4;
            int kk = idx & 15;
            int gr = rowBase + m, gk = k0 + kk;
            As[kk][m] = (gr < M && gk < K) ? A[(long)gr * lda + gk] : 0.f;
        }
#pragma unroll
        for (int it = 0; it < 4; it++) {
            int idx = tid + it * 256;
            int kk = idx >> 6;
            int n = idx & 63;
            int gk = k0 + kk, gn = colBase + n;
            Ws[kk][n] = (gk < K && gn < N) ? W[(long)gk * N + gn] : 0.f;
        }
        __syncthreads();
#pragma unroll
        for (int k = 0; k < 16; k++) {
            float a[8], w[4];
            float4 a0 = *(const float4*)&As[k][ty * 8];
            float4 a1 = *(const float4*)&As[k][ty * 8 + 4];
            a[0] = a0.x; a[1] = a0.y; a[2] = a0.z; a[3] = a0.w;
            a[4] = a1.x; a[5] = a1.y; a[6] = a1.z; a[7] = a1.w;
            float4 w0 = *(const float4*)&Ws[k][tx * 4];
            w[0] = w0.x; w[1] = w0.y; w[2] = w0.z; w[3] = w0.w;
#pragma unroll
            for (int i = 0; i < 8; i++)
#pragma unroll
                for (int j = 0; j < 4; j++)
                    acc[i][j] = fmaf(a[i], w[j], acc[i][j]);
        }
        __syncthreads();
    }

#pragma unroll
    for (int i = 0; i < 8; i++) {
        int gr = rowBase + ty * 8 + i;
        if (gr >= M) continue;
#pragma unroll
        for (int j = 0; j < 4; j++) {
            int gn = colBase + tx * 4 + j;
            if (gn >= N) continue;
            float v = acc[i][j];
            if (bias) v += bias[gn];
            if (act == 1) v = (v > 20.f) ? v : log1pf(expf(v));
            C[(long)gr * N + gn] = v;
        }
    }
}

// ---------------------------------------------------------------------------
// depthwise causal conv (K=4) + bias + silu
// ---------------------------------------------------------------------------
__global__ void conv_silu_kernel(const float* __restrict__ xz,
                                 const float* __restrict__ convw,
                                 const float* __restrict__ convb,
                                 float* __restrict__ xc)
{
    long i = (long)blockIdx.x * 256 + threadIdx.x;
    if (i >= 2 * MTOK * 256) return;
    int d = (int)(i & 255);
    long gm = i >> 8;
    int g = (int)(gm / MTOK);
    long m = gm % MTOK;
    int t = (int)(m & 511);

    const float* w = convw + ((long)g * 256 + d) * 4;
    const float* xp = xz + ((long)g * MTOK + m) * 512 + d;
    float acc = convb[(long)g * 256 + d];
#pragma unroll
    for (int k = 0; k < 4; k++) {
        int tt = t - 3 + k;
        if (tt >= 0) acc = fmaf(xp[(long)(k - 3) * 512], w[k], acc);
    }
    xc[i] = acc / (1.f + __expf(-acc));
}

// ---------------------------------------------------------------------------
// Selective scan (+ fused output gate y *= silu(z)), z prefetched one
// iteration ahead and loaded by ALL lanes (broadcast) — no predicated
// load->use stall on the serial path.
// ---------------------------------------------------------------------------
__global__ void scan_kernel(const float* __restrict__ dt,
                            const float* __restrict__ xc,
                            const float* __restrict__ dbc,
                            const float* __restrict__ xz,
                            const float* __restrict__ alog,
                            const float* __restrict__ dpar,
                            float* __restrict__ y)
{
    int grp = blockIdx.x * 16 + (threadIdx.x >> 4);
    int n = threadIdx.x & 15;
    int g = grp >> 12;
    int bd = grp & 4095;
    int b = bd >> 8;
    int d = bd & 255;

    float A = -__expf(alog[((long)(g * 256 + d)) * 16 + n]);
    float dp = dpar[(long)g * 256 + d];

    long mbase = (long)g * MTOK + (long)b * 512;
    const float* dtp = dt + mbase * 256 + d;
    const float* xcp = xc + mbase * 256 + d;
    const float* dbp = dbc + mbase * 40;
    const float* zp  = xz + mbase * 512 + 256 + d;
    float* yp = y + mbase * 256 + d;

    float h = 0.f;
    float z_nxt = zp[0];
    for (int t = 0; t < 512; t++) {
        float z = z_nxt;
        int tn = (t + 1 < 512) ? t + 1 : 511;
        z_nxt = zp[(long)tn * 512];
        float dtv = dtp[(long)t * 256];
        float xv = xcp[(long)t * 256];
        float Bn = dbp[(long)t * 40 + 8 + n];
        float Cn = dbp[(long)t * 40 + 24 + n];
        h = __expf(dtv * A) * h + dtv * Bn * xv;
        float p = h * Cn;
        p += __shfl_xor_sync(0xffffffffu, p, 8);
        p += __shfl_xor_sync(0xffffffffu, p, 4);
        p += __shfl_xor_sync(0xffffffffu, p, 2);
        p += __shfl_xor_sync(0xffffffffu, p, 1);
        if (n == 0) {
            float sz = z / (1.f + __expf(-z));
            yp[(long)t * 256] = (p + dp * xv) * sz;
        }
    }
}

// ---------------------------------------------------------------------------
// Launch helpers
// ---------------------------------------------------------------------------
constexpr int GEMM_SMEM = 3 * 4736 * 4;   // 56832 B

template<int ACT, int SMODE, bool NG>
static void launch_tf32(const float* A, const float* W, const float* bias, float* C,
                        int M, int N, int K, int G,
                        long sAg, long sWg, long sCg)
{
    cudaFuncSetAttribute(tf32gemm_kernel<ACT, SMODE, NG>,
                         cudaFuncAttributeMaxDynamicSharedMemorySize, GEMM_SMEM);
    dim3 grid((N + 127) / 128, M / 128, G);
    tf32gemm_kernel<ACT, SMODE, NG><<<grid, 256, GEMM_SMEM>>>(A, W, bias, C, M, N, K,
                                                              sAg, sWg, sCg);
}

static void launch_sgemm(const float* A, const float* W, const float* bias, float* C,
                         int M, int N, int K, int lda, int act, int G,
                         long sAg, long sWg, long sCg, long sBg)
{
    dim3 grid((N + 63) / 64, (M + 127) / 128, G);
    sgemm_kernel<<<grid, 256>>>(A, W, bias, C, M, N, K, lda, act, sAg, sWg, sCg, sBg);
}

extern "C" void kernel_launch(void* const* d_in, const int* in_sizes, int n_in,
                              void* d_out, int out_size)
{
    const float* input_ids = (const float*)d_in[0];
    const float* proj_w    = (const float*)d_in[1];
    const float* proj_b    = (const float*)d_in[2];
    const float* ln0_g     = (const float*)d_in[3];
    const float* ln0_b     = (const float*)d_in[4];
    const float* ln1_g     = (const float*)d_in[5];
    const float* ln1_b     = (const float*)d_in[6];
    const float* ip_w      = (const float*)d_in[7];
    const float* ip_b      = (const float*)d_in[8];
    const float* s_inw     = (const float*)d_in[9];
    const float* s_convw   = (const float*)d_in[10];
    const float* s_convb   = (const float*)d_in[11];
    const float* s_xw      = (const float*)d_in[12];
    const float* s_dtw     = (const float*)d_in[13];
    const float* s_dtb     = (const float*)d_in[14];
    const float* s_alog    = (const float*)d_in[15];
    const float* s_d       = (const float*)d_in[16];
    const float* s_outw    = (const float*)d_in[17];
    const float* op_w      = (const float*)d_in[18];
    const float* op_b      = (const float*)d_in[19];
    const float* ln2_g     = (const float*)d_in[20];
    const float* ln2_b     = (const float*)d_in[21];
    const float* f_w1      = (const float*)d_in[22];
    const float* f_b1      = (const float*)d_in[23];
    const float* f_w2      = (const float*)d_in[24];
    const float* f_b2      = (const float*)d_in[25];
    const float* ln3_g     = (const float*)d_in[26];
    const float* ln3_b     = (const float*)d_in[27];

    float* base = nullptr;
    cudaGetSymbolAddress((void**)&base, g_buf);

    float* X    = base + OFF_X;
    float* LNb  = base + OFF_LN;
    float* B256 = base + OFF_B256;
    float* U    = base + OFF_U;
    float* XZ   = base + OFF_XZ;
    float* XC   = base + OFF_XC;
    float* DBC  = base + OFF_DBC;
    float* DT   = base + OFF_DT;
    float* Y    = base + OFF_Y;
    float* CAT  = base + OFF_CAT;
    float* FF   = base + OFF_FF;

    const int M = (int)MTOK;
    const long EW2 = 2 * MTOK * 256;
    const int EW2_BLOCKS = (int)((EW2 + 255) / 256);

    embed_ln_kernel<<<M, 256>>>(input_ids, proj_w, proj_b, ln0_g, ln0_b, X);

    for (int l = 0; l < 12; l++) {
        // LN1
        ln_kernel<<<M, 256>>>(X, nullptr, ln1_g + l * 256, ln1_b + l * 256, LNb);
        // in-proj -> fused split+reverse into U
        launch_tf32<0, 1, false>(LNb, ip_w + (long)l * 256 * 256, ip_b + l * 256, U,
                                 M, 256, 256, 1, 0, 0, 0);
        // xz = u @ inw (batched 2)
        launch_tf32<0, 0, false>(U, s_inw + (long)l * 2 * 128 * 512, nullptr, XZ,
                                 M, 512, 128, 2, MTOK * 128, 128 * 512, MTOK * 512);
        // conv + silu
        conv_silu_kernel<<<EW2_BLOCKS, 256>>>(XZ, s_convw + (long)l * 2 * 256 * 4,
                                              s_convb + (long)l * 2 * 256, XC);
        // dbc = xc @ xw (tf32, N=40 guarded)
        launch_tf32<0, 0, true>(XC, s_xw + (long)l * 2 * 256 * 40, nullptr, DBC,
                                M, 40, 256, 2, MTOK * 256, 256 * 40, MTOK * 40);
        // dt = softplus(dbc[:, :8] @ dtw + dtb)  (fp32, K=8)
        launch_sgemm(DBC, s_dtw + (long)l * 2 * 8 * 256, s_dtb + (long)l * 2 * 256, DT,
                     M, 256, 8, 40, 1, 2, MTOK * 40, 8 * 256, MTOK * 256, 256);
        // selective scan + fused silu(z) gate (prefetched z)
        scan_kernel<<<512, 256>>>(DT, XC, DBC, XZ,
                                  s_alog + (long)l * 2 * 256 * 16,
                                  s_d + (long)l * 2 * 256, Y);
        // so = y @ outw (batched 2) -> fused concat+unreverse into CAT
        launch_tf32<0, 2, false>(Y, s_outw + (long)l * 2 * 256 * 128, nullptr, CAT,
                                 M, 128, 256, 2, MTOK * 256, 256 * 128, 0);
        // out-proj
        launch_tf32<0, 0, false>(CAT, op_w + (long)l * 256 * 256, op_b + l * 256, B256,
                                 M, 256, 256, 1, 0, 0, 0);
        // LN2 (residual)
        ln_kernel<<<M, 256>>>(B256, X, ln2_g + l * 256, ln2_b + l * 256, X);
        // ff = gelu(x @ w1 + b1)
        launch_tf32<2, 0, false>(X, f_w1 + (long)l * 256 * 1024, f_b1 + l * 1024, FF,
                                 M, 1024, 256, 1, 0, 0, 0);
        // f = ff @ w2 + b2
        launch_tf32<0, 0, false>(FF, f_w2 + (long)l * 1024 * 256, f_b2 + l * 256, B256,
                                 M, 256, 1024, 1, 0, 0, 0);
        // LN3 (residual); last layer -> d_out
        float* dst = (l == 11) ? (float*)d_out : X;
        ln_kernel<<<M, 256>>>(B256, X, ln3_g + l * 256, ln3_b + l * 256, dst);
    }
}

// round 6
// speedup vs baseline: 1.5411x; 1.0454x over previous
#include <cuda_runtime.h>
#include <math.h>
#include <stdint.h>

constexpr long MTOK  = 16 * 512;     // 8192 tokens

// ---------------------------------------------------------------------------
// Scratch arena
// ---------------------------------------------------------------------------
constexpr long OFF_X    = 0;
constexpr long OFF_LN   = OFF_X    + MTOK * 256;
constexpr long OFF_B256 = OFF_LN   + MTOK * 256;
constexpr long OFF_U    = OFF_B256 + MTOK * 256;
constexpr long OFF_XZ   = OFF_U    + 2 * MTOK * 128;
constexpr long OFF_XC   = OFF_XZ   + 2 * MTOK * 512;
constexpr long OFF_DBC  = OFF_XC   + 2 * MTOK * 256;
constexpr long OFF_DT   = OFF_DBC  + 2 * MTOK * 40;
constexpr long OFF_Y    = OFF_DT   + 2 * MTOK * 256;
constexpr long OFF_CAT  = OFF_Y    + 2 * MTOK * 256;
constexpr long OFF_FF   = OFF_CAT  + MTOK * 256;
constexpr long TOTAL_F  = OFF_FF   + MTOK * 1024;

__device__ float g_buf[TOTAL_F];

__device__ __forceinline__ uint32_t smem_u32(const void* p)
{
    return (uint32_t)__cvta_generic_to_shared(p);
}

// ---------------------------------------------------------------------------
// Embedding: x = LN(ids @ proj_w + proj_b)  (runs once; block version)
// ---------------------------------------------------------------------------
__global__ void embed_ln_kernel(const float* __restrict__ ids,
                                const float* __restrict__ pw,
                                const float* __restrict__ pb,
                                const float* __restrict__ gam,
                                const float* __restrict__ bet,
                                float* __restrict__ x)
{
    __shared__ float sin[32];
    __shared__ float sred[8];
    int m = blockIdx.x, d = threadIdx.x;
    if (d < 32) sin[d] = ids[(long)m * 32 + d];
    __syncthreads();
    float v = pb[d];
#pragma unroll
    for (int e = 0; e < 32; e++)
        v = fmaf(sin[e], pw[e * 256 + d], v);
    // block reduce (256 threads)
    float s = v;
#pragma unroll
    for (int o = 16; o > 0; o >>= 1) s += __shfl_xor_sync(0xffffffffu, s, o);
    if ((d & 31) == 0) sred[d >> 5] = s;
    __syncthreads();
    float mean = 0.f;
#pragma unroll
    for (int i = 0; i < 8; i++) mean += sred[i];
    mean *= (1.f / 256.f);
    float c = v - mean;
    float q = c * c;
#pragma unroll
    for (int o = 16; o > 0; o >>= 1) q += __shfl_xor_sync(0xffffffffu, q, o);
    __syncthreads();
    if ((d & 31) == 0) sred[d >> 5] = q;
    __syncthreads();
    float var = 0.f;
#pragma unroll
    for (int i = 0; i < 8; i++) var += sred[i];
    var *= (1.f / 256.f);
    x[(long)m * 256 + d] = c * rsqrtf(var + 1e-5f) * gam[d] + bet[d];
}

// ---------------------------------------------------------------------------
// Warp-per-token LayerNorm over D=256, optional residual. No __syncthreads.
// grid = MTOK/8 blocks x 256 threads (8 warps = 8 tokens).
// ---------------------------------------------------------------------------
__global__ void __launch_bounds__(256)
ln_kernel(const float* __restrict__ in,
          const float* __restrict__ res,
          const float* __restrict__ gam,
          const float* __restrict__ bet,
          float* __restrict__ out)
{
    int w = threadIdx.x >> 5, lane = threadIdx.x & 31;
    long m = (long)blockIdx.x * 8 + w;
    const float4* ip = (const float4*)(in + m * 256);
    float4 v0 = ip[lane * 2];
    float4 v1 = ip[lane * 2 + 1];
    if (res) {
        const float4* rp = (const float4*)(res + m * 256);
        float4 r0 = rp[lane * 2];
        float4 r1 = rp[lane * 2 + 1];
        v0.x += r0.x; v0.y += r0.y; v0.z += r0.z; v0.w += r0.w;
        v1.x += r1.x; v1.y += r1.y; v1.z += r1.z; v1.w += r1.w;
    }
    float s = v0.x + v0.y + v0.z + v0.w + v1.x + v1.y + v1.z + v1.w;
#pragma unroll
    for (int o = 16; o > 0; o >>= 1) s += __shfl_xor_sync(0xffffffffu, s, o);
    float mean = s * (1.f / 256.f);
    float a[8] = {v0.x - mean, v0.y - mean, v0.z - mean, v0.w - mean,
                  v1.x - mean, v1.y - mean, v1.z - mean, v1.w - mean};
    float q = 0.f;
#pragma unroll
    for (int i = 0; i < 8; i++) q = fmaf(a[i], a[i], q);
#pragma unroll
    for (int o = 16; o > 0; o >>= 1) q += __shfl_xor_sync(0xffffffffu, q, o);
    float inv = rsqrtf(q * (1.f / 256.f) + 1e-5f);
    const float4* gp = (const float4*)(gam + lane * 8);
    const float4* bp = (const float4*)(bet + lane * 8);
    float4 g0 = gp[0], g1 = gp[1], b0 = bp[0], b1 = bp[1];
    float4 o0, o1;
    o0.x = a[0] * inv * g0.x + b0.x;
    o0.y = a[1] * inv * g0.y + b0.y;
    o0.z = a[2] * inv * g0.z + b0.z;
    o0.w = a[3] * inv * g0.w + b0.w;
    o1.x = a[4] * inv * g1.x + b1.x;
    o1.y = a[5] * inv * g1.y + b1.y;
    o1.z = a[6] * inv * g1.z + b1.z;
    o1.w = a[7] * inv * g1.w + b1.w;
    float4* op = (float4*)(out + m * 256);
    op[lane * 2] = o0;
    op[lane * 2 + 1] = o1;
}

// ---------------------------------------------------------------------------
// TF32 tensor-core GEMM. TM x 128 tile, BK=32, 2-stage cp.async.ca pipeline.
// M%TM==0, K%32==0, lda==K.
// TM: 128 (big grids) or 64 (fills the machine for N<=256 GEMMs)
// ACT: 0=none, 2=exact GELU
// SMODE: 0=plain C (+g*sCg), 1=split+reverse into U, 2=concat+unreverse into CAT
// NG: N not multiple of 128 (guarded loads/stores; colBase==0; N%4==0)
// +0x1000 on raw fp32 bits ~= round-to-nearest into tf32.
// ---------------------------------------------------------------------------
template<int TM, int ACT, int SMODE, bool NG>
__global__ void __launch_bounds__(256, 2)
tf32gemm_kernel(const float* __restrict__ A,
                const float* __restrict__ W,
                const float* __restrict__ bias,
                float* __restrict__ C,
                int M, int N, int K,
                long sAg, long sWg, long sCg)
{
    extern __shared__ uint32_t dyn[];
    constexpr int AW = TM * 36;          // A stage words (32 + 4 pad per row)
    constexpr int SW = AW + 32 * 136;    // total stage words
    constexpr int WM = TM / 2;           // warp m-extent (64 or 32)
    constexpr int MT = WM / 16;          // m16 tiles per warp (4 or 2)

    int g = blockIdx.z;
    A += (long)g * sAg;
    W += (long)g * sWg;
    if (SMODE == 0) C += (long)g * sCg;

    int tid  = threadIdx.x;
    int warp = tid >> 5;
    int lane = tid & 31;
    int wm = (warp & 1) * WM;
    int wn = (warp >> 1) * 32;
    int gID = lane >> 2;
    int tig = lane & 3;
    int rowBase = blockIdx.y * TM;
    int colBase = blockIdx.x * 128;

    const float* Abase = A + (long)rowBase * K;
    const float* Wbase = W + colBase;

    // NG: zero-fill pad columns of both B stages once
    if (NG) {
#pragma unroll
        for (int s = 0; s < 2; s++) {
            uint32_t* Bs = dyn + s * SW + AW;
            for (int f = tid; f < 1024; f += 256) {
                int kr = f >> 5, n4 = (f & 31) * 4;
                if (n4 + 4 > N)
                    *(uint4*)&Bs[kr * 136 + n4] = make_uint4(0, 0, 0, 0);
            }
        }
        __syncthreads();
    }

    auto stage = [&](int buf, int k0) {
        uint32_t* As = dyn + buf * SW;
        uint32_t* Bs = dyn + buf * SW + AW;
#pragma unroll
        for (int it = 0; it < TM / 32; it++) {      // TM*8/256
            int f = tid + it * 256;
            int r = f >> 3, k4 = (f & 7) * 4;
            asm volatile("cp.async.ca.shared.global [%0], [%1], 16;\n"
                         :: "r"(smem_u32(&As[r * 36 + k4])),
                            "l"(Abase + (long)r * K + k0 + k4));
        }
#pragma unroll
        for (int it = 0; it < 4; it++) {
            int f = tid + it * 256;
            int kr = f >> 5, n4 = (f & 31) * 4;
            if (!NG || n4 + 4 <= N)
                asm volatile("cp.async.ca.shared.global [%0], [%1], 16;\n"
                             :: "r"(smem_u32(&Bs[kr * 136 + n4])),
                                "l"(Wbase + (long)(k0 + kr) * N + n4));
        }
        asm volatile("cp.async.commit_group;\n");
    };

    float acc[MT][4][4];
#pragma unroll
    for (int a = 0; a < MT; a++)
#pragma unroll
        for (int b = 0; b < 4; b++)
#pragma unroll
            for (int c = 0; c < 4; c++) acc[a][b][c] = 0.f;

    auto compute = [&](int buf) {
        uint32_t* As = dyn + buf * SW;
        uint32_t* Bs = dyn + buf * SW + AW;
#pragma unroll
        for (int ks = 0; ks < 32; ks += 8) {
            uint32_t bf[4][2];
#pragma unroll
            for (int nt = 0; nt < 4; nt++) {
                int col = wn + nt * 8 + gID;
                bf[nt][0] = Bs[(ks + tig) * 136 + col] + 0x1000u;
                bf[nt][1] = Bs[(ks + tig + 4) * 136 + col] + 0x1000u;
            }
#pragma unroll
            for (int mt = 0; mt < MT; mt++) {
                int row = wm + mt * 16 + gID;
                uint32_t a0 = As[row * 36 + ks + tig] + 0x1000u;
                uint32_t a1 = As[(row + 8) * 36 + ks + tig] + 0x1000u;
                uint32_t a2 = As[row * 36 + ks + tig + 4] + 0x1000u;
                uint32_t a3 = As[(row + 8) * 36 + ks + tig + 4] + 0x1000u;
#pragma unroll
                for (int nt = 0; nt < 4; nt++) {
                    asm volatile(
                        "mma.sync.aligned.m16n8k8.row.col.f32.tf32.tf32.f32 "
                        "{%0,%1,%2,%3}, {%4,%5,%6,%7}, {%8,%9}, {%0,%1,%2,%3};\n"
                        : "+f"(acc[mt][nt][0]), "+f"(acc[mt][nt][1]),
                          "+f"(acc[mt][nt][2]), "+f"(acc[mt][nt][3])
                        : "r"(a0), "r"(a1), "r"(a2), "r"(a3),
                          "r"(bf[nt][0]), "r"(bf[nt][1]));
                }
            }
        }
    };

    int nk = K >> 5;
    stage(0, 0);
    for (int ki = 0; ki < nk; ki++) {
        if (ki + 1 < nk) {
            stage((ki + 1) & 1, (ki + 1) << 5);
            asm volatile("cp.async.wait_group 1;\n");
        } else {
            asm volatile("cp.async.wait_group 0;\n");
        }
        __syncthreads();
        compute(ki & 1);
        __syncthreads();
    }

    // epilogue
#pragma unroll
    for (int mt = 0; mt < MT; mt++) {
        int row0 = rowBase + wm + mt * 16 + gID;
#pragma unroll
        for (int nt = 0; nt < 4; nt++) {
            int col = colBase + wn + nt * 8 + tig * 2;
            if (NG && col >= N) continue;
            float b0 = 0.f, b1 = 0.f;
            if (bias) { b0 = bias[col]; b1 = bias[col + 1]; }
            float v[4];
            v[0] = acc[mt][nt][0] + b0;
            v[1] = acc[mt][nt][1] + b1;
            v[2] = acc[mt][nt][2] + b0;
            v[3] = acc[mt][nt][3] + b1;
            if (ACT == 2) {
#pragma unroll
                for (int q = 0; q < 4; q++)
                    v[q] = 0.5f * v[q] * (1.f + erff(v[q] * 0.70710678118654752f));
            }
#pragma unroll
            for (int h = 0; h < 2; h++) {
                int row = row0 + h * 8;
                float2 val = make_float2(v[h * 2], v[h * 2 + 1]);
                if (SMODE == 0) {
                    *(float2*)&C[(long)row * N + col] = val;
                } else if (SMODE == 1) {
                    if (col < 128) {
                        *(float2*)&C[(long)row * 128 + col] = val;
                    } else {
                        long b = row >> 9, t = row & 511;
                        *(float2*)&C[MTOK * 128 + ((b << 9) + 511 - t) * 128 + (col - 128)] = val;
                    }
                } else {
                    if (g == 0) {
                        *(float2*)&C[(long)row * 256 + col] = val;
                    } else {
                        long b = row >> 9, t = row & 511;
                        *(float2*)&C[((b << 9) + 511 - t) * 256 + 128 + col] = val;
                    }
                }
            }
        }
    }
}

// ---------------------------------------------------------------------------
// fp32 SGEMM (dt projection: K=8, fused softplus). act: 0=none, 1=softplus
// ---------------------------------------------------------------------------
__global__ void sgemm_kernel(const float* __restrict__ A,
                             const float* __restrict__ W,
                             const float* __restrict__ bias,
                             float* __restrict__ C,
                             int M, int N, int K, int lda, int act,
                             long sAg, long sWg, long sCg, long sBg)
{
    int g = blockIdx.z;
    A += (long)g * sAg;
    W += (long)g * sWg;
    C += (long)g * sCg;
    if (bias) bias += (long)g * sBg;

    __shared__ __align__(16) float As[16][128];
    __shared__ __align__(16) float Ws[16][64];

    int tid = threadIdx.x;
    int tx = tid & 15;
    int ty = tid >> 4;
    int rowBase = blockIdx.y * 128;
    int colBase = blockIdx.x * 64;

    float acc[8][4];
#pragma unroll
    for (int i = 0; i < 8; i++)
#pragma unroll
        for (int j = 0; j < 4; j++) acc[i][j] = 0.f;

    for (int k0 = 0; k0 < K; k0 += 16) {
#pragma unroll
        for (int it = 0; it < 8; it++) {
            int idx = tid + it * 256;
            int m = idx >> 4;
            int kk = idx & 15;
            int gr = rowBase + m, gk = k0 + kk;
            As[kk][m] = (gr < M && gk < K) ? A[(long)gr * lda + gk] : 0.f;
        }
#pragma unroll
        for (int it = 0; it < 4; it++) {
            int idx = tid + it * 256;
            int kk = idx >> 6;
            int n = idx & 63;
            int gk = k0 + kk, gn = colBase + n;
            Ws[kk][n] = (gk < K && gn < N) ? W[(long)gk * N + gn] : 0.f;
        }
        __syncthreads();
#pragma unroll
        for (int k = 0; k < 16; k++) {
            float a[8], w[4];
            float4 a0 = *(const float4*)&As[k][ty * 8];
            float4 a1 = *(const float4*)&As[k][ty * 8 + 4];
            a[0] = a0.x; a[1] = a0.y; a[2] = a0.z; a[3] = a0.w;
            a[4] = a1.x; a[5] = a1.y; a[6] = a1.z; a[7] = a1.w;
            float4 w0 = *(const float4*)&Ws[k][tx * 4];
            w[0] = w0.x; w[1] = w0.y; w[2] = w0.z; w[3] = w0.w;
#pragma unroll
            for (int i = 0; i < 8; i++)
#pragma unroll
                for (int j = 0; j < 4; j++)
                    acc[i][j] = fmaf(a[i], w[j], acc[i][j]);
        }
        __syncthreads();
    }

#pragma unroll
    for (int i = 0; i < 8; i++) {
        int gr = rowBase + ty * 8 + i;
        if (gr >= M) continue;
#pragma unroll
        for (int j = 0; j < 4; j++) {
            int gn = colBase + tx * 4 + j;
            if (gn >= N) continue;
            float v = acc[i][j];
            if (bias) v += bias[gn];
            if (act == 1) v = (v > 20.f) ? v : log1pf(expf(v));
            C[(long)gr * N + gn] = v;
        }
    }
}

// ---------------------------------------------------------------------------
// depthwise causal conv (K=4) + bias + silu
// ---------------------------------------------------------------------------
__global__ void conv_silu_kernel(const float* __restrict__ xz,
                                 const float* __restrict__ convw,
                                 const float* __restrict__ convb,
                                 float* __restrict__ xc)
{
    long i = (long)blockIdx.x * 256 + threadIdx.x;
    if (i >= 2 * MTOK * 256) return;
    int d = (int)(i & 255);
    long gm = i >> 8;
    int g = (int)(gm / MTOK);
    long m = gm % MTOK;
    int t = (int)(m & 511);

    const float* w = convw + ((long)g * 256 + d) * 4;
    const float* xp = xz + ((long)g * MTOK + m) * 512 + d;
    float acc = convb[(long)g * 256 + d];
#pragma unroll
    for (int k = 0; k < 4; k++) {
        int tt = t - 3 + k;
        if (tt >= 0) acc = fmaf(xp[(long)(k - 3) * 512], w[k], acc);
    }
    xc[i] = acc / (1.f + __expf(-acc));
}

// ---------------------------------------------------------------------------
// Selective scan (+ fused output gate y *= silu(z)), z prefetched
// ---------------------------------------------------------------------------
__global__ void scan_kernel(const float* __restrict__ dt,
                            const float* __restrict__ xc,
                            const float* __restrict__ dbc,
                            const float* __restrict__ xz,
                            const float* __restrict__ alog,
                            const float* __restrict__ dpar,
                            float* __restrict__ y)
{
    int grp = blockIdx.x * 16 + (threadIdx.x >> 4);
    int n = threadIdx.x & 15;
    int g = grp >> 12;
    int bd = grp & 4095;
    int b = bd >> 8;
    int d = bd & 255;

    float A = -__expf(alog[((long)(g * 256 + d)) * 16 + n]);
    float dp = dpar[(long)g * 256 + d];

    long mbase = (long)g * MTOK + (long)b * 512;
    const float* dtp = dt + mbase * 256 + d;
    const float* xcp = xc + mbase * 256 + d;
    const float* dbp = dbc + mbase * 40;
    const float* zp  = xz + mbase * 512 + 256 + d;
    float* yp = y + mbase * 256 + d;

    float h = 0.f;
    float z_nxt = zp[0];
    for (int t = 0; t < 512; t++) {
        float z = z_nxt;
        int tn = (t + 1 < 512) ? t + 1 : 511;
        z_nxt = zp[(long)tn * 512];
        float dtv = dtp[(long)t * 256];
        float xv = xcp[(long)t * 256];
        float Bn = dbp[(long)t * 40 + 8 + n];
        float Cn = dbp[(long)t * 40 + 24 + n];
        h = __expf(dtv * A) * h + dtv * Bn * xv;
        float p = h * Cn;
        p += __shfl_xor_sync(0xffffffffu, p, 8);
        p += __shfl_xor_sync(0xffffffffu, p, 4);
        p += __shfl_xor_sync(0xffffffffu, p, 2);
        p += __shfl_xor_sync(0xffffffffu, p, 1);
        if (n == 0) {
            float sz = z / (1.f + __expf(-z));
            yp[(long)t * 256] = (p + dp * xv) * sz;
        }
    }
}

// ---------------------------------------------------------------------------
// Launch helpers
// ---------------------------------------------------------------------------
template<int TM, int ACT, int SMODE, bool NG>
static void launch_tf32(const float* A, const float* W, const float* bias, float* C,
                        int M, int N, int K, int G,
                        long sAg, long sWg, long sCg)
{
    constexpr int SMEM = 2 * (TM * 36 + 32 * 136) * 4;
    cudaFuncSetAttribute(tf32gemm_kernel<TM, ACT, SMODE, NG>,
                         cudaFuncAttributeMaxDynamicSharedMemorySize, SMEM);
    dim3 grid((N + 127) / 128, M / TM, G);
    tf32gemm_kernel<TM, ACT, SMODE, NG><<<grid, 256, SMEM>>>(A, W, bias, C, M, N, K,
                                                             sAg, sWg, sCg);
}

static void launch_sgemm(const float* A, const float* W, const float* bias, float* C,
                         int M, int N, int K, int lda, int act, int G,
                         long sAg, long sWg, long sCg, long sBg)
{
    dim3 grid((N + 63) / 64, (M + 127) / 128, G);
    sgemm_kernel<<<grid, 256>>>(A, W, bias, C, M, N, K, lda, act, sAg, sWg, sCg, sBg);
}

extern "C" void kernel_launch(void* const* d_in, const int* in_sizes, int n_in,
                              void* d_out, int out_size)
{
    const float* input_ids = (const float*)d_in[0];
    const float* proj_w    = (const float*)d_in[1];
    const float* proj_b    = (const float*)d_in[2];
    const float* ln0_g     = (const float*)d_in[3];
    const float* ln0_b     = (const float*)d_in[4];
    const float* ln1_g     = (const float*)d_in[5];
    const float* ln1_b     = (const float*)d_in[6];
    const float* ip_w      = (const float*)d_in[7];
    const float* ip_b      = (const float*)d_in[8];
    const float* s_inw     = (const float*)d_in[9];
    const float* s_convw   = (const float*)d_in[10];
    const float* s_convb   = (const float*)d_in[11];
    const float* s_xw      = (const float*)d_in[12];
    const float* s_dtw     = (const float*)d_in[13];
    const float* s_dtb     = (const float*)d_in[14];
    const float* s_alog    = (const float*)d_in[15];
    const float* s_d       = (const float*)d_in[16];
    const float* s_outw    = (const float*)d_in[17];
    const float* op_w      = (const float*)d_in[18];
    const float* op_b      = (const float*)d_in[19];
    const float* ln2_g     = (const float*)d_in[20];
    const float* ln2_b     = (const float*)d_in[21];
    const float* f_w1      = (const float*)d_in[22];
    const float* f_b1      = (const float*)d_in[23];
    const float* f_w2      = (const float*)d_in[24];
    const float* f_b2      = (const float*)d_in[25];
    const float* ln3_g     = (const float*)d_in[26];
    const float* ln3_b     = (const float*)d_in[27];

    float* base = nullptr;
    cudaGetSymbolAddress((void**)&base, g_buf);

    float* X    = base + OFF_X;
    float* LNb  = base + OFF_LN;
    float* B256 = base + OFF_B256;
    float* U    = base + OFF_U;
    float* XZ   = base + OFF_XZ;
    float* XC   = base + OFF_XC;
    float* DBC  = base + OFF_DBC;
    float* DT   = base + OFF_DT;
    float* Y    = base + OFF_Y;
    float* CAT  = base + OFF_CAT;

    float* FF   = base + OFF_FF;

    const int M = (int)MTOK;
    const long EW2 = 2 * MTOK * 256;
    const int EW2_BLOCKS = (int)((EW2 + 255) / 256);
    const int LN_BLOCKS = (int)(MTOK / 8);

    embed_ln_kernel<<<M, 256>>>(input_ids, proj_w, proj_b, ln0_g, ln0_b, X);

    for (int l = 0; l < 12; l++) {
        // LN1 (warp-per-token)
        ln_kernel<<<LN_BLOCKS, 256>>>(X, nullptr, ln1_g + l * 256, ln1_b + l * 256, LNb);
        // in-proj -> fused split+reverse into U (TM=64: 256 CTAs)
        launch_tf32<64, 0, 1, false>(LNb, ip_w + (long)l * 256 * 256, ip_b + l * 256, U,
                                     M, 256, 256, 1, 0, 0, 0);
        // xz = u @ inw (batched 2; 512 CTAs)
        launch_tf32<128, 0, 0, false>(U, s_inw + (long)l * 2 * 128 * 512, nullptr, XZ,
                                      M, 512, 128, 2, MTOK * 128, 128 * 512, MTOK * 512);
        // conv + silu
        conv_silu_kernel<<<EW2_BLOCKS, 256>>>(XZ, s_convw + (long)l * 2 * 256 * 4,
                                              s_convb + (long)l * 2 * 256, XC);
        // dbc = xc @ xw (tf32, N=40 guarded, TM=64)
        launch_tf32<64, 0, 0, true>(XC, s_xw + (long)l * 2 * 256 * 40, nullptr, DBC,
                                    M, 40, 256, 2, MTOK * 256, 256 * 40, MTOK * 40);
        // dt = softplus(dbc[:, :8] @ dtw + dtb)  (fp32, K=8)
        launch_sgemm(DBC, s_dtw + (long)l * 2 * 8 * 256, s_dtb + (long)l * 2 * 256, DT,
                     M, 256, 8, 40, 1, 2, MTOK * 40, 8 * 256, MTOK * 256, 256);
        // selective scan + fused silu(z) gate
        scan_kernel<<<512, 256>>>(DT, XC, DBC, XZ,
                                  s_alog + (long)l * 2 * 256 * 16,
                                  s_d + (long)l * 2 * 256, Y);
        // so = y @ outw (batched 2) -> fused concat+unreverse into CAT (TM=64)
        launch_tf32<64, 0, 2, false>(Y, s_outw + (long)l * 2 * 256 * 128, nullptr, CAT,
                                     M, 128, 256, 2, MTOK * 256, 256 * 128, 0);
        // out-proj (TM=64)
        launch_tf32<64, 0, 0, false>(CAT, op_w + (long)l * 256 * 256, op_b + l * 256, B256,
                                     M, 256, 256, 1, 0, 0, 0);
        // LN2 (residual)
        ln_kernel<<<LN_BLOCKS, 256>>>(B256, X, ln2_g + l * 256, ln2_b + l * 256, X);
        // ff = gelu(x @ w1 + b1) (512 CTAs)
        launch_tf32<128, 2, 0, false>(X, f_w1 + (long)l * 256 * 1024, f_b1 + l * 1024, FF,
                                      M, 1024, 256, 1, 0, 0, 0);
        // f = ff @ w2 + b2 (TM=64: 256 CTAs)
        launch_tf32<64, 0, 0, false>(FF, f_w2 + (long)l * 1024 * 256, f_b2 + l * 256, B256,
                                     M, 256, 1024, 1, 0, 0, 0);
        // LN3 (residual); last layer -> d_out
        float* dst = (l == 11) ? (float*)d_out : X;
        ln_kernel<<<LN_BLOCKS, 256>>>(B256, X, ln3_g + l * 256, ln3_b + l * 256, dst);
    }
}

// round 7
// speedup vs baseline: 1.6921x; 1.0980x over previous
#include <cuda_runtime.h>
#include <math.h>
#include <stdint.h>

constexpr long MTOK  = 16 * 512;     // 8192 tokens

// ---------------------------------------------------------------------------
// Scratch arena
// ---------------------------------------------------------------------------
constexpr long OFF_X    = 0;
constexpr long OFF_LN   = OFF_X    + MTOK * 256;
constexpr long OFF_B256 = OFF_LN   + MTOK * 256;
constexpr long OFF_U    = OFF_B256 + MTOK * 256;
constexpr long OFF_XZ   = OFF_U    + 2 * MTOK * 128;
constexpr long OFF_XC   = OFF_XZ   + 2 * MTOK * 512;
constexpr long OFF_DBC  = OFF_XC   + 2 * MTOK * 256;
constexpr long OFF_DT   = OFF_DBC  + 2 * MTOK * 40;
constexpr long OFF_Y    = OFF_DT   + 2 * MTOK * 256;
constexpr long OFF_CAT  = OFF_Y    + 2 * MTOK * 256;
constexpr long OFF_FF   = OFF_CAT  + MTOK * 256;
constexpr long TOTAL_F  = OFF_FF   + MTOK * 1024;

__device__ float g_buf[TOTAL_F];

__device__ __forceinline__ uint32_t smem_u32(const void* p)
{
    return (uint32_t)__cvta_generic_to_shared(p);
}

// ---------------------------------------------------------------------------
// Embedding: x = LN(ids @ proj_w + proj_b)  (runs once)
// ---------------------------------------------------------------------------
__global__ void embed_ln_kernel(const float* __restrict__ ids,
                                const float* __restrict__ pw,
                                const float* __restrict__ pb,
                                const float* __restrict__ gam,
                                const float* __restrict__ bet,
                                float* __restrict__ x)
{
    __shared__ float sin[32];
    __shared__ float sred[8];
    int m = blockIdx.x, d = threadIdx.x;
    if (d < 32) sin[d] = ids[(long)m * 32 + d];
    __syncthreads();
    float v = pb[d];
#pragma unroll
    for (int e = 0; e < 32; e++)
        v = fmaf(sin[e], pw[e * 256 + d], v);
    float s = v;
#pragma unroll
    for (int o = 16; o > 0; o >>= 1) s += __shfl_xor_sync(0xffffffffu, s, o);
    if ((d & 31) == 0) sred[d >> 5] = s;
    __syncthreads();
    float mean = 0.f;
#pragma unroll
    for (int i = 0; i < 8; i++) mean += sred[i];
    mean *= (1.f / 256.f);
    float c = v - mean;
    float q = c * c;
#pragma unroll
    for (int o = 16; o > 0; o >>= 1) q += __shfl_xor_sync(0xffffffffu, q, o);
    __syncthreads();
    if ((d & 31) == 0) sred[d >> 5] = q;
    __syncthreads();
    float var = 0.f;
#pragma unroll
    for (int i = 0; i < 8; i++) var += sred[i];
    var *= (1.f / 256.f);
    x[(long)m * 256 + d] = c * rsqrtf(var + 1e-5f) * gam[d] + bet[d];
}

// ---------------------------------------------------------------------------
// Warp-per-token LayerNorm over D=256, optional residual. No __syncthreads.
// ---------------------------------------------------------------------------
__global__ void __launch_bounds__(256)
ln_kernel(const float* __restrict__ in,
          const float* __restrict__ res,
          const float* __restrict__ gam,
          const float* __restrict__ bet,
          float* __restrict__ out)
{
    int w = threadIdx.x >> 5, lane = threadIdx.x & 31;
    long m = (long)blockIdx.x * 8 + w;
    const float4* ip = (const float4*)(in + m * 256);
    float4 v0 = ip[lane * 2];
    float4 v1 = ip[lane * 2 + 1];
    if (res) {
        const float4* rp = (const float4*)(res + m * 256);
        float4 r0 = rp[lane * 2];
        float4 r1 = rp[lane * 2 + 1];
        v0.x += r0.x; v0.y += r0.y; v0.z += r0.z; v0.w += r0.w;
        v1.x += r1.x; v1.y += r1.y; v1.z += r1.z; v1.w += r1.w;
    }
    float s = v0.x + v0.y + v0.z + v0.w + v1.x + v1.y + v1.z + v1.w;
#pragma unroll
    for (int o = 16; o > 0; o >>= 1) s += __shfl_xor_sync(0xffffffffu, s, o);
    float mean = s * (1.f / 256.f);
    float a[8] = {v0.x - mean, v0.y - mean, v0.z - mean, v0.w - mean,
                  v1.x - mean, v1.y - mean, v1.z - mean, v1.w - mean};
    float q = 0.f;
#pragma unroll
    for (int i = 0; i < 8; i++) q = fmaf(a[i], a[i], q);
#pragma unroll
    for (int o = 16; o > 0; o >>= 1) q += __shfl_xor_sync(0xffffffffu, q, o);
    float inv = rsqrtf(q * (1.f / 256.f) + 1e-5f);
    const float4* gp = (const float4*)(gam + lane * 8);
    const float4* bp = (const float4*)(bet + lane * 8);
    float4 g0 = gp[0], g1 = gp[1], b0 = bp[0], b1 = bp[1];
    float4 o0, o1;
    o0.x = a[0] * inv * g0.x + b0.x;
    o0.y = a[1] * inv * g0.y + b0.y;
    o0.z = a[2] * inv * g0.z + b0.z;
    o0.w = a[3] * inv * g0.w + b0.w;
    o1.x = a[4] * inv * g1.x + b1.x;
    o1.y = a[5] * inv * g1.y + b1.y;
    o1.z = a[6] * inv * g1.z + b1.z;
    o1.w = a[7] * inv * g1.w + b1.w;
    float4* op = (float4*)(out + m * 256);
    op[lane * 2] = o0;
    op[lane * 2 + 1] = o1;
}

// ---------------------------------------------------------------------------
// TF32 tensor-core GEMM. TM x 128 tile, BK=32, 2-stage cp.async.ca pipeline.
// (unchanged from Round 6)
// ---------------------------------------------------------------------------
template<int TM, int ACT, int SMODE, bool NG>
__global__ void __launch_bounds__(256, 2)
tf32gemm_kernel(const float* __restrict__ A,
                const float* __restrict__ W,
                const float* __restrict__ bias,
                float* __restrict__ C,
                int M, int N, int K,
                long sAg, long sWg, long sCg)
{
    extern __shared__ uint32_t dyn[];
    constexpr int AW = TM * 36;
    constexpr int SW = AW + 32 * 136;
    constexpr int WM = TM / 2;
    constexpr int MT = WM / 16;

    int g = blockIdx.z;
    A += (long)g * sAg;
    W += (long)g * sWg;
    if (SMODE == 0) C += (long)g * sCg;

    int tid  = threadIdx.x;
    int warp = tid >> 5;
    int lane = tid & 31;
    int wm = (warp & 1) * WM;
    int wn = (warp >> 1) * 32;
    int gID = lane >> 2;
    int tig = lane & 3;
    int rowBase = blockIdx.y * TM;
    int colBase = blockIdx.x * 128;

    const float* Abase = A + (long)rowBase * K;
    const float* Wbase = W + colBase;

    if (NG) {
#pragma unroll
        for (int s = 0; s < 2; s++) {
            uint32_t* Bs = dyn + s * SW + AW;
            for (int f = tid; f < 1024; f += 256) {
                int kr = f >> 5, n4 = (f & 31) * 4;
                if (n4 + 4 > N)
                    *(uint4*)&Bs[kr * 136 + n4] = make_uint4(0, 0, 0, 0);
            }
        }
        __syncthreads();
    }

    auto stage = [&](int buf, int k0) {
        uint32_t* As = dyn + buf * SW;
        uint32_t* Bs = dyn + buf * SW + AW;
#pragma unroll
        for (int it = 0; it < TM / 32; it++) {
            int f = tid + it * 256;
            int r = f >> 3, k4 = (f & 7) * 4;
            asm volatile("cp.async.ca.shared.global [%0], [%1], 16;\n"
                         :: "r"(smem_u32(&As[r * 36 + k4])),
                            "l"(Abase + (long)r * K + k0 + k4));
        }
#pragma unroll
        for (int it = 0; it < 4; it++) {
            int f = tid + it * 256;
            int kr = f >> 5, n4 = (f & 31) * 4;
            if (!NG || n4 + 4 <= N)
                asm volatile("cp.async.ca.shared.global [%0], [%1], 16;\n"
                             :: "r"(smem_u32(&Bs[kr * 136 + n4])),
                                "l"(Wbase + (long)(k0 + kr) * N + n4));
        }
        asm volatile("cp.async.commit_group;\n");
    };

    float acc[MT][4][4];
#pragma unroll
    for (int a = 0; a < MT; a++)
#pragma unroll
        for (int b = 0; b < 4; b++)
#pragma unroll
            for (int c = 0; c < 4; c++) acc[a][b][c] = 0.f;

    auto compute = [&](int buf) {
        uint32_t* As = dyn + buf * SW;
        uint32_t* Bs = dyn + buf * SW + AW;
#pragma unroll
        for (int ks = 0; ks < 32; ks += 8) {
            uint32_t bf[4][2];
#pragma unroll
            for (int nt = 0; nt < 4; nt++) {
                int col = wn + nt * 8 + gID;
                bf[nt][0] = Bs[(ks + tig) * 136 + col] + 0x1000u;
                bf[nt][1] = Bs[(ks + tig + 4) * 136 + col] + 0x1000u;
            }
#pragma unroll
            for (int mt = 0; mt < MT; mt++) {
                int row = wm + mt * 16 + gID;
                uint32_t a0 = As[row * 36 + ks + tig] + 0x1000u;
                uint32_t a1 = As[(row + 8) * 36 + ks + tig] + 0x1000u;
                uint32_t a2 = As[row * 36 + ks + tig + 4] + 0x1000u;
                uint32_t a3 = As[(row + 8) * 36 + ks + tig + 4] + 0x1000u;
#pragma unroll
                for (int nt = 0; nt < 4; nt++) {
                    asm volatile(
                        "mma.sync.aligned.m16n8k8.row.col.f32.tf32.tf32.f32 "
                        "{%0,%1,%2,%3}, {%4,%5,%6,%7}, {%8,%9}, {%0,%1,%2,%3};\n"
                        : "+f"(acc[mt][nt][0]), "+f"(acc[mt][nt][1]),
                          "+f"(acc[mt][nt][2]), "+f"(acc[mt][nt][3])
                        : "r"(a0), "r"(a1), "r"(a2), "r"(a3),
                          "r"(bf[nt][0]), "r"(bf[nt][1]));
                }
            }
        }
    };

    int nk = K >> 5;
    stage(0, 0);
    for (int ki = 0; ki < nk; ki++) {
        if (ki + 1 < nk) {
            stage((ki + 1) & 1, (ki + 1) << 5);
            asm volatile("cp.async.wait_group 1;\n");
        } else {
            asm volatile("cp.async.wait_group 0;\n");
        }
        __syncthreads();
        compute(ki & 1);
        __syncthreads();
    }

#pragma unroll
    for (int mt = 0; mt < MT; mt++) {
        int row0 = rowBase + wm + mt * 16 + gID;
#pragma unroll
        for (int nt = 0; nt < 4; nt++) {
            int col = colBase + wn + nt * 8 + tig * 2;
            if (NG && col >= N) continue;
            float b0 = 0.f, b1 = 0.f;
            if (bias) { b0 = bias[col]; b1 = bias[col + 1]; }
            float v[4];
            v[0] = acc[mt][nt][0] + b0;
            v[1] = acc[mt][nt][1] + b1;
            v[2] = acc[mt][nt][2] + b0;
            v[3] = acc[mt][nt][3] + b1;
            if (ACT == 2) {
#pragma unroll
                for (int q = 0; q < 4; q++)
                    v[q] = 0.5f * v[q] * (1.f + erff(v[q] * 0.70710678118654752f));
            }
#pragma unroll
            for (int h = 0; h < 2; h++) {
                int row = row0 + h * 8;
                float2 val = make_float2(v[h * 2], v[h * 2 + 1]);
                if (SMODE == 0) {
                    *(float2*)&C[(long)row * N + col] = val;
                } else if (SMODE == 1) {
                    if (col < 128) {
                        *(float2*)&C[(long)row * 128 + col] = val;
                    } else {
                        long b = row >> 9, t = row & 511;
                        *(float2*)&C[MTOK * 128 + ((b << 9) + 511 - t) * 128 + (col - 128)] = val;
                    }
                } else {
                    if (g == 0) {
                        *(float2*)&C[(long)row * 256 + col] = val;
                    } else {
                        long b = row >> 9, t = row & 511;
                        *(float2*)&C[((b << 9) + 511 - t) * 256 + 128 + col] = val;
                    }
                }
            }
        }
    }
}

// ---------------------------------------------------------------------------
// fp32 SGEMM (dt projection: K=8, fused softplus). act: 0=none, 1=softplus
// ---------------------------------------------------------------------------
__global__ void sgemm_kernel(const float* __restrict__ A,
                             const float* __restrict__ W,
                             const float* __restrict__ bias,
                             float* __restrict__ C,
                             int M, int N, int K, int lda, int act,
                             long sAg, long sWg, long sCg, long sBg)
{
    int g = blockIdx.z;
    A += (long)g * sAg;
    W += (long)g * sWg;
    C += (long)g * sCg;
    if (bias) bias += (long)g * sBg;

    __shared__ __align__(16) float As[16][128];
    __shared__ __align__(16) float Ws[16][64];

    int tid = threadIdx.x;
    int tx = tid & 15;
    int ty = tid >> 4;
    int rowBase = blockIdx.y * 128;
    int colBase = blockIdx.x * 64;

    float acc[8][4];
#pragma unroll
    for (int i = 0; i < 8; i++)
#pragma unroll
        for (int j = 0; j < 4; j++) acc[i][j] = 0.f;

    for (int k0 = 0; k0 < K; k0 += 16) {
#pragma unroll
        for (int it = 0; it < 8; it++) {
            int idx = tid + it * 256;
            int m = idx >> 4;
            int kk = idx & 15;
            int gr = rowBase + m, gk = k0 + kk;
            As[kk][m] = (gr < M && gk < K) ? A[(long)gr * lda + gk] : 0.f;
        }
#pragma unroll
        for (int it = 0; it < 4; it++) {
            int idx = tid + it * 256;
            int kk = idx >> 6;
            int n = idx & 63;
            int gk = k0 + kk, gn = colBase + n;
            Ws[kk][n] = (gk < K && gn < N) ? W[(long)gk * N + gn] : 0.f;
        }
        __syncthreads();
#pragma unroll
        for (int k = 0; k < 16; k++) {
            float a[8], w[4];
            float4 a0 = *(const float4*)&As[k][ty * 8];
            float4 a1 = *(const float4*)&As[k][ty * 8 + 4];
            a[0] = a0.x; a[1] = a0.y; a[2] = a0.z; a[3] = a0.w;
            a[4] = a1.x; a[5] = a1.y; a[6] = a1.z; a[7] = a1.w;
            float4 w0 = *(const float4*)&Ws[k][tx * 4];
            w[0] = w0.x; w[1] = w0.y; w[2] = w0.z; w[3] = w0.w;
#pragma unroll
            for (int i = 0; i < 8; i++)
#pragma unroll
                for (int j = 0; j < 4; j++)
                    acc[i][j] = fmaf(a[i], w[j], acc[i][j]);
        }
        __syncthreads();
    }

#pragma unroll
    for (int i = 0; i < 8; i++) {
        int gr = rowBase + ty * 8 + i;
        if (gr >= M) continue;
#pragma unroll
        for (int j = 0; j < 4; j++) {
            int gn = colBase + tx * 4 + j;
            if (gn >= N) continue;
            float v = acc[i][j];
            if (bias) v += bias[gn];
            if (act == 1) v = (v > 20.f) ? v : log1pf(expf(v));
            C[(long)gr * N + gn] = v;
        }
    }
}

// ---------------------------------------------------------------------------
// depthwise causal conv (K=4) + bias + silu
// ---------------------------------------------------------------------------
__global__ void conv_silu_kernel(const float* __restrict__ xz,
                                 const float* __restrict__ convw,
                                 const float* __restrict__ convb,
                                 float* __restrict__ xc)
{
    long i = (long)blockIdx.x * 256 + threadIdx.x;
    if (i >= 2 * MTOK * 256) return;
    int d = (int)(i & 255);
    long gm = i >> 8;
    int g = (int)(gm / MTOK);
    long m = gm % MTOK;
    int t = (int)(m & 511);

    const float* w = convw + ((long)g * 256 + d) * 4;
    const float* xp = xz + ((long)g * MTOK + m) * 512 + d;
    float acc = convb[(long)g * 256 + d];
#pragma unroll
    for (int k = 0; k < 4; k++) {
        int tt = t - 3 + k;
        if (tt >= 0) acc = fmaf(xp[(long)(k - 3) * 512], w[k], acc);
    }
    xc[i] = acc / (1.f + __expf(-acc));
}

// ---------------------------------------------------------------------------
// Selective scan, 8 lanes per (g,b,d) group, 2 states per lane.
// Fully software-pipelined loads (one iteration ahead) + fused silu(z) gate.
// grid: 8192 groups / 32 per block = 256 blocks x 256 threads.
// ---------------------------------------------------------------------------
__global__ void __launch_bounds__(256)
scan_kernel(const float* __restrict__ dt,
            const float* __restrict__ xc,
            const float* __restrict__ dbc,
            const float* __restrict__ xz,
            const float* __restrict__ alog,
            const float* __restrict__ dpar,
            float* __restrict__ y)
{
    int gidx = blockIdx.x * 32 + (threadIdx.x >> 3);   // group 0..8191
    int li = threadIdx.x & 7;                          // lane in group
    int g = gidx >> 12;
    int b = (gidx >> 8) & 15;
    int d = gidx & 255;

    const float2 al = *(const float2*)&alog[((long)(g * 256 + d)) * 16 + li * 2];
    const float L2E = 1.4426950408889634f;
    float A0 = -__expf(al.x) * L2E;     // pre-scaled for exp2f
    float A1 = -__expf(al.y) * L2E;
    float dp = dpar[(long)g * 256 + d];

    long mbase = (long)g * MTOK + (long)b * 512;
    const float* dtp = dt + mbase * 256 + d;
    const float* xcp = xc + mbase * 256 + d;
    const float* dbp = dbc + mbase * 40;
    const float* zp  = xz + mbase * 512 + 256 + d;
    float* yp = y + mbase * 256 + d;

    float h0 = 0.f, h1 = 0.f;

    // prefetch t=0
    float dtv_n = dtp[0];
    float xv_n  = xcp[0];
    float z_n   = zp[0];
    float2 B_n  = *(const float2*)&dbp[8 + li * 2];
    float2 C_n  = *(const float2*)&dbp[24 + li * 2];

    for (int t = 0; t < 512; t++) {
        float dtv = dtv_n, xv = xv_n, z = z_n;
        float2 Bv = B_n, Cv = C_n;
        long tn = (t + 1 < 512) ? t + 1 : 511;
        dtv_n = dtp[tn * 256];
        xv_n  = xcp[tn * 256];
        z_n   = zp[tn * 512];
        B_n   = *(const float2*)&dbp[tn * 40 + 8 + li * 2];
        C_n   = *(const float2*)&dbp[tn * 40 + 24 + li * 2];

        float dx = dtv * xv;
        h0 = exp2f(dtv * A0) * h0 + dx * Bv.x;
        h1 = exp2f(dtv * A1) * h1 + dx * Bv.y;
        float p = h0 * Cv.x + h1 * Cv.y;
        p += __shfl_xor_sync(0xffffffffu, p, 4);
        p += __shfl_xor_sync(0xffffffffu, p, 2);
        p += __shfl_xor_sync(0xffffffffu, p, 1);
        if (li == 0) {
            float sz = z / (1.f + __expf(-z));
            yp[(long)t * 256] = (p + dp * xv) * sz;
        }
    }
}

// ---------------------------------------------------------------------------
// Launch helpers
// ---------------------------------------------------------------------------
template<int TM, int ACT, int SMODE, bool NG>
static void launch_tf32(const float* A, const float* W, const float* bias, float* C,
                        int M, int N, int K, int G,
                        long sAg, long sWg, long sCg)
{
    constexpr int SMEM = 2 * (TM * 36 + 32 * 136) * 4;
    cudaFuncSetAttribute(tf32gemm_kernel<TM, ACT, SMODE, NG>,
                         cudaFuncAttributeMaxDynamicSharedMemorySize, SMEM);
    dim3 grid((N + 127) / 128, M / TM, G);
    tf32gemm_kernel<TM, ACT, SMODE, NG><<<grid, 256, SMEM>>>(A, W, bias, C, M, N, K,
                                                             sAg, sWg, sCg);
}

static void launch_sgemm(const float* A, const float* W, const float* bias, float* C,
                         int M, int N, int K, int lda, int act, int G,
                         long sAg, long sWg, long sCg, long sBg)
{
    dim3 grid((N + 63) / 64, (M + 127) / 128, G);
    sgemm_kernel<<<grid, 256>>>(A, W, bias, C, M, N, K, lda, act, sAg, sWg, sCg, sBg);
}

extern "C" void kernel_launch(void* const* d_in, const int* in_sizes, int n_in,
                              void* d_out, int out_size)
{
    const float* input_ids = (const float*)d_in[0];
    const float* proj_w    = (const float*)d_in[1];
    const float* proj_b    = (const float*)d_in[2];
    const float* ln0_g     = (const float*)d_in[3];
    const float* ln0_b     = (const float*)d_in[4];
    const float* ln1_g     = (const float*)d_in[5];
    const float* ln1_b     = (const float*)d_in[6];
    const float* ip_w      = (const float*)d_in[7];
    const float* ip_b      = (const float*)d_in[8];
    const float* s_inw     = (const float*)d_in[9];
    const float* s_convw   = (const float*)d_in[10];
    const float* s_convb   = (const float*)d_in[11];
    const float* s_xw      = (const float*)d_in[12];
    const float* s_dtw     = (const float*)d_in[13];
    const float* s_dtb     = (const float*)d_in[14];
    const float* s_alog    = (const float*)d_in[15];
    const float* s_d       = (const float*)d_in[16];
    const float* s_outw    = (const float*)d_in[17];
    const float* op_w      = (const float*)d_in[18];
    const float* op_b      = (const float*)d_in[19];
    const float* ln2_g     = (const float*)d_in[20];
    const float* ln2_b     = (const float*)d_in[21];
    const float* f_w1      = (const float*)d_in[22];
    const float* f_b1      = (const float*)d_in[23];
    const float* f_w2      = (const float*)d_in[24];
    const float* f_b2      = (const float*)d_in[25];
    const float* ln3_g     = (const float*)d_in[26];
    const float* ln3_b     = (const float*)d_in[27];

    float* base = nullptr;
    cudaGetSymbolAddress((void**)&base, g_buf);

    float* X    = base + OFF_X;
    float* LNb  = base + OFF_LN;
    float* B256 = base + OFF_B256;
    float* U    = base + OFF_U;
    float* XZ   = base + OFF_XZ;
    float* XC   = base + OFF_XC;
    float* DBC  = base + OFF_DBC;
    float* DT   = base + OFF_DT;
    float* Y    = base + OFF_Y;
    float* CAT  = base + OFF_CAT;
    float* FF   = base + OFF_FF;

    const int M = (int)MTOK;
    const long EW2 = 2 * MTOK * 256;
    const int EW2_BLOCKS = (int)((EW2 + 255) / 256);
    const int LN_BLOCKS = (int)(MTOK / 8);

    embed_ln_kernel<<<M, 256>>>(input_ids, proj_w, proj_b, ln0_g, ln0_b, X);

    for (int l = 0; l < 12; l++) {
        // LN1 (warp-per-token)
        ln_kernel<<<LN_BLOCKS, 256>>>(X, nullptr, ln1_g + l * 256, ln1_b + l * 256, LNb);
        // in-proj -> fused split+reverse into U
        launch_tf32<64, 0, 1, false>(LNb, ip_w + (long)l * 256 * 256, ip_b + l * 256, U,
                                     M, 256, 256, 1, 0, 0, 0);
        // xz = u @ inw (batched 2)
        launch_tf32<128, 0, 0, false>(U, s_inw + (long)l * 2 * 128 * 512, nullptr, XZ,
                                      M, 512, 128, 2, MTOK * 128, 128 * 512, MTOK * 512);
        // conv + silu
        conv_silu_kernel<<<EW2_BLOCKS, 256>>>(XZ, s_convw + (long)l * 2 * 256 * 4,
                                              s_convb + (long)l * 2 * 256, XC);
        // dbc = xc @ xw (tf32, N=40 guarded)
        launch_tf32<64, 0, 0, true>(XC, s_xw + (long)l * 2 * 256 * 40, nullptr, DBC,
                                    M, 40, 256, 2, MTOK * 256, 256 * 40, MTOK * 40);
        // dt = softplus(dbc[:, :8] @ dtw + dtb)
        launch_sgemm(DBC, s_dtw + (long)l * 2 * 8 * 256, s_dtb + (long)l * 2 * 256, DT,
                     M, 256, 8, 40, 1, 2, MTOK * 40, 8 * 256, MTOK * 256, 256);
        // selective scan + fused silu(z) gate (8-lane groups, pipelined)
        scan_kernel<<<256, 256>>>(DT, XC, DBC, XZ,
                                  s_alog + (long)l * 2 * 256 * 16,
                                  s_d + (long)l * 2 * 256, Y);
        // so = y @ outw -> fused concat+unreverse into CAT
        launch_tf32<64, 0, 2, false>(Y, s_outw + (long)l * 2 * 256 * 128, nullptr, CAT,
                                     M, 128, 256, 2, MTOK * 256, 256 * 128, 0);
        // out-proj
        launch_tf32<64, 0, 0, false>(CAT, op_w + (long)l * 256 * 256, op_b + l * 256, B256,
                                     M, 256, 256, 1, 0, 0, 0);
        // LN2 (residual)
        ln_kernel<<<LN_BLOCKS, 256>>>(B256, X, ln2_g + l * 256, ln2_b + l * 256, X);
        // ff = gelu(x @ w1 + b1)
        launch_tf32<128, 2, 0, false>(X, f_w1 + (long)l * 256 * 1024, f_b1 + l * 1024, FF,
                                      M, 1024, 256, 1, 0, 0, 0);
        // f = ff @ w2 + b2
        launch_tf32<64, 0, 0, false>(FF, f_w2 + (long)l * 1024 * 256, f_b2 + l * 256, B256,
                                     M, 256, 1024, 1, 0, 0, 0);
        // LN3 (residual); last layer -> d_out
        float* dst = (l == 11) ? (float*)d_out : X;
        ln_kernel<<<LN_BLOCKS, 256>>>(B256, X, ln3_g + l * 256, ln3_b + l * 256, dst);
    }
}

// round 8
// speedup vs baseline: 1.7146x; 1.0133x over previous
#include <cuda_runtime.h>
#include <math.h>
#include <stdint.h>

constexpr long MTOK  = 16 * 512;     // 8192 tokens

// ---------------------------------------------------------------------------
// Scratch arena
// ---------------------------------------------------------------------------
constexpr long OFF_X    = 0;
constexpr long OFF_LN   = OFF_X    + MTOK * 256;
constexpr long OFF_B256 = OFF_LN   + MTOK * 256;
constexpr long OFF_U    = OFF_B256 + MTOK * 256;
constexpr long OFF_XZ   = OFF_U    + 2 * MTOK * 128;
constexpr long OFF_XC   = OFF_XZ   + 2 * MTOK * 512;
constexpr long OFF_DBC  = OFF_XC   + 2 * MTOK * 256;
constexpr long OFF_DT   = OFF_DBC  + 2 * MTOK * 40;
constexpr long OFF_Y    = OFF_DT   + 2 * MTOK * 256;
constexpr long OFF_CAT  = OFF_Y    + 2 * MTOK * 256;
constexpr long OFF_FF   = OFF_CAT  + MTOK * 256;
constexpr long TOTAL_F  = OFF_FF   + MTOK * 1024;

__device__ float g_buf[TOTAL_F];

__device__ __forceinline__ uint32_t smem_u32(const void* p)
{
    return (uint32_t)__cvta_generic_to_shared(p);
}

// ---------------------------------------------------------------------------
// Embedding: x = LN(ids @ proj_w + proj_b)  (runs once)
// ---------------------------------------------------------------------------
__global__ void embed_ln_kernel(const float* __restrict__ ids,
                                const float* __restrict__ pw,
                                const float* __restrict__ pb,
                                const float* __restrict__ gam,
                                const float* __restrict__ bet,
                                float* __restrict__ x)
{
    __shared__ float sin[32];
    __shared__ float sred[8];
    int m = blockIdx.x, d = threadIdx.x;
    if (d < 32) sin[d] = ids[(long)m * 32 + d];
    __syncthreads();
    float v = pb[d];
#pragma unroll
    for (int e = 0; e < 32; e++)
        v = fmaf(sin[e], pw[e * 256 + d], v);
    float s = v;
#pragma unroll
    for (int o = 16; o > 0; o >>= 1) s += __shfl_xor_sync(0xffffffffu, s, o);
    if ((d & 31) == 0) sred[d >> 5] = s;
    __syncthreads();
    float mean = 0.f;
#pragma unroll
    for (int i = 0; i < 8; i++) mean += sred[i];
    mean *= (1.f / 256.f);
    float c = v - mean;
    float q = c * c;
#pragma unroll
    for (int o = 16; o > 0; o >>= 1) q += __shfl_xor_sync(0xffffffffu, q, o);
    __syncthreads();
    if ((d & 31) == 0) sred[d >> 5] = q;
    __syncthreads();
    float var = 0.f;
#pragma unroll
    for (int i = 0; i < 8; i++) var += sred[i];
    var *= (1.f / 256.f);
    x[(long)m * 256 + d] = c * rsqrtf(var + 1e-5f) * gam[d] + bet[d];
}

// ---------------------------------------------------------------------------
// Warp-level LN helper on 8 registers (one token spread over a warp)
// ---------------------------------------------------------------------------
__device__ __forceinline__ void warp_ln8(float* a,
                                         const float* __restrict__ gam,
                                         const float* __restrict__ bet,
                                         int lane, float* o)
{
    float s = 0.f;
#pragma unroll
    for (int i = 0; i < 8; i++) s += a[i];
#pragma unroll
    for (int off = 16; off > 0; off >>= 1) s += __shfl_xor_sync(0xffffffffu, s, off);
    float mean = s * (1.f / 256.f);
    float q = 0.f;
#pragma unroll
    for (int i = 0; i < 8; i++) {
        float c = a[i] - mean;
        q = fmaf(c, c, q);
    }
#pragma unroll
    for (int off = 16; off > 0; off >>= 1) q += __shfl_xor_sync(0xffffffffu, q, off);
    float inv = rsqrtf(q * (1.f / 256.f) + 1e-5f);
    const float4* gp = (const float4*)(gam + lane * 8);
    const float4* bp = (const float4*)(bet + lane * 8);
    float4 g0 = gp[0], g1 = gp[1], b0 = bp[0], b1 = bp[1];
    o[0] = (a[0] - mean) * inv * g0.x + b0.x;
    o[1] = (a[1] - mean) * inv * g0.y + b0.y;
    o[2] = (a[2] - mean) * inv * g0.z + b0.z;
    o[3] = (a[3] - mean) * inv * g0.w + b0.w;
    o[4] = (a[4] - mean) * inv * g1.x + b1.x;
    o[5] = (a[5] - mean) * inv * g1.y + b1.y;
    o[6] = (a[6] - mean) * inv * g1.z + b1.z;
    o[7] = (a[7] - mean) * inv * g1.w + b1.w;
}

// ---------------------------------------------------------------------------
// Warp-per-token LayerNorm over D=256, optional residual.
// ---------------------------------------------------------------------------
__global__ void __launch_bounds__(256)
ln_kernel(const float* __restrict__ in,
          const float* __restrict__ res,
          const float* __restrict__ gam,
          const float* __restrict__ bet,
          float* __restrict__ out)
{
    int w = threadIdx.x >> 5, lane = threadIdx.x & 31;
    long m = (long)blockIdx.x * 8 + w;
    const float4* ip = (const float4*)(in + m * 256);
    float4 v0 = ip[lane * 2];
    float4 v1 = ip[lane * 2 + 1];
    if (res) {
        const float4* rp = (const float4*)(res + m * 256);
        float4 r0 = rp[lane * 2];
        float4 r1 = rp[lane * 2 + 1];
        v0.x += r0.x; v0.y += r0.y; v0.z += r0.z; v0.w += r0.w;
        v1.x += r1.x; v1.y += r1.y; v1.z += r1.z; v1.w += r1.w;
    }
    float a[8] = {v0.x, v0.y, v0.z, v0.w, v1.x, v1.y, v1.z, v1.w};
    float o[8];
    warp_ln8(a, gam, bet, lane, o);
    float4* op = (float4*)(out + m * 256);
    op[lane * 2]     = make_float4(o[0], o[1], o[2], o[3]);
    op[lane * 2 + 1] = make_float4(o[4], o[5], o[6], o[7]);
}

// ---------------------------------------------------------------------------
// Fused LN3 + LN1(next layer): x = LN(in + res, g3, b3); lnb = LN(x, g1, b1)
// lnb may be null (last layer).
// ---------------------------------------------------------------------------
__global__ void __launch_bounds__(256)
ln3ln1_kernel(const float* __restrict__ in,
              const float* __restrict__ res,
              const float* __restrict__ g3,
              const float* __restrict__ b3,
              const float* __restrict__ g1,
              const float* __restrict__ b1,
              float* __restrict__ xout,
              float* __restrict__ lnb)
{
    int w = threadIdx.x >> 5, lane = threadIdx.x & 31;
    long m = (long)blockIdx.x * 8 + w;
    const float4* ip = (const float4*)(in + m * 256);
    const float4* rp = (const float4*)(res + m * 256);
    float4 v0 = ip[lane * 2], v1 = ip[lane * 2 + 1];
    float4 r0 = rp[lane * 2], r1 = rp[lane * 2 + 1];
    float a[8] = {v0.x + r0.x, v0.y + r0.y, v0.z + r0.z, v0.w + r0.w,
                  v1.x + r1.x, v1.y + r1.y, v1.z + r1.z, v1.w + r1.w};
    float o[8];
    warp_ln8(a, g3, b3, lane, o);
    float4* xp = (float4*)(xout + m * 256);
    xp[lane * 2]     = make_float4(o[0], o[1], o[2], o[3]);
    xp[lane * 2 + 1] = make_float4(o[4], o[5], o[6], o[7]);
    if (lnb) {
        float o2[8];
        warp_ln8(o, g1, b1, lane, o2);
        float4* lp = (float4*)(lnb + m * 256);
        lp[lane * 2]     = make_float4(o2[0], o2[1], o2[2], o2[3]);
        lp[lane * 2 + 1] = make_float4(o2[4], o2[5], o2[6], o2[7]);
    }
}

// ---------------------------------------------------------------------------
// TF32 tensor-core GEMM. TM x 128 tile, BK=32, 2-stage cp.async.ca pipeline.
// OCC: min blocks per SM (3 for TM=64, 2 for TM=128)
// ---------------------------------------------------------------------------
template<int TM, int ACT, int SMODE, bool NG, int OCC>
__global__ void __launch_bounds__(256, OCC)
tf32gemm_kernel(const float* __restrict__ A,
                const float* __restrict__ W,
                const float* __restrict__ bias,
                float* __restrict__ C,
                int M, int N, int K,
                long sAg, long sWg, long sCg)
{
    extern __shared__ uint32_t dyn[];
    constexpr int AW = TM * 36;
    constexpr int SW = AW + 32 * 136;
    constexpr int WM = TM / 2;
    constexpr int MT = WM / 16;

    int g = blockIdx.z;
    A += (long)g * sAg;
    W += (long)g * sWg;
    if (SMODE == 0) C += (long)g * sCg;

    int tid  = threadIdx.x;
    int warp = tid >> 5;
    int lane = tid & 31;
    int wm = (warp & 1) * WM;
    int wn = (warp >> 1) * 32;
    int gID = lane >> 2;
    int tig = lane & 3;
    int rowBase = blockIdx.y * TM;
    int colBase = blockIdx.x * 128;

    const float* Abase = A + (long)rowBase * K;
    const float* Wbase = W + colBase;

    if (NG) {
#pragma unroll
        for (int s = 0; s < 2; s++) {
            uint32_t* Bs = dyn + s * SW + AW;
            for (int f = tid; f < 1024; f += 256) {
                int kr = f >> 5, n4 = (f & 31) * 4;
                if (n4 + 4 > N)
                    *(uint4*)&Bs[kr * 136 + n4] = make_uint4(0, 0, 0, 0);
            }
        }
        __syncthreads();
    }

    auto stage = [&](int buf, int k0) {
        uint32_t* As = dyn + buf * SW;
        uint32_t* Bs = dyn + buf * SW + AW;
#pragma unroll
        for (int it = 0; it < TM / 32; it++) {
            int f = tid + it * 256;
            int r = f >> 3, k4 = (f & 7) * 4;
            asm volatile("cp.async.ca.shared.global [%0], [%1], 16;\n"
                         :: "r"(smem_u32(&As[r * 36 + k4])),
                            "l"(Abase + (long)r * K + k0 + k4));
        }
#pragma unroll
        for (int it = 0; it < 4; it++) {
            int f = tid + it * 256;
            int kr = f >> 5, n4 = (f & 31) * 4;
            if (!NG || n4 + 4 <= N)
                asm volatile("cp.async.ca.shared.global [%0], [%1], 16;\n"
                             :: "r"(smem_u32(&Bs[kr * 136 + n4])),
                                "l"(Wbase + (long)(k0 + kr) * N + n4));
        }
        asm volatile("cp.async.commit_group;\n");
    };

    float acc[MT][4][4];
#pragma unroll
    for (int a = 0; a < MT; a++)
#pragma unroll
        for (int b = 0; b < 4; b++)
#pragma unroll
            for (int c = 0; c < 4; c++) acc[a][b][c] = 0.f;

    auto compute = [&](int buf) {
        uint32_t* As = dyn + buf * SW;
        uint32_t* Bs = dyn + buf * SW + AW;
#pragma unroll
        for (int ks = 0; ks < 32; ks += 8) {
            uint32_t bf[4][2];
#pragma unroll
            for (int nt = 0; nt < 4; nt++) {
                int col = wn + nt * 8 + gID;
                bf[nt][0] = Bs[(ks + tig) * 136 + col] + 0x1000u;
                bf[nt][1] = Bs[(ks + tig + 4) * 136 + col] + 0x1000u;
            }
#pragma unroll
            for (int mt = 0; mt < MT; mt++) {
                int row = wm + mt * 16 + gID;
                uint32_t a0 = As[row * 36 + ks + tig] + 0x1000u;
                uint32_t a1 = As[(row + 8) * 36 + ks + tig] + 0x1000u;
                uint32_t a2 = As[row * 36 + ks + tig + 4] + 0x1000u;
                uint32_t a3 = As[(row + 8) * 36 + ks + tig + 4] + 0x1000u;
#pragma unroll
                for (int nt = 0; nt < 4; nt++) {
                    asm volatile(
                        "mma.sync.aligned.m16n8k8.row.col.f32.tf32.tf32.f32 "
                        "{%0,%1,%2,%3}, {%4,%5,%6,%7}, {%8,%9}, {%0,%1,%2,%3};\n"
                        : "+f"(acc[mt][nt][0]), "+f"(acc[mt][nt][1]),
                          "+f"(acc[mt][nt][2]), "+f"(acc[mt][nt][3])
                        : "r"(a0), "r"(a1), "r"(a2), "r"(a3),
                          "r"(bf[nt][0]), "r"(bf[nt][1]));
                }
            }
        }
    };

    int nk = K >> 5;
    stage(0, 0);
    for (int ki = 0; ki < nk; ki++) {
        if (ki + 1 < nk) {
            stage((ki + 1) & 1, (ki + 1) << 5);
            asm volatile("cp.async.wait_group 1;\n");
        } else {
            asm volatile("cp.async.wait_group 0;\n");
        }
        __syncthreads();
        compute(ki & 1);
        __syncthreads();
    }

#pragma unroll
    for (int mt = 0; mt < MT; mt++) {
        int row0 = rowBase + wm + mt * 16 + gID;
#pragma unroll
        for (int nt = 0; nt < 4; nt++) {
            int col = colBase + wn + nt * 8 + tig * 2;
            if (NG && col >= N) continue;
            float b0 = 0.f, b1 = 0.f;
            if (bias) { b0 = bias[col]; b1 = bias[col + 1]; }
            float v[4];
            v[0] = acc[mt][nt][0] + b0;
            v[1] = acc[mt][nt][1] + b1;
            v[2] = acc[mt][nt][2] + b0;
            v[3] = acc[mt][nt][3] + b1;
            if (ACT == 2) {
#pragma unroll
                for (int q = 0; q < 4; q++)
                    v[q] = 0.5f * v[q] * (1.f + erff(v[q] * 0.70710678118654752f));
            }
#pragma unroll
            for (int h = 0; h < 2; h++) {
                int row = row0 + h * 8;
                float2 val = make_float2(v[h * 2], v[h * 2 + 1]);
                if (SMODE == 0) {
                    *(float2*)&C[(long)row * N + col] = val;
                } else if (SMODE == 1) {
                    if (col < 128) {
                        *(float2*)&C[(long)row * 128 + col] = val;
                    } else {
                        long b = row >> 9, t = row & 511;
                        *(float2*)&C[MTOK * 128 + ((b << 9) + 511 - t) * 128 + (col - 128)] = val;
                    }
                } else {
                    if (g == 0) {
                        *(float2*)&C[(long)row * 256 + col] = val;
                    } else {
                        long b = row >> 9, t = row & 511;
                        *(float2*)&C[((b << 9) + 511 - t) * 256 + 128 + col] = val;
                    }
                }
            }
        }
    }
}

// ---------------------------------------------------------------------------
// fp32 SGEMM (dt projection: K=8, fused softplus). act: 0=none, 1=softplus
// ---------------------------------------------------------------------------
__global__ void sgemm_kernel(const float* __restrict__ A,
                             const float* __restrict__ W,
                             const float* __restrict__ bias,
                             float* __restrict__ C,
                             int M, int N, int K, int lda, int act,
                             long sAg, long sWg, long sCg, long sBg)
{
    int g = blockIdx.z;
    A += (long)g * sAg;
    W += (long)g * sWg;
    C += (long)g * sCg;
    if (bias) bias += (long)g * sBg;

    __shared__ __align__(16) float As[16][128];
    __shared__ __align__(16) float Ws[16][64];

    int tid = threadIdx.x;
    int tx = tid & 15;
    int ty = tid >> 4;
    int rowBase = blockIdx.y * 128;
    int colBase = blockIdx.x * 64;

    float acc[8][4];
#pragma unroll
    for (int i = 0; i < 8; i++)
#pragma unroll
        for (int j = 0; j < 4; j++) acc[i][j] = 0.f;

    for (int k0 = 0; k0 < K; k0 += 16) {
#pragma unroll
        for (int it = 0; it < 8; it++) {
            int idx = tid + it * 256;
            int m = idx >> 4;
            int kk = idx & 15;
            int gr = rowBase + m, gk = k0 + kk;
            As[kk][m] = (gr < M && gk < K) ? A[(long)gr * lda + gk] : 0.f;
        }
#pragma unroll
        for (int it = 0; it < 4; it++) {
            int idx = tid + it * 256;
            int kk = idx >> 6;
            int n = idx & 63;
            int gk = k0 + kk, gn = colBase + n;
            Ws[kk][n] = (gk < K && gn < N) ? W[(long)gk * N + gn] : 0.f;
        }
        __syncthreads();
#pragma unroll
        for (int k = 0; k < 16; k++) {
            float a[8], w[4];
            float4 a0 = *(const float4*)&As[k][ty * 8];
            float4 a1 = *(const float4*)&As[k][ty * 8 + 4];
            a[0] = a0.x; a[1] = a0.y; a[2] = a0.z; a[3] = a0.w;
            a[4] = a1.x; a[5] = a1.y; a[6] = a1.z; a[7] = a1.w;
            float4 w0 = *(const float4*)&Ws[k][tx * 4];
            w[0] = w0.x; w[1] = w0.y; w[2] = w0.z; w[3] = w0.w;
#pragma unroll
            for (int i = 0; i < 8; i++)
#pragma unroll
                for (int j = 0; j < 4; j++)
                    acc[i][j] = fmaf(a[i], w[j], acc[i][j]);
        }
        __syncthreads();
    }

#pragma unroll
    for (int i = 0; i < 8; i++) {
        int gr = rowBase + ty * 8 + i;
        if (gr >= M) continue;
#pragma unroll
        for (int j = 0; j < 4; j++) {
            int gn = colBase + tx * 4 + j;
            if (gn >= N) continue;
            float v = acc[i][j];
            if (bias) v += bias[gn];
            if (act == 1) v = (v > 20.f) ? v : log1pf(expf(v));
            C[(long)gr * N + gn] = v;
        }
    }
}

// ---------------------------------------------------------------------------
// depthwise causal conv (K=4) + bias + silu
// ---------------------------------------------------------------------------
__global__ void conv_silu_kernel(const float* __restrict__ xz,
                                 const float* __restrict__ convw,
                                 const float* __restrict__ convb,
                                 float* __restrict__ xc)
{
    long i = (long)blockIdx.x * 256 + threadIdx.x;
    if (i >= 2 * MTOK * 256) return;
    int d = (int)(i & 255);
    long gm = i >> 8;
    int g = (int)(gm / MTOK);
    long m = gm % MTOK;
    int t = (int)(m & 511);

    const float* w = convw + ((long)g * 256 + d) * 4;
    const float* xp = xz + ((long)g * MTOK + m) * 512 + d;
    float acc = convb[(long)g * 256 + d];
#pragma unroll
    for (int k = 0; k < 4; k++) {
        int tt = t - 3 + k;
        if (tt >= 0) acc = fmaf(xp[(long)(k - 3) * 512], w[k], acc);
    }
    xc[i] = acc / (1.f + __expf(-acc));
}

// ---------------------------------------------------------------------------
// Selective scan, 8 lanes per (g,b,d) group, 2 states per lane.
// Fully software-pipelined loads + fused silu(z) gate.
// ---------------------------------------------------------------------------
__global__ void __launch_bounds__(256)
scan_kernel(const float* __restrict__ dt,
            const float* __restrict__ xc,
            const float* __restrict__ dbc,
            const float* __restrict__ xz,
            const float* __restrict__ alog,
            const float* __restrict__ dpar,
            float* __restrict__ y)
{
    int gidx = blockIdx.x * 32 + (threadIdx.x >> 3);   // group 0..8191
    int li = threadIdx.x & 7;                          // lane in group
    int g = gidx >> 12;
    int b = (gidx >> 8) & 15;
    int d = gidx & 255;

    const float2 al = *(const float2*)&alog[((long)(g * 256 + d)) * 16 + li * 2];
    const float L2E = 1.4426950408889634f;
    float A0 = -__expf(al.x) * L2E;
    float A1 = -__expf(al.y) * L2E;
    float dp = dpar[(long)g * 256 + d];

    long mbase = (long)g * MTOK + (long)b * 512;
    const float* dtp = dt + mbase * 256 + d;
    const float* xcp = xc + mbase * 256 + d;
    const float* dbp = dbc + mbase * 40;
    const float* zp  = xz + mbase * 512 + 256 + d;
    float* yp = y + mbase * 256 + d;

    float h0 = 0.f, h1 = 0.f;

    float dtv_n = dtp[0];
    float xv_n  = xcp[0];
    float z_n   = zp[0];
    float2 B_n  = *(const float2*)&dbp[8 + li * 2];
    float2 C_n  = *(const float2*)&dbp[24 + li * 2];

    for (int t = 0; t < 512; t++) {
        float dtv = dtv_n, xv = xv_n, z = z_n;
        float2 Bv = B_n, Cv = C_n;
        long tn = (t + 1 < 512) ? t + 1 : 511;
        dtv_n = dtp[tn * 256];
        xv_n  = xcp[tn * 256];
        z_n   = zp[tn * 512];
        B_n   = *(const float2*)&dbp[tn * 40 + 8 + li * 2];
        C_n   = *(const float2*)&dbp[tn * 40 + 24 + li * 2];

        float dx = dtv * xv;
        h0 = exp2f(dtv * A0) * h0 + dx * Bv.x;
        h1 = exp2f(dtv * A1) * h1 + dx * Bv.y;
        float p = h0 * Cv.x + h1 * Cv.y;
        p += __shfl_xor_sync(0xffffffffu, p, 4);
        p += __shfl_xor_sync(0xffffffffu, p, 2);
        p += __shfl_xor_sync(0xffffffffu, p, 1);
        if (li == 0) {
            float sz = z / (1.f + __expf(-z));
            yp[(long)t * 256] = (p + dp * xv) * sz;
        }
    }
}

// ---------------------------------------------------------------------------
// Launch helpers
// ---------------------------------------------------------------------------
template<int TM, int ACT, int SMODE, bool NG, int OCC>
static void launch_tf32(const float* A, const float* W, const float* bias, float* C,
                        int M, int N, int K, int G,
                        long sAg, long sWg, long sCg)
{
    constexpr int SMEM = 2 * (TM * 36 + 32 * 136) * 4;
    cudaFuncSetAttribute(tf32gemm_kernel<TM, ACT, SMODE, NG, OCC>,
                         cudaFuncAttributeMaxDynamicSharedMemorySize, SMEM);
    dim3 grid((N + 127) / 128, M / TM, G);
    tf32gemm_kernel<TM, ACT, SMODE, NG, OCC><<<grid, 256, SMEM>>>(A, W, bias, C,
                                                                  M, N, K,
                                                                  sAg, sWg, sCg);
}

static void launch_sgemm(const float* A, const float* W, const float* bias, float* C,
                         int M, int N, int K, int lda, int act, int G,
                         long sAg, long sWg, long sCg, long sBg)
{
    dim3 grid((N + 63) / 64, (M + 127) / 128, G);
    sgemm_kernel<<<grid, 256>>>(A, W, bias, C, M, N, K, lda, act, sAg, sWg, sCg, sBg);
}

extern "C" void kernel_launch(void* const* d_in, const int* in_sizes, int n_in,
                              void* d_out, int out_size)
{
    const float* input_ids = (const float*)d_in[0];
    const float* proj_w    = (const float*)d_in[1];
    const float* proj_b    = (const float*)d_in[2];
    const float* ln0_g     = (const float*)d_in[3];
    const float* ln0_b     = (const float*)d_in[4];
    const float* ln1_g     = (const float*)d_in[5];
    const float* ln1_b     = (const float*)d_in[6];
    const float* ip_w      = (const float*)d_in[7];
    const float* ip_b      = (const float*)d_in[8];
    const float* s_inw     = (const float*)d_in[9];
    const float* s_convw   = (const float*)d_in[10];
    const float* s_convb   = (const float*)d_in[11];
    const float* s_xw      = (const float*)d_in[12];
    const float* s_dtw     = (const float*)d_in[13];
    const float* s_dtb     = (const float*)d_in[14];
    const float* s_alog    = (const float*)d_in[15];
    const float* s_d       = (const float*)d_in[16];
    const float* s_outw    = (const float*)d_in[17];
    const float* op_w      = (const float*)d_in[18];
    const float* op_b      = (const float*)d_in[19];
    const float* ln2_g     = (const float*)d_in[20];
    const float* ln2_b     = (const float*)d_in[21];
    const float* f_w1      = (const float*)d_in[22];
    const float* f_b1      = (const float*)d_in[23];
    const float* f_w2      = (const float*)d_in[24];
    const float* f_b2      = (const float*)d_in[25];
    const float* ln3_g     = (const float*)d_in[26];
    const float* ln3_b     = (const float*)d_in[27];

    float* base = nullptr;
    cudaGetSymbolAddress((void**)&base, g_buf);

    float* X    = base + OFF_X;
    float* LNb  = base + OFF_LN;
    float* B256 = base + OFF_B256;
    float* U    = base + OFF_U;
    float* XZ   = base + OFF_XZ;
    float* XC   = base + OFF_XC;
    float* DBC  = base + OFF_DBC;
    float* DT   = base + OFF_DT;
    float* Y    = base + OFF_Y;
    float* CAT  = base + OFF_CAT;
    float* FF   = base + OFF_FF;

    const int M = (int)MTOK;
    const long EW2 = 2 * MTOK * 256;
    const int EW2_BLOCKS = (int)((EW2 + 255) / 256);
    const int LN_BLOCKS = (int)(MTOK / 8);

    embed_ln_kernel<<<M, 256>>>(input_ids, proj_w, proj_b, ln0_g, ln0_b, X);
    // first layer's LN1 (later layers get it fused into ln3ln1)
    ln_kernel<<<LN_BLOCKS, 256>>>(X, nullptr, ln1_g, ln1_b, LNb);

    for (int l = 0; l < 12; l++) {
        // in-proj -> fused split+reverse into U (occ 3)
        launch_tf32<64, 0, 1, false, 3>(LNb, ip_w + (long)l * 256 * 256, ip_b + l * 256, U,
                                        M, 256, 256, 1, 0, 0, 0);
        // xz = u @ inw (batched 2)
        launch_tf32<128, 0, 0, false, 2>(U, s_inw + (long)l * 2 * 128 * 512, nullptr, XZ,
                                         M, 512, 128, 2, MTOK * 128, 128 * 512, MTOK * 512);
        // conv + silu
        conv_silu_kernel<<<EW2_BLOCKS, 256>>>(XZ, s_convw + (long)l * 2 * 256 * 4,
                                              s_convb + (long)l * 2 * 256, XC);
        // dbc = xc @ xw (tf32, N=40 guarded, occ 3)
        launch_tf32<64, 0, 0, true, 3>(XC, s_xw + (long)l * 2 * 256 * 40, nullptr, DBC,
                                       M, 40, 256, 2, MTOK * 256, 256 * 40, MTOK * 40);
        // dt = softplus(dbc[:, :8] @ dtw + dtb)
        launch_sgemm(DBC, s_dtw + (long)l * 2 * 8 * 256, s_dtb + (long)l * 2 * 256, DT,
                     M, 256, 8, 40, 1, 2, MTOK * 40, 8 * 256, MTOK * 256, 256);
        // selective scan + fused silu(z) gate
        scan_kernel<<<256, 256>>>(DT, XC, DBC, XZ,
                                  s_alog + (long)l * 2 * 256 * 16,
                                  s_d + (long)l * 2 * 256, Y);
        // so = y @ outw -> fused concat+unreverse into CAT (occ 3)
        launch_tf32<64, 0, 2, false, 3>(Y, s_outw + (long)l * 2 * 256 * 128, nullptr, CAT,
                                        M, 128, 256, 2, MTOK * 256, 256 * 128, 0);
        // out-proj (occ 3)
        launch_tf32<64, 0, 0, false, 3>(CAT, op_w + (long)l * 256 * 256, op_b + l * 256, B256,
                                        M, 256, 256, 1, 0, 0, 0);
        // LN2 (residual)
        ln_kernel<<<LN_BLOCKS, 256>>>(B256, X, ln2_g + l * 256, ln2_b + l * 256, X);
        // ff = gelu(x @ w1 + b1)
        launch_tf32<128, 2, 0, false, 2>(X, f_w1 + (long)l * 256 * 1024, f_b1 + l * 1024, FF,
                                         M, 1024, 256, 1, 0, 0, 0);
        // f = ff @ w2 + b2 (occ 3)
        launch_tf32<64, 0, 0, false, 3>(FF, f_w2 + (long)l * 1024 * 256, f_b2 + l * 256, B256,
                                        M, 256, 1024, 1, 0, 0, 0);
        // LN3 fused with next layer's LN1; last layer writes d_out, no LNb
        float* dst = (l == 11) ? (float*)d_out : X;
        float* lnb = (l == 11) ? nullptr : LNb;
        const float* g1 = ln1_g + (l + 1 < 12 ? (l + 1) * 256 : 0);
        const float* b1 = ln1_b + (l + 1 < 12 ? (l + 1) * 256 : 0);
        ln3ln1_kernel<<<LN_BLOCKS, 256>>>(B256, X, ln3_g + l * 256, ln3_b + l * 256,
                                          g1, b1, dst, lnb);
    }
}

// round 9
// speedup vs baseline: 1.7454x; 1.0180x over previous
#include <cuda_runtime.h>
#include <math.h>
#include <stdint.h>

constexpr long MTOK  = 16 * 512;     // 8192 tokens

// ---------------------------------------------------------------------------
// Scratch arena
// ---------------------------------------------------------------------------
constexpr long OFF_X    = 0;
constexpr long OFF_LN   = OFF_X    + MTOK * 256;
constexpr long OFF_B256 = OFF_LN   + MTOK * 256;
constexpr long OFF_U    = OFF_B256 + MTOK * 256;
constexpr long OFF_XZ   = OFF_U    + 2 * MTOK * 128;
constexpr long OFF_XC   = OFF_XZ   + 2 * MTOK * 512;
constexpr long OFF_DBC  = OFF_XC   + 2 * MTOK * 256;
constexpr long OFF_DT   = OFF_DBC  + 2 * MTOK * 40;
constexpr long OFF_Y    = OFF_DT   + 2 * MTOK * 256;
constexpr long OFF_CAT  = OFF_Y    + 2 * MTOK * 256;
constexpr long OFF_FF   = OFF_CAT  + MTOK * 256;
constexpr long TOTAL_F  = OFF_FF   + MTOK * 1024;

__device__ float g_buf[TOTAL_F];

__device__ __forceinline__ uint32_t smem_u32(const void* p)
{
    return (uint32_t)__cvta_generic_to_shared(p);
}

// ---------------------------------------------------------------------------
// Embedding: x = LN(ids @ proj_w + proj_b)  (runs once)
// ---------------------------------------------------------------------------
__global__ void embed_ln_kernel(const float* __restrict__ ids,
                                const float* __restrict__ pw,
                                const float* __restrict__ pb,
                                const float* __restrict__ gam,
                                const float* __restrict__ bet,
                                float* __restrict__ x)
{
    __shared__ float sin[32];
    __shared__ float sred[8];
    int m = blockIdx.x, d = threadIdx.x;
    if (d < 32) sin[d] = ids[(long)m * 32 + d];
    __syncthreads();
    float v = pb[d];
#pragma unroll
    for (int e = 0; e < 32; e++)
        v = fmaf(sin[e], pw[e * 256 + d], v);
    float s = v;
#pragma unroll
    for (int o = 16; o > 0; o >>= 1) s += __shfl_xor_sync(0xffffffffu, s, o);
    if ((d & 31) == 0) sred[d >> 5] = s;
    __syncthreads();
    float mean = 0.f;
#pragma unroll
    for (int i = 0; i < 8; i++) mean += sred[i];
    mean *= (1.f / 256.f);
    float c = v - mean;
    float q = c * c;
#pragma unroll
    for (int o = 16; o > 0; o >>= 1) q += __shfl_xor_sync(0xffffffffu, q, o);
    __syncthreads();
    if ((d & 31) == 0) sred[d >> 5] = q;
    __syncthreads();
    float var = 0.f;
#pragma unroll
    for (int i = 0; i < 8; i++) var += sred[i];
    var *= (1.f / 256.f);
    x[(long)m * 256 + d] = c * rsqrtf(var + 1e-5f) * gam[d] + bet[d];
}

// ---------------------------------------------------------------------------
// Warp-level LN helper on 8 registers (one token spread over a warp)
// ---------------------------------------------------------------------------
__device__ __forceinline__ void warp_ln8(float* a,
                                         const float* __restrict__ gam,
                                         const float* __restrict__ bet,
                                         int lane, float* o)
{
    float s = 0.f;
#pragma unroll
    for (int i = 0; i < 8; i++) s += a[i];
#pragma unroll
    for (int off = 16; off > 0; off >>= 1) s += __shfl_xor_sync(0xffffffffu, s, off);
    float mean = s * (1.f / 256.f);
    float q = 0.f;
#pragma unroll
    for (int i = 0; i < 8; i++) {
        float c = a[i] - mean;
        q = fmaf(c, c, q);
    }
#pragma unroll
    for (int off = 16; off > 0; off >>= 1) q += __shfl_xor_sync(0xffffffffu, q, off);
    float inv = rsqrtf(q * (1.f / 256.f) + 1e-5f);
    const float4* gp = (const float4*)(gam + lane * 8);
    const float4* bp = (const float4*)(bet + lane * 8);
    float4 g0 = gp[0], g1 = gp[1], b0 = bp[0], b1 = bp[1];
    o[0] = (a[0] - mean) * inv * g0.x + b0.x;
    o[1] = (a[1] - mean) * inv * g0.y + b0.y;
    o[2] = (a[2] - mean) * inv * g0.z + b0.z;
    o[3] = (a[3] - mean) * inv * g0.w + b0.w;
    o[4] = (a[4] - mean) * inv * g1.x + b1.x;
    o[5] = (a[5] - mean) * inv * g1.y + b1.y;
    o[6] = (a[6] - mean) * inv * g1.z + b1.z;
    o[7] = (a[7] - mean) * inv * g1.w + b1.w;
}

// ---------------------------------------------------------------------------
// Warp-per-token LayerNorm over D=256, optional residual.
// ---------------------------------------------------------------------------
__global__ void __launch_bounds__(256)
ln_kernel(const float* __restrict__ in,
          const float* __restrict__ res,
          const float* __restrict__ gam,
          const float* __restrict__ bet,
          float* __restrict__ out)
{
    int w = threadIdx.x >> 5, lane = threadIdx.x & 31;
    long m = (long)blockIdx.x * 8 + w;
    const float4* ip = (const float4*)(in + m * 256);
    float4 v0 = ip[lane * 2];
    float4 v1 = ip[lane * 2 + 1];
    if (res) {
        const float4* rp = (const float4*)(res + m * 256);
        float4 r0 = rp[lane * 2];
        float4 r1 = rp[lane * 2 + 1];
        v0.x += r0.x; v0.y += r0.y; v0.z += r0.z; v0.w += r0.w;
        v1.x += r1.x; v1.y += r1.y; v1.z += r1.z; v1.w += r1.w;
    }
    float a[8] = {v0.x, v0.y, v0.z, v0.w, v1.x, v1.y, v1.z, v1.w};
    float o[8];
    warp_ln8(a, gam, bet, lane, o);
    float4* op = (float4*)(out + m * 256);
    op[lane * 2]     = make_float4(o[0], o[1], o[2], o[3]);
    op[lane * 2 + 1] = make_float4(o[4], o[5], o[6], o[7]);
}

// ---------------------------------------------------------------------------
// Fused LN3 + LN1(next layer)
// ---------------------------------------------------------------------------
__global__ void __launch_bounds__(256)
ln3ln1_kernel(const float* __restrict__ in,
              const float* __restrict__ res,
              const float* __restrict__ g3,
              const float* __restrict__ b3,
              const float* __restrict__ g1,
              const float* __restrict__ b1,
              float* __restrict__ xout,
              float* __restrict__ lnb)
{
    int w = threadIdx.x >> 5, lane = threadIdx.x & 31;
    long m = (long)blockIdx.x * 8 + w;
    const float4* ip = (const float4*)(in + m * 256);
    const float4* rp = (const float4*)(res + m * 256);
    float4 v0 = ip[lane * 2], v1 = ip[lane * 2 + 1];
    float4 r0 = rp[lane * 2], r1 = rp[lane * 2 + 1];
    float a[8] = {v0.x + r0.x, v0.y + r0.y, v0.z + r0.z, v0.w + r0.w,
                  v1.x + r1.x, v1.y + r1.y, v1.z + r1.z, v1.w + r1.w};
    float o[8];
    warp_ln8(a, g3, b3, lane, o);
    float4* xp = (float4*)(xout + m * 256);
    xp[lane * 2]     = make_float4(o[0], o[1], o[2], o[3]);
    xp[lane * 2 + 1] = make_float4(o[4], o[5], o[6], o[7]);
    if (lnb) {
        float o2[8];
        warp_ln8(o, g1, b1, lane, o2);
        float4* lp = (float4*)(lnb + m * 256);
        lp[lane * 2]     = make_float4(o2[0], o2[1], o2[2], o2[3]);
        lp[lane * 2 + 1] = make_float4(o2[4], o2[5], o2[6], o2[7]);
    }
}

// ---------------------------------------------------------------------------
// TF32 GEMM, 512 threads, 128x128 tile, 16 warps of 32x32. BK=32, 2-stage
// cp.async.ca pipeline. occ 2 -> 32 warps/SM (latency hiding is the point).
// M%128==0, N%128==0, K%32==0, lda==K. ACT: 0=none, 2=GELU.
// ---------------------------------------------------------------------------
template<int ACT>
__global__ void __launch_bounds__(512, 2)
tf32gemm512_kernel(const float* __restrict__ A,
                   const float* __restrict__ W,
                   const float* __restrict__ bias,
                   float* __restrict__ C,
                   int M, int N, int K,
                   long sAg, long sWg, long sCg)
{
    extern __shared__ uint32_t dyn[];
    constexpr int AW = 128 * 36;          // 4608 words
    constexpr int SW = AW + 32 * 136;     // 8960 words per stage

    int g = blockIdx.z;
    A += (long)g * sAg;
    W += (long)g * sWg;
    C += (long)g * sCg;

    int tid  = threadIdx.x;
    int warp = tid >> 5;
    int lane = tid & 31;
    int wm = (warp & 3) * 32;      // 4 m-groups
    int wn = (warp >> 2) * 32;     // 4 n-groups
    int gID = lane >> 2;
    int tig = lane & 3;
    int rowBase = blockIdx.y * 128;
    int colBase = blockIdx.x * 128;

    const float* Abase = A + (long)rowBase * K;
    const float* Wbase = W + colBase;

    auto stage = [&](int buf, int k0) {
        uint32_t* As = dyn + buf * SW;
        uint32_t* Bs = dyn + buf * SW + AW;
#pragma unroll
        for (int it = 0; it < 2; it++) {           // A: 128x32 = 1024 float4
            int f = tid + it * 512;
            int r = f >> 3, k4 = (f & 7) * 4;
            asm volatile("cp.async.ca.shared.global [%0], [%1], 16;\n"
                         :: "r"(smem_u32(&As[r * 36 + k4])),
                            "l"(Abase + (long)r * K + k0 + k4));
        }
#pragma unroll
        for (int it = 0; it < 2; it++) {           // B: 32x128 = 1024 float4
            int f = tid + it * 512;
            int kr = f >> 5, n4 = (f & 31) * 4;
            asm volatile("cp.async.ca.shared.global [%0], [%1], 16;\n"
                         :: "r"(smem_u32(&Bs[kr * 136 + n4])),
                            "l"(Wbase + (long)(k0 + kr) * N + n4));
        }
        asm volatile("cp.async.commit_group;\n");
    };

    float acc[2][4][4];
#pragma unroll
    for (int a = 0; a < 2; a++)
#pragma unroll
        for (int b = 0; b < 4; b++)
#pragma unroll
            for (int c = 0; c < 4; c++) acc[a][b][c] = 0.f;

    auto compute = [&](int buf) {
        uint32_t* As = dyn + buf * SW;
        uint32_t* Bs = dyn + buf * SW + AW;
#pragma unroll
        for (int ks = 0; ks < 32; ks += 8) {
            uint32_t bf[4][2];
#pragma unroll
            for (int nt = 0; nt < 4; nt++) {
                int col = wn + nt * 8 + gID;
                bf[nt][0] = Bs[(ks + tig) * 136 + col] + 0x1000u;
                bf[nt][1] = Bs[(ks + tig + 4) * 136 + col] + 0x1000u;
            }
#pragma unroll
            for (int mt = 0; mt < 2; mt++) {
                int row = wm + mt * 16 + gID;
                uint32_t a0 = As[row * 36 + ks + tig] + 0x1000u;
                uint32_t a1 = As[(row + 8) * 36 + ks + tig] + 0x1000u;
                uint32_t a2 = As[row * 36 + ks + tig + 4] + 0x1000u;
                uint32_t a3 = As[(row + 8) * 36 + ks + tig + 4] + 0x1000u;
#pragma unroll
                for (int nt = 0; nt < 4; nt++) {
                    asm volatile(
                        "mma.sync.aligned.m16n8k8.row.col.f32.tf32.tf32.f32 "
                        "{%0,%1,%2,%3}, {%4,%5,%6,%7}, {%8,%9}, {%0,%1,%2,%3};\n"
                        : "+f"(acc[mt][nt][0]), "+f"(acc[mt][nt][1]),
                          "+f"(acc[mt][nt][2]), "+f"(acc[mt][nt][3])
                        : "r"(a0), "r"(a1), "r"(a2), "r"(a3),
                          "r"(bf[nt][0]), "r"(bf[nt][1]));
                }
            }
        }
    };

    int nk = K >> 5;
    stage(0, 0);
    for (int ki = 0; ki < nk; ki++) {
        if (ki + 1 < nk) {
            stage((ki + 1) & 1, (ki + 1) << 5);
            asm volatile("cp.async.wait_group 1;\n");
        } else {
            asm volatile("cp.async.wait_group 0;\n");
        }
        __syncthreads();
        compute(ki & 1);
        __syncthreads();
    }

#pragma unroll
    for (int mt = 0; mt < 2; mt++) {
        int row0 = rowBase + wm + mt * 16 + gID;
#pragma unroll
        for (int nt = 0; nt < 4; nt++) {
            int col = colBase + wn + nt * 8 + tig * 2;
            float b0 = 0.f, b1 = 0.f;
            if (bias) { b0 = bias[col]; b1 = bias[col + 1]; }
            float v[4];
            v[0] = acc[mt][nt][0] + b0;
            v[1] = acc[mt][nt][1] + b1;
            v[2] = acc[mt][nt][2] + b0;
            v[3] = acc[mt][nt][3] + b1;
            if (ACT == 2) {
#pragma unroll
                for (int q = 0; q < 4; q++)
                    v[q] = 0.5f * v[q] * (1.f + erff(v[q] * 0.70710678118654752f));
            }
            *(float2*)&C[(long)row0 * N + col] = make_float2(v[0], v[1]);
            *(float2*)&C[(long)(row0 + 8) * N + col] = make_float2(v[2], v[3]);
        }
    }
}

// ---------------------------------------------------------------------------
// TF32 GEMM, 256 threads, TM x 128 tile (TM=64 path for N<=256 GEMMs).
// ---------------------------------------------------------------------------
template<int TM, int ACT, int SMODE, bool NG, int OCC>
__global__ void __launch_bounds__(256, OCC)
tf32gemm_kernel(const float* __restrict__ A,
                const float* __restrict__ W,
                const float* __restrict__ bias,
                float* __restrict__ C,
                int M, int N, int K,
                long sAg, long sWg, long sCg)
{
    extern __shared__ uint32_t dyn[];
    constexpr int AW = TM * 36;
    constexpr int SW = AW + 32 * 136;
    constexpr int WM = TM / 2;
    constexpr int MT = WM / 16;

    int g = blockIdx.z;
    A += (long)g * sAg;
    W += (long)g * sWg;
    if (SMODE == 0) C += (long)g * sCg;

    int tid  = threadIdx.x;
    int warp = tid >> 5;
    int lane = tid & 31;
    int wm = (warp & 1) * WM;
    int wn = (warp >> 1) * 32;
    int gID = lane >> 2;
    int tig = lane & 3;
    int rowBase = blockIdx.y * TM;
    int colBase = blockIdx.x * 128;

    const float* Abase = A + (long)rowBase * K;
    const float* Wbase = W + colBase;

    if (NG) {
#pragma unroll
        for (int s = 0; s < 2; s++) {
            uint32_t* Bs = dyn + s * SW + AW;
            for (int f = tid; f < 1024; f += 256) {
                int kr = f >> 5, n4 = (f & 31) * 4;
                if (n4 + 4 > N)
                    *(uint4*)&Bs[kr * 136 + n4] = make_uint4(0, 0, 0, 0);
            }
        }
        __syncthreads();
    }

    auto stage = [&](int buf, int k0) {
        uint32_t* As = dyn + buf * SW;
        uint32_t* Bs = dyn + buf * SW + AW;
#pragma unroll
        for (int it = 0; it < TM / 32; it++) {
            int f = tid + it * 256;
            int r = f >> 3, k4 = (f & 7) * 4;
            asm volatile("cp.async.ca.shared.global [%0], [%1], 16;\n"
                         :: "r"(smem_u32(&As[r * 36 + k4])),
                            "l"(Abase + (long)r * K + k0 + k4));
        }
#pragma unroll
        for (int it = 0; it < 4; it++) {
            int f = tid + it * 256;
            int kr = f >> 5, n4 = (f & 31) * 4;
            if (!NG || n4 + 4 <= N)
                asm volatile("cp.async.ca.shared.global [%0], [%1], 16;\n"
                             :: "r"(smem_u32(&Bs[kr * 136 + n4])),
                                "l"(Wbase + (long)(k0 + kr) * N + n4));
        }
        asm volatile("cp.async.commit_group;\n");
    };

    float acc[MT][4][4];
#pragma unroll
    for (int a = 0; a < MT; a++)
#pragma unroll
        for (int b = 0; b < 4; b++)
#pragma unroll
            for (int c = 0; c < 4; c++) acc[a][b][c] = 0.f;

    auto compute = [&](int buf) {
        uint32_t* As = dyn + buf * SW;
        uint32_t* Bs = dyn + buf * SW + AW;
#pragma unroll
        for (int ks = 0; ks < 32; ks += 8) {
            uint32_t bf[4][2];
#pragma unroll
            for (int nt = 0; nt < 4; nt++) {
                int col = wn + nt * 8 + gID;
                bf[nt][0] = Bs[(ks + tig) * 136 + col] + 0x1000u;
                bf[nt][1] = Bs[(ks + tig + 4) * 136 + col] + 0x1000u;
            }
#pragma unroll
            for (int mt = 0; mt < MT; mt++) {
                int row = wm + mt * 16 + gID;
                uint32_t a0 = As[row * 36 + ks + tig] + 0x1000u;
                uint32_t a1 = As[(row + 8) * 36 + ks + tig] + 0x1000u;
                uint32_t a2 = As[row * 36 + ks + tig + 4] + 0x1000u;
                uint32_t a3 = As[(row + 8) * 36 + ks + tig + 4] + 0x1000u;
#pragma unroll
                for (int nt = 0; nt < 4; nt++) {
                    asm volatile(
                        "mma.sync.aligned.m16n8k8.row.col.f32.tf32.tf32.f32 "
                        "{%0,%1,%2,%3}, {%4,%5,%6,%7}, {%8,%9}, {%0,%1,%2,%3};\n"
                        : "+f"(acc[mt][nt][0]), "+f"(acc[mt][nt][1]),
                          "+f"(acc[mt][nt][2]), "+f"(acc[mt][nt][3])
                        : "r"(a0), "r"(a1), "r"(a2), "r"(a3),
                          "r"(bf[nt][0]), "r"(bf[nt][1]));
                }
            }
        }
    };

    int nk = K >> 5;
    stage(0, 0);
    for (int ki = 0; ki < nk; ki++) {
        if (ki + 1 < nk) {
            stage((ki + 1) & 1, (ki + 1) << 5);
            asm volatile("cp.async.wait_group 1;\n");
        } else {
            asm volatile("cp.async.wait_group 0;\n");
        }
        __syncthreads();
        compute(ki & 1);
        __syncthreads();
    }

#pragma unroll
    for (int mt = 0; mt < MT; mt++) {
        int row0 = rowBase + wm + mt * 16 + gID;
#pragma unroll
        for (int nt = 0; nt < 4; nt++) {
            int col = colBase + wn + nt * 8 + tig * 2;
            if (NG && col >= N) continue;
            float b0 = 0.f, b1 = 0.f;
            if (bias) { b0 = bias[col]; b1 = bias[col + 1]; }
            float v[4];
            v[0] = acc[mt][nt][0] + b0;
            v[1] = acc[mt][nt][1] + b1;
            v[2] = acc[mt][nt][2] + b0;
            v[3] = acc[mt][nt][3] + b1;
            if (ACT == 2) {
#pragma unroll
                for (int q = 0; q < 4; q++)
                    v[q] = 0.5f * v[q] * (1.f + erff(v[q] * 0.70710678118654752f));
            }
#pragma unroll
            for (int h = 0; h < 2; h++) {
                int row = row0 + h * 8;
                float2 val = make_float2(v[h * 2], v[h * 2 + 1]);
                if (SMODE == 0) {
                    *(float2*)&C[(long)row * N + col] = val;
                } else if (SMODE == 1) {
                    if (col < 128) {
                        *(float2*)&C[(long)row * 128 + col] = val;
                    } else {
                        long b = row >> 9, t = row & 511;
                        *(float2*)&C[MTOK * 128 + ((b << 9) + 511 - t) * 128 + (col - 128)] = val;
                    }
                } else {
                    if (g == 0) {
                        *(float2*)&C[(long)row * 256 + col] = val;
                    } else {
                        long b = row >> 9, t = row & 511;
                        *(float2*)&C[((b << 9) + 511 - t) * 256 + 128 + col] = val;
                    }
                }
            }
        }
    }
}

// ---------------------------------------------------------------------------
// fp32 SGEMM (dt projection: K=8, fused softplus). act: 0=none, 1=softplus
// ---------------------------------------------------------------------------
__global__ void sgemm_kernel(const float* __restrict__ A,
                             const float* __restrict__ W,
                             const float* __restrict__ bias,
                             float* __restrict__ C,
                             int M, int N, int K, int lda, int act,
                             long sAg, long sWg, long sCg, long sBg)
{
    int g = blockIdx.z;
    A += (long)g * sAg;
    W += (long)g * sWg;
    C += (long)g * sCg;
    if (bias) bias += (long)g * sBg;

    __shared__ __align__(16) float As[16][128];
    __shared__ __align__(16) float Ws[16][64];

    int tid = threadIdx.x;
    int tx = tid & 15;
    int ty = tid >> 4;
    int rowBase = blockIdx.y * 128;
    int colBase = blockIdx.x * 64;

    float acc[8][4];
#pragma unroll
    for (int i = 0; i < 8; i++)
#pragma unroll
        for (int j = 0; j < 4; j++) acc[i][j] = 0.f;

    for (int k0 = 0; k0 < K; k0 += 16) {
#pragma unroll
        for (int it = 0; it < 8; it++) {
            int idx = tid + it * 256;
            int m = idx >> 4;
            int kk = idx & 15;
            int gr = rowBase + m, gk = k0 + kk;
            As[kk][m] = (gr < M && gk < K) ? A[(long)gr * lda + gk] : 0.f;
        }
#pragma unroll
        for (int it = 0; it < 4; it++) {
            int idx = tid + it * 256;
            int kk = idx >> 6;
            int n = idx & 63;
            int gk = k0 + kk, gn = colBase + n;
            Ws[kk][n] = (gk < K && gn < N) ? W[(long)gk * N + gn] : 0.f;
        }
        __syncthreads();
#pragma unroll
        for (int k = 0; k < 16; k++) {
            float a[8], w[4];
            float4 a0 = *(const float4*)&As[k][ty * 8];
            float4 a1 = *(const float4*)&As[k][ty * 8 + 4];
            a[0] = a0.x; a[1] = a0.y; a[2] = a0.z; a[3] = a0.w;
            a[4] = a1.x; a[5] = a1.y; a[6] = a1.z; a[7] = a1.w;
            float4 w0 = *(const float4*)&Ws[k][tx * 4];
            w[0] = w0.x; w[1] = w0.y; w[2] = w0.z; w[3] = w0.w;
#pragma unroll
            for (int i = 0; i < 8; i++)
#pragma unroll
                for (int j = 0; j < 4; j++)
                    acc[i][j] = fmaf(a[i], w[j], acc[i][j]);
        }
        __syncthreads();
    }

#pragma unroll
    for (int i = 0; i < 8; i++) {
        int gr = rowBase + ty * 8 + i;
        if (gr >= M) continue;
#pragma unroll
        for (int j = 0; j < 4; j++) {
            int gn = colBase + tx * 4 + j;
            if (gn >= N) continue;
            float v = acc[i][j];
            if (bias) v += bias[gn];
            if (act == 1) v = (v > 20.f) ? v : log1pf(expf(v));
            C[(long)gr * N + gn] = v;
        }
    }
}

// ---------------------------------------------------------------------------
// depthwise causal conv (K=4) + bias + silu; 4 t-outputs per thread
// ---------------------------------------------------------------------------
__global__ void conv_silu_kernel(const float* __restrict__ xz,
                                 const float* __restrict__ convw,
                                 const float* __restrict__ convb,
                                 float* __restrict__ xc)
{
    long i = (long)blockIdx.x * 256 + threadIdx.x;   // over 2*16*128*256
    if (i >= 2 * MTOK * 64) return;
    int d = (int)(i & 255);
    long q = i >> 8;                  // 0..4095
    int t0 = (int)(q & 127) * 4;
    int b  = (int)((q >> 7) & 15);
    int g  = (int)(q >> 11);

    const float4 w4 = *(const float4*)(convw + ((long)g * 256 + d) * 4);
    float bias = convb[(long)g * 256 + d];

    long mrow = (long)g * MTOK + (long)b * 512 + t0;
    const float* xp = xz + mrow * 512 + d;
    float xv[7];
#pragma unroll
    for (int j = 0; j < 7; j++) {
        int t = t0 - 3 + j;
        xv[j] = (t >= 0) ? xp[(long)(j - 3) * 512] : 0.f;
    }
    float* op = xc + mrow * 256 + d;
#pragma unroll
    for (int j = 0; j < 4; j++) {
        float acc = bias;
        acc = fmaf(xv[j],     w4.x, acc);
        acc = fmaf(xv[j + 1], w4.y, acc);
        acc = fmaf(xv[j + 2], w4.z, acc);
        acc = fmaf(xv[j + 3], w4.w, acc);
        op[(long)j * 256] = acc / (1.f + __expf(-acc));
    }
}

// ---------------------------------------------------------------------------
// Selective scan, 8 lanes per (g,b,d) group, 2 states per lane.
// Fully software-pipelined loads + fused silu(z) gate.
// ---------------------------------------------------------------------------
__global__ void __launch_bounds__(256)
scan_kernel(const float* __restrict__ dt,
            const float* __restrict__ xc,
            const float* __restrict__ dbc,
            const float* __restrict__ xz,
            const float* __restrict__ alog,
            const float* __restrict__ dpar,
            float* __restrict__ y)
{
    int gidx = blockIdx.x * 32 + (threadIdx.x >> 3);   // group 0..8191
    int li = threadIdx.x & 7;                          // lane in group
    int g = gidx >> 12;
    int b = (gidx >> 8) & 15;
    int d = gidx & 255;

    const float2 al = *(const float2*)&alog[((long)(g * 256 + d)) * 16 + li * 2];
    const float L2E = 1.4426950408889634f;
    float A0 = -__expf(al.x) * L2E;
    float A1 = -__expf(al.y) * L2E;
    float dp = dpar[(long)g * 256 + d];

    long mbase = (long)g * MTOK + (long)b * 512;
    const float* dtp = dt + mbase * 256 + d;
    const float* xcp = xc + mbase * 256 + d;
    const float* dbp = dbc + mbase * 40;
    const float* zp  = xz + mbase * 512 + 256 + d;
    float* yp = y + mbase * 256 + d;

    float h0 = 0.f, h1 = 0.f;

    float dtv_n = dtp[0];
    float xv_n  = xcp[0];
    float z_n   = zp[0];
    float2 B_n  = *(const float2*)&dbp[8 + li * 2];
    float2 C_n  = *(const float2*)&dbp[24 + li * 2];

    for (int t = 0; t < 512; t++) {
        float dtv = dtv_n, xv = xv_n, z = z_n;
        float2 Bv = B_n, Cv = C_n;
        long tn = (t + 1 < 512) ? t + 1 : 511;
        dtv_n = dtp[tn * 256];
        xv_n  = xcp[tn * 256];
        z_n   = zp[tn * 512];
        B_n   = *(const float2*)&dbp[tn * 40 + 8 + li * 2];
        C_n   = *(const float2*)&dbp[tn * 40 + 24 + li * 2];

        float dx = dtv * xv;
        h0 = exp2f(dtv * A0) * h0 + dx * Bv.x;
        h1 = exp2f(dtv * A1) * h1 + dx * Bv.y;
        float p = h0 * Cv.x + h1 * Cv.y;
        p += __shfl_xor_sync(0xffffffffu, p, 4);
        p += __shfl_xor_sync(0xffffffffu, p, 2);
        p += __shfl_xor_sync(0xffffffffu, p, 1);
        if (li == 0) {
            float sz = z / (1.f + __expf(-z));
            yp[(long)t * 256] = (p + dp * xv) * sz;
        }
    }
}

// ---------------------------------------------------------------------------
// Launch helpers
// ---------------------------------------------------------------------------
template<int ACT>
static void launch_tf32_512(const float* A, const float* W, const float* bias, float* C,
                            int M, int N, int K, int G,
                            long sAg, long sWg, long sCg)
{
    constexpr int SMEM = 2 * (128 * 36 + 32 * 136) * 4;   // 71680 B
    cudaFuncSetAttribute(tf32gemm512_kernel<ACT>,
                         cudaFuncAttributeMaxDynamicSharedMemorySize, SMEM);
    dim3 grid(N / 128, M / 128, G);
    tf32gemm512_kernel<ACT><<<grid, 512, SMEM>>>(A, W, bias, C, M, N, K,
                                                 sAg, sWg, sCg);
}

template<int TM, int ACT, int SMODE, bool NG, int OCC>
static void launch_tf32(const float* A, const float* W, const float* bias, float* C,
                        int M, int N, int K, int G,
                        long sAg, long sWg, long sCg)
{
    constexpr int SMEM = 2 * (TM * 36 + 32 * 136) * 4;
    cudaFuncSetAttribute(tf32gemm_kernel<TM, ACT, SMODE, NG, OCC>,
                         cudaFuncAttributeMaxDynamicSharedMemorySize, SMEM);
    dim3 grid((N + 127) / 128, M / TM, G);
    tf32gemm_kernel<TM, ACT, SMODE, NG, OCC><<<grid, 256, SMEM>>>(A, W, bias, C,
                                                                  M, N, K,
                                                                  sAg, sWg, sCg);
}

static void launch_sgemm(const float* A, const float* W, const float* bias, float* C,
                         int M, int N, int K, int lda, int act, int G,
                         long sAg, long sWg, long sCg, long sBg)
{
    dim3 grid((N + 63) / 64, (M + 127) / 128, G);
    sgemm_kernel<<<grid, 256>>>(A, W, bias, C, M, N, K, lda, act, sAg, sWg, sCg, sBg);
}

extern "C" void kernel_launch(void* const* d_in, const int* in_sizes, int n_in,
                              void* d_out, int out_size)
{
    const float* input_ids = (const float*)d_in[0];
    const float* proj_w    = (const float*)d_in[1];
    const float* proj_b    = (const float*)d_in[2];
    const float* ln0_g     = (const float*)d_in[3];
    const float* ln0_b     = (const float*)d_in[4];
    const float* ln1_g     = (const float*)d_in[5];
    const float* ln1_b     = (const float*)d_in[6];
    const float* ip_w      = (const float*)d_in[7];
    const float* ip_b      = (const float*)d_in[8];
    const float* s_inw     = (const float*)d_in[9];
    const float* s_convw   = (const float*)d_in[10];
    const float* s_convb   = (const float*)d_in[11];
    const float* s_xw      = (const float*)d_in[12];
    const float* s_dtw     = (const float*)d_in[13];
    const float* s_dtb     = (const float*)d_in[14];
    const float* s_alog    = (const float*)d_in[15];
    const float* s_d       = (const float*)d_in[16];
    const float* s_outw    = (const float*)d_in[17];
    const float* op_w      = (const float*)d_in[18];
    const float* op_b      = (const float*)d_in[19];
    const float* ln2_g     = (const float*)d_in[20];
    const float* ln2_b     = (const float*)d_in[21];
    const float* f_w1      = (const float*)d_in[22];
    const float* f_b1      = (const float*)d_in[23];
    const float* f_w2      = (const float*)d_in[24];
    const float* f_b2      = (const float*)d_in[25];
    const float* ln3_g     = (const float*)d_in[26];
    const float* ln3_b     = (const float*)d_in[27];

    float* base = nullptr;
    cudaGetSymbolAddress((void**)&base, g_buf);

    float* X    = base + OFF_X;
    float* LNb  = base + OFF_LN;
    float* B256 = base + OFF_B256;
    float* U    = base + OFF_U;
    float* XZ   = base + OFF_XZ;
    float* XC   = base + OFF_XC;
    float* DBC  = base + OFF_DBC;
    float* DT   = base + OFF_DT;
    float* Y    = base + OFF_Y;
    float* CAT  = base + OFF_CAT;
    float* FF   = base + OFF_FF;

    const int M = (int)MTOK;
    const int CONV_BLOCKS = (int)(2 * MTOK * 64 / 256);
    const int LN_BLOCKS = (int)(MTOK / 8);

    embed_ln_kernel<<<M, 256>>>(input_ids, proj_w, proj_b, ln0_g, ln0_b, X);
    ln_kernel<<<LN_BLOCKS, 256>>>(X, nullptr, ln1_g, ln1_b, LNb);

    for (int l = 0; l < 12; l++) {
        // in-proj -> fused split+reverse into U
        launch_tf32<64, 0, 1, false, 3>(LNb, ip_w + (long)l * 256 * 256, ip_b + l * 256, U,
                                        M, 256, 256, 1, 0, 0, 0);
        // xz = u @ inw (batched 2) — 512-thread GEMM
        launch_tf32_512<0>(U, s_inw + (long)l * 2 * 128 * 512, nullptr, XZ,
                           M, 512, 128, 2, MTOK * 128, 128 * 512, MTOK * 512);
        // conv + silu (4 t per thread)
        conv_silu_kernel<<<CONV_BLOCKS, 256>>>(XZ, s_convw + (long)l * 2 * 256 * 4,
                                               s_convb + (long)l * 2 * 256, XC);
        // dbc = xc @ xw (tf32, N=40 guarded)
        launch_tf32<64, 0, 0, true, 3>(XC, s_xw + (long)l * 2 * 256 * 40, nullptr, DBC,
                                       M, 40, 256, 2, MTOK * 256, 256 * 40, MTOK * 40);
        // dt = softplus(dbc[:, :8] @ dtw + dtb)
        launch_sgemm(DBC, s_dtw + (long)l * 2 * 8 * 256, s_dtb + (long)l * 2 * 256, DT,
                     M, 256, 8, 40, 1, 2, MTOK * 40, 8 * 256, MTOK * 256, 256);
        // selective scan + fused silu(z) gate
        scan_kernel<<<256, 256>>>(DT, XC, DBC, XZ,
                                  s_alog + (long)l * 2 * 256 * 16,
                                  s_d + (long)l * 2 * 256, Y);
        // so = y @ outw -> fused concat+unreverse into CAT
        launch_tf32<64, 0, 2, false, 3>(Y, s_outw + (long)l * 2 * 256 * 128, nullptr, CAT,
                                        M, 128, 256, 2, MTOK * 256, 256 * 128, 0);
        // out-proj
        launch_tf32<64, 0, 0, false, 3>(CAT, op_w + (long)l * 256 * 256, op_b + l * 256, B256,
                                        M, 256, 256, 1, 0, 0, 0);
        // LN2 (residual)
        ln_kernel<<<LN_BLOCKS, 256>>>(B256, X, ln2_g + l * 256, ln2_b + l * 256, X);
        // ff = gelu(x @ w1 + b1) — 512-thread GEMM
        launch_tf32_512<2>(X, f_w1 + (long)l * 256 * 1024, f_b1 + l * 1024, FF,
                           M, 1024, 256, 1, 0, 0, 0);
        // f = ff @ w2 + b2
        launch_tf32<64, 0, 0, false, 3>(FF, f_w2 + (long)l * 1024 * 256, f_b2 + l * 256, B256,
                                        M, 256, 1024, 1, 0, 0, 0);
        // LN3 fused with next layer's LN1
        float* dst = (l == 11) ? (float*)d_out : X;
        float* lnb = (l == 11) ? nullptr : LNb;
        const float* g1 = ln1_g + (l + 1 < 12 ? (l + 1) * 256 : 0);
        const float* b1 = ln1_b + (l + 1 < 12 ? (l + 1) * 256 : 0);
        ln3ln1_kernel<<<LN_BLOCKS, 256>>>(B256, X, ln3_g + l * 256, ln3_b + l * 256,
                                          g1, b1, dst, lnb);
    }
}

// round 10
// speedup vs baseline: 1.7996x; 1.0311x over previous
#include <cuda_runtime.h>
#include <math.h>
#include <stdint.h>

constexpr long MTOK  = 16 * 512;     // 8192 tokens

// ---------------------------------------------------------------------------
// Scratch arena
// ---------------------------------------------------------------------------
constexpr long OFF_X    = 0;
constexpr long OFF_LN   = OFF_X    + MTOK * 256;
constexpr long OFF_B256 = OFF_LN   + MTOK * 256;
constexpr long OFF_U    = OFF_B256 + MTOK * 256;
constexpr long OFF_XZ   = OFF_U    + 2 * MTOK * 128;
constexpr long OFF_XC   = OFF_XZ   + 2 * MTOK * 512;
constexpr long OFF_DBC  = OFF_XC   + 2 * MTOK * 256;
constexpr long OFF_DT   = OFF_DBC  + 2 * MTOK * 40;
constexpr long OFF_Y    = OFF_DT   + 2 * MTOK * 256;
constexpr long OFF_CAT  = OFF_Y    + 2 * MTOK * 256;
constexpr long OFF_FF   = OFF_CAT  + MTOK * 256;
constexpr long TOTAL_F  = OFF_FF   + MTOK * 1024;

__device__ float g_buf[TOTAL_F];

__device__ __forceinline__ uint32_t smem_u32(const void* p)
{
    return (uint32_t)__cvta_generic_to_shared(p);
}

// ---------------------------------------------------------------------------
// Embedding: x = LN(ids @ proj_w + proj_b)  (runs once)
// ---------------------------------------------------------------------------
__global__ void embed_ln_kernel(const float* __restrict__ ids,
                                const float* __restrict__ pw,
                                const float* __restrict__ pb,
                                const float* __restrict__ gam,
                                const float* __restrict__ bet,
                                float* __restrict__ x)
{
    __shared__ float sin[32];
    __shared__ float sred[8];
    int m = blockIdx.x, d = threadIdx.x;
    if (d < 32) sin[d] = ids[(long)m * 32 + d];
    __syncthreads();
    float v = pb[d];
#pragma unroll
    for (int e = 0; e < 32; e++)
        v = fmaf(sin[e], pw[e * 256 + d], v);
    float s = v;
#pragma unroll
    for (int o = 16; o > 0; o >>= 1) s += __shfl_xor_sync(0xffffffffu, s, o);
    if ((d & 31) == 0) sred[d >> 5] = s;
    __syncthreads();
    float mean = 0.f;
#pragma unroll
    for (int i = 0; i < 8; i++) mean += sred[i];
    mean *= (1.f / 256.f);
    float c = v - mean;
    float q = c * c;
#pragma unroll
    for (int o = 16; o > 0; o >>= 1) q += __shfl_xor_sync(0xffffffffu, q, o);
    __syncthreads();
    if ((d & 31) == 0) sred[d >> 5] = q;
    __syncthreads();
    float var = 0.f;
#pragma unroll
    for (int i = 0; i < 8; i++) var += sred[i];
    var *= (1.f / 256.f);
    x[(long)m * 256 + d] = c * rsqrtf(var + 1e-5f) * gam[d] + bet[d];
}

// ---------------------------------------------------------------------------
// Warp-level LN helper on 8 registers
// ---------------------------------------------------------------------------
__device__ __forceinline__ void warp_ln8(float* a,
                                         const float* __restrict__ gam,
                                         const float* __restrict__ bet,
                                         int lane, float* o)
{
    float s = 0.f;
#pragma unroll
    for (int i = 0; i < 8; i++) s += a[i];
#pragma unroll
    for (int off = 16; off > 0; off >>= 1) s += __shfl_xor_sync(0xffffffffu, s, off);
    float mean = s * (1.f / 256.f);
    float q = 0.f;
#pragma unroll
    for (int i = 0; i < 8; i++) {
        float c = a[i] - mean;
        q = fmaf(c, c, q);
    }
#pragma unroll
    for (int off = 16; off > 0; off >>= 1) q += __shfl_xor_sync(0xffffffffu, q, off);
    float inv = rsqrtf(q * (1.f / 256.f) + 1e-5f);
    const float4* gp = (const float4*)(gam + lane * 8);
    const float4* bp = (const float4*)(bet + lane * 8);
    float4 g0 = gp[0], g1 = gp[1], b0 = bp[0], b1 = bp[1];
    o[0] = (a[0] - mean) * inv * g0.x + b0.x;
    o[1] = (a[1] - mean) * inv * g0.y + b0.y;
    o[2] = (a[2] - mean) * inv * g0.z + b0.z;
    o[3] = (a[3] - mean) * inv * g0.w + b0.w;
    o[4] = (a[4] - mean) * inv * g1.x + b1.x;
    o[5] = (a[5] - mean) * inv * g1.y + b1.y;
    o[6] = (a[6] - mean) * inv * g1.z + b1.z;
    o[7] = (a[7] - mean) * inv * g1.w + b1.w;
}

// ---------------------------------------------------------------------------
// Warp-per-token LayerNorm, optional residual.
// ---------------------------------------------------------------------------
__global__ void __launch_bounds__(256)
ln_kernel(const float* __restrict__ in,
          const float* __restrict__ res,
          const float* __restrict__ gam,
          const float* __restrict__ bet,
          float* __restrict__ out)
{
    int w = threadIdx.x >> 5, lane = threadIdx.x & 31;
    long m = (long)blockIdx.x * 8 + w;
    const float4* ip = (const float4*)(in + m * 256);
    float4 v0 = ip[lane * 2];
    float4 v1 = ip[lane * 2 + 1];
    if (res) {
        const float4* rp = (const float4*)(res + m * 256);
        float4 r0 = rp[lane * 2];
        float4 r1 = rp[lane * 2 + 1];
        v0.x += r0.x; v0.y += r0.y; v0.z += r0.z; v0.w += r0.w;
        v1.x += r1.x; v1.y += r1.y; v1.z += r1.z; v1.w += r1.w;
    }
    float a[8] = {v0.x, v0.y, v0.z, v0.w, v1.x, v1.y, v1.z, v1.w};
    float o[8];
    warp_ln8(a, gam, bet, lane, o);
    float4* op = (float4*)(out + m * 256);
    op[lane * 2]     = make_float4(o[0], o[1], o[2], o[3]);
    op[lane * 2 + 1] = make_float4(o[4], o[5], o[6], o[7]);
}

// ---------------------------------------------------------------------------
// Fused LN3 + LN1(next layer)
// ---------------------------------------------------------------------------
__global__ void __launch_bounds__(256)
ln3ln1_kernel(const float* __restrict__ in,
              const float* __restrict__ res,
              const float* __restrict__ g3,
              const float* __restrict__ b3,
              const float* __restrict__ g1,
              const float* __restrict__ b1,
              float* __restrict__ xout,
              float* __restrict__ lnb)
{
    int w = threadIdx.x >> 5, lane = threadIdx.x & 31;
    long m = (long)blockIdx.x * 8 + w;
    const float4* ip = (const float4*)(in + m * 256);
    const float4* rp = (const float4*)(res + m * 256);
    float4 v0 = ip[lane * 2], v1 = ip[lane * 2 + 1];
    float4 r0 = rp[lane * 2], r1 = rp[lane * 2 + 1];
    float a[8] = {v0.x + r0.x, v0.y + r0.y, v0.z + r0.z, v0.w + r0.w,
                  v1.x + r1.x, v1.y + r1.y, v1.z + r1.z, v1.w + r1.w};
    float o[8];
    warp_ln8(a, g3, b3, lane, o);
    float4* xp = (float4*)(xout + m * 256);
    xp[lane * 2]     = make_float4(o[0], o[1], o[2], o[3]);
    xp[lane * 2 + 1] = make_float4(o[4], o[5], o[6], o[7]);
    if (lnb) {
        float o2[8];
        warp_ln8(o, g1, b1, lane, o2);
        float4* lp = (float4*)(lnb + m * 256);
        lp[lane * 2]     = make_float4(o2[0], o2[1], o2[2], o2[3]);
        lp[lane * 2 + 1] = make_float4(o2[4], o2[5], o2[6], o2[7]);
    }
}

// ---------------------------------------------------------------------------
// TF32 GEMM, 512 threads, 128x128 tile, 16 warps of 32x32. BK=32, 3-stage
// cp.async.ca pipeline with ONE barrier per K-slab.
// ---------------------------------------------------------------------------
template<int ACT>
__global__ void __launch_bounds__(512, 2)
tf32gemm512_kernel(const float* __restrict__ A,
                   const float* __restrict__ W,
                   const float* __restrict__ bias,
                   float* __restrict__ C,
                   int M, int N, int K,
                   long sAg, long sWg, long sCg)
{
    extern __shared__ uint32_t dyn[];
    constexpr int AW = 128 * 36;
    constexpr int SW = AW + 32 * 136;     // 8960 words per stage

    int g = blockIdx.z;
    A += (long)g * sAg;
    W += (long)g * sWg;
    C += (long)g * sCg;

    int tid  = threadIdx.x;
    int warp = tid >> 5;
    int lane = tid & 31;
    int wm = (warp & 3) * 32;
    int wn = (warp >> 2) * 32;
    int gID = lane >> 2;
    int tig = lane & 3;
    int rowBase = blockIdx.y * 128;
    int colBase = blockIdx.x * 128;

    const float* Abase = A + (long)rowBase * K;
    const float* Wbase = W + colBase;

    auto stage = [&](int buf, int k0) {
        uint32_t* As = dyn + buf * SW;
        uint32_t* Bs = dyn + buf * SW + AW;
#pragma unroll
        for (int it = 0; it < 2; it++) {
            int f = tid + it * 512;
            int r = f >> 3, k4 = (f & 7) * 4;
            asm volatile("cp.async.ca.shared.global [%0], [%1], 16;\n"
                         :: "r"(smem_u32(&As[r * 36 + k4])),
                            "l"(Abase + (long)r * K + k0 + k4));
        }
#pragma unroll
        for (int it = 0; it < 2; it++) {
            int f = tid + it * 512;
            int kr = f >> 5, n4 = (f & 31) * 4;
            asm volatile("cp.async.ca.shared.global [%0], [%1], 16;\n"
                         :: "r"(smem_u32(&Bs[kr * 136 + n4])),
                            "l"(Wbase + (long)(k0 + kr) * N + n4));
        }
        asm volatile("cp.async.commit_group;\n");
    };

    float acc[2][4][4];
#pragma unroll
    for (int a = 0; a < 2; a++)
#pragma unroll
        for (int b = 0; b < 4; b++)
#pragma unroll
            for (int c = 0; c < 4; c++) acc[a][b][c] = 0.f;

    auto compute = [&](int buf) {
        uint32_t* As = dyn + buf * SW;
        uint32_t* Bs = dyn + buf * SW + AW;
#pragma unroll
        for (int ks = 0; ks < 32; ks += 8) {
            uint32_t bf[4][2];
#pragma unroll
            for (int nt = 0; nt < 4; nt++) {
                int col = wn + nt * 8 + gID;
                bf[nt][0] = Bs[(ks + tig) * 136 + col];
                bf[nt][1] = Bs[(ks + tig + 4) * 136 + col];
            }
#pragma unroll
            for (int mt = 0; mt < 2; mt++) {
                int row = wm + mt * 16 + gID;
                uint32_t a0 = As[row * 36 + ks + tig] + 0x1000u;
                uint32_t a1 = As[(row + 8) * 36 + ks + tig] + 0x1000u;
                uint32_t a2 = As[row * 36 + ks + tig + 4] + 0x1000u;
                uint32_t a3 = As[(row + 8) * 36 + ks + tig + 4] + 0x1000u;
#pragma unroll
                for (int nt = 0; nt < 4; nt++) {
                    asm volatile(
                        "mma.sync.aligned.m16n8k8.row.col.f32.tf32.tf32.f32 "
                        "{%0,%1,%2,%3}, {%4,%5,%6,%7}, {%8,%9}, {%0,%1,%2,%3};\n"
                        : "+f"(acc[mt][nt][0]), "+f"(acc[mt][nt][1]),
                          "+f"(acc[mt][nt][2]), "+f"(acc[mt][nt][3])
                        : "r"(a0), "r"(a1), "r"(a2), "r"(a3),
                          "r"(bf[nt][0]), "r"(bf[nt][1]));
                }
            }
        }
    };

    int nk = K >> 5;
    stage(0, 0);
    if (nk > 1) stage(1, 32);
    for (int ki = 0; ki < nk; ki++) {
        if (ki < nk - 1) asm volatile("cp.async.wait_group 1;\n");
        else             asm volatile("cp.async.wait_group 0;\n");
        __syncthreads();
        int kn = ki + 2;
        if (kn < nk) stage(kn % 3, kn << 5);
        compute(ki % 3);
    }

#pragma unroll
    for (int mt = 0; mt < 2; mt++) {
        int row0 = rowBase + wm + mt * 16 + gID;
#pragma unroll
        for (int nt = 0; nt < 4; nt++) {
            int col = colBase + wn + nt * 8 + tig * 2;
            float b0 = 0.f, b1 = 0.f;
            if (bias) { b0 = bias[col]; b1 = bias[col + 1]; }
            float v[4];
            v[0] = acc[mt][nt][0] + b0;
            v[1] = acc[mt][nt][1] + b1;
            v[2] = acc[mt][nt][2] + b0;
            v[3] = acc[mt][nt][3] + b1;
            if (ACT == 2) {
#pragma unroll
                for (int q = 0; q < 4; q++)
                    v[q] = 0.5f * v[q] * (1.f + erff(v[q] * 0.70710678118654752f));
            }
            *(float2*)&C[(long)row0 * N + col] = make_float2(v[0], v[1]);
            *(float2*)&C[(long)(row0 + 8) * N + col] = make_float2(v[2], v[3]);
        }
    }
}

// ---------------------------------------------------------------------------
// TF32 GEMM, 256 threads, 64x128 tile, BK=32, 3-stage pipeline (1 barrier/slab)
// SMODE: 0=plain, 1=split+reverse into U, 2=concat+unreverse into CAT
// NG: guarded N (colBase==0 assumed). DTF: fuse dt=softplus(dbc[:,:8]@dtw+dtb).
// ---------------------------------------------------------------------------
template<int ACT, int SMODE, bool NG, bool DTF>
__global__ void __launch_bounds__(256, 2)
tf32gemm64_kernel(const float* __restrict__ A,
                  const float* __restrict__ W,
                  const float* __restrict__ bias,
                  float* __restrict__ C,
                  int M, int N, int K,
                  long sAg, long sWg, long sCg,
                  const float* __restrict__ dtw,
                  const float* __restrict__ dtb,
                  float* __restrict__ DTout)
{
    extern __shared__ uint32_t dyn[];
    constexpr int AW = 64 * 36;
    constexpr int SW = AW + 32 * 136;      // 6656 words per stage

    int g = blockIdx.z;
    A += (long)g * sAg;
    W += (long)g * sWg;
    if (SMODE == 0) C += (long)g * sCg;
    if (DTF) {
        dtw += (long)g * 2048;
        dtb += (long)g * 256;
        DTout += (long)g * MTOK * 256;
    }

    int tid  = threadIdx.x;
    int warp = tid >> 5;
    int lane = tid & 31;
    int wm = (warp & 1) * 32;
    int wn = (warp >> 1) * 32;
    int gID = lane >> 2;
    int tig = lane & 3;
    int rowBase = blockIdx.y * 64;
    int colBase = blockIdx.x * 128;

    const float* Abase = A + (long)rowBase * K;
    const float* Wbase = W + colBase;

    if (NG) {
#pragma unroll
        for (int s = 0; s < 3; s++) {
            uint32_t* Bs = dyn + s * SW + AW;
            for (int f = tid; f < 1024; f += 256) {
                int kr = f >> 5, n4 = (f & 31) * 4;
                if (n4 + 4 > N)
                    *(uint4*)&Bs[kr * 136 + n4] = make_uint4(0, 0, 0, 0);
            }
        }
        __syncthreads();
    }

    auto stage = [&](int buf, int k0) {
        uint32_t* As = dyn + buf * SW;
        uint32_t* Bs = dyn + buf * SW + AW;
#pragma unroll
        for (int it = 0; it < 2; it++) {
            int f = tid + it * 256;
            int r = f >> 3, k4 = (f & 7) * 4;
            asm volatile("cp.async.ca.shared.global [%0], [%1], 16;\n"
                         :: "r"(smem_u32(&As[r * 36 + k4])),
                            "l"(Abase + (long)r * K + k0 + k4));
        }
#pragma unroll
        for (int it = 0; it < 4; it++) {
            int f = tid + it * 256;
            int kr = f >> 5, n4 = (f & 31) * 4;
            if (!NG || n4 + 4 <= N)
                asm volatile("cp.async.ca.shared.global [%0], [%1], 16;\n"
                             :: "r"(smem_u32(&Bs[kr * 136 + n4])),
                                "l"(Wbase + (long)(k0 + kr) * N + n4));
        }
        asm volatile("cp.async.commit_group;\n");
    };

    float acc[2][4][4];
#pragma unroll
    for (int a = 0; a < 2; a++)
#pragma unroll
        for (int b = 0; b < 4; b++)
#pragma unroll
            for (int c = 0; c < 4; c++) acc[a][b][c] = 0.f;

    auto compute = [&](int buf) {
        uint32_t* As = dyn + buf * SW;
        uint32_t* Bs = dyn + buf * SW + AW;
#pragma unroll
        for (int ks = 0; ks < 32; ks += 8) {
            uint32_t bf[4][2];
#pragma unroll
            for (int nt = 0; nt < 4; nt++) {
                int col = wn + nt * 8 + gID;
                bf[nt][0] = Bs[(ks + tig) * 136 + col];
                bf[nt][1] = Bs[(ks + tig + 4) * 136 + col];
            }
#pragma unroll
            for (int mt = 0; mt < 2; mt++) {
                int row = wm + mt * 16 + gID;
                uint32_t a0 = As[row * 36 + ks + tig] + 0x1000u;
                uint32_t a1 = As[(row + 8) * 36 + ks + tig] + 0x1000u;
                uint32_t a2 = As[row * 36 + ks + tig + 4] + 0x1000u;
                uint32_t a3 = As[(row + 8) * 36 + ks + tig + 4] + 0x1000u;
#pragma unroll
                for (int nt = 0; nt < 4; nt++) {
                    asm volatile(
                        "mma.sync.aligned.m16n8k8.row.col.f32.tf32.tf32.f32 "
                        "{%0,%1,%2,%3}, {%4,%5,%6,%7}, {%8,%9}, {%0,%1,%2,%3};\n"
                        : "+f"(acc[mt][nt][0]), "+f"(acc[mt][nt][1]),
                          "+f"(acc[mt][nt][2]), "+f"(acc[mt][nt][3])
                        : "r"(a0), "r"(a1), "r"(a2), "r"(a3),
                          "r"(bf[nt][0]), "r"(bf[nt][1]));
                }
            }
        }
    };

    int nk = K >> 5;
    stage(0, 0);
    if (nk > 1) stage(1, 32);
    for (int ki = 0; ki < nk; ki++) {
        if (ki < nk - 1) asm volatile("cp.async.wait_group 1;\n");
        else             asm volatile("cp.async.wait_group 0;\n");
        __syncthreads();
        int kn = ki + 2;
        if (kn < nk) stage(kn % 3, kn << 5);
        compute(ki % 3);
    }

    // main epilogue
#pragma unroll
    for (int mt = 0; mt < 2; mt++) {
        int row0 = rowBase + wm + mt * 16 + gID;
#pragma unroll
        for (int nt = 0; nt < 4; nt++) {
            int col = colBase + wn + nt * 8 + tig * 2;
            if (NG && col >= N) continue;
            float b0 = 0.f, b1 = 0.f;
            if (bias) { b0 = bias[col]; b1 = bias[col + 1]; }
            float v[4];
            v[0] = acc[mt][nt][0] + b0;
            v[1] = acc[mt][nt][1] + b1;
            v[2] = acc[mt][nt][2] + b0;
            v[3] = acc[mt][nt][3] + b1;
            if (ACT == 2) {
#pragma unroll
                for (int q = 0; q < 4; q++)
                    v[q] = 0.5f * v[q] * (1.f + erff(v[q] * 0.70710678118654752f));
            }
#pragma unroll
            for (int h = 0; h < 2; h++) {
                int row = row0 + h * 8;
                float2 val = make_float2(v[h * 2], v[h * 2 + 1]);
                if (SMODE == 0) {
                    *(float2*)&C[(long)row * N + col] = val;
                } else if (SMODE == 1) {
                    if (col < 128) {
                        *(float2*)&C[(long)row * 128 + col] = val;
                    } else {
                        long b = row >> 9, t = row & 511;
                        *(float2*)&C[MTOK * 128 + ((b << 9) + 511 - t) * 128 + (col - 128)] = val;
                    }
                } else {
                    if (g == 0) {
                        *(float2*)&C[(long)row * 256 + col] = val;
                    } else {
                        long b = row >> 9, t = row & 511;
                        *(float2*)&C[((b << 9) + 511 - t) * 256 + 128 + col] = val;
                    }
                }
            }
        }
    }

    // fused dt = softplus(dbc[:, :8] @ dtw + dtb)  (DTF path: N=40, grid.x==1)
    if (DTF) {
        float* dbs = (float*)(dyn + 3 * SW);   // [64][8]
        if (warp < 2) {                        // wn == 0 warps hold cols 0..7
            int col = tig * 2;
#pragma unroll
            for (int mt = 0; mt < 2; mt++) {
#pragma unroll
                for (int h = 0; h < 2; h++) {
                    int rl = wm + mt * 16 + gID + h * 8;
                    dbs[rl * 8 + col]     = acc[mt][0][h * 2];
                    dbs[rl * 8 + col + 1] = acc[mt][0][h * 2 + 1];
                }
            }
        }
        __syncthreads();
        int d = tid;                           // 0..255
        float wreg[8];
#pragma unroll
        for (int r = 0; r < 8; r++) wreg[r] = dtw[r * 256 + d];
        float bb = dtb[d];
        float* dto = DTout + (long)rowBase * 256 + d;
        for (int r = 0; r < 64; r++) {
            float s = bb;
#pragma unroll
            for (int j = 0; j < 8; j++) s = fmaf(dbs[r * 8 + j], wreg[j], s);
            s = (s > 20.f) ? s : log1pf(expf(s));
            dto[(long)r * 256] = s;
        }
    }
}

// ---------------------------------------------------------------------------
// depthwise causal conv (K=4) + bias + silu; 4 t-outputs per thread
// ---------------------------------------------------------------------------
__global__ void conv_silu_kernel(const float* __restrict__ xz,
                                 const float* __restrict__ convw,
                                 const float* __restrict__ convb,
                                 float* __restrict__ xc)
{
    long i = (long)blockIdx.x * 256 + threadIdx.x;
    if (i >= 2 * MTOK * 64) return;
    int d = (int)(i & 255);
    long q = i >> 8;
    int t0 = (int)(q & 127) * 4;
    int b  = (int)((q >> 7) & 15);
    int g  = (int)(q >> 11);

    const float4 w4 = *(const float4*)(convw + ((long)g * 256 + d) * 4);
    float bias = convb[(long)g * 256 + d];

    long mrow = (long)g * MTOK + (long)b * 512 + t0;
    const float* xp = xz + mrow * 512 + d;
    float xv[7];
#pragma unroll
    for (int j = 0; j < 7; j++) {
        int t = t0 - 3 + j;
        xv[j] = (t >= 0) ? xp[(long)(j - 3) * 512] : 0.f;
    }
    float* op = xc + mrow * 256 + d;
#pragma unroll
    for (int j = 0; j < 4; j++) {
        float acc = bias;
        acc = fmaf(xv[j],     w4.x, acc);
        acc = fmaf(xv[j + 1], w4.y, acc);
        acc = fmaf(xv[j + 2], w4.z, acc);
        acc = fmaf(xv[j + 3], w4.w, acc);
        op[(long)j * 256] = acc / (1.f + __expf(-acc));
    }
}

// ---------------------------------------------------------------------------
// Selective scan, 8 lanes per (g,b,d) group, 2 states per lane, pipelined.
// ---------------------------------------------------------------------------
__global__ void __launch_bounds__(256)
scan_kernel(const float* __restrict__ dt,
            const float* __restrict__ xc,
            const float* __restrict__ dbc,
            const float* __restrict__ xz,
            const float* __restrict__ alog,
            const float* __restrict__ dpar,
            float* __restrict__ y)
{
    int gidx = blockIdx.x * 32 + (threadIdx.x >> 3);
    int li = threadIdx.x & 7;
    int g = gidx >> 12;
    int b = (gidx >> 8) & 15;
    int d = gidx & 255;

    const float2 al = *(const float2*)&alog[((long)(g * 256 + d)) * 16 + li * 2];
    const float L2E = 1.4426950408889634f;
    float A0 = -__expf(al.x) * L2E;
    float A1 = -__expf(al.y) * L2E;
    float dp = dpar[(long)g * 256 + d];

    long mbase = (long)g * MTOK + (long)b * 512;
    const float* dtp = dt + mbase * 256 + d;
    const float* xcp = xc + mbase * 256 + d;
    const float* dbp = dbc + mbase * 40;
    const float* zp  = xz + mbase * 512 + 256 + d;
    float* yp = y + mbase * 256 + d;

    float h0 = 0.f, h1 = 0.f;

    float dtv_n = dtp[0];
    float xv_n  = xcp[0];
    float z_n   = zp[0];
    float2 B_n  = *(const float2*)&dbp[8 + li * 2];
    float2 C_n  = *(const float2*)&dbp[24 + li * 2];

    for (int t = 0; t < 512; t++) {
        float dtv = dtv_n, xv = xv_n, z = z_n;
        float2 Bv = B_n, Cv = C_n;
        long tn = (t + 1 < 512) ? t + 1 : 511;
        dtv_n = dtp[tn * 256];
        xv_n  = xcp[tn * 256];
        z_n   = zp[tn * 512];
        B_n   = *(const float2*)&dbp[tn * 40 + 8 + li * 2];
        C_n   = *(const float2*)&dbp[tn * 40 + 24 + li * 2];

        float dx = dtv * xv;
        h0 = exp2f(dtv * A0) * h0 + dx * Bv.x;
        h1 = exp2f(dtv * A1) * h1 + dx * Bv.y;
        float p = h0 * Cv.x + h1 * Cv.y;
        p += __shfl_xor_sync(0xffffffffu, p, 4);
        p += __shfl_xor_sync(0xffffffffu, p, 2);
        p += __shfl_xor_sync(0xffffffffu, p, 1);
        if (li == 0) {
            float sz = z / (1.f + __expf(-z));
            yp[(long)t * 256] = (p + dp * xv) * sz;
        }
    }
}

// ---------------------------------------------------------------------------
// Launch helpers
// ---------------------------------------------------------------------------
template<int ACT>
static void launch_tf32_512(const float* A, const float* W, const float* bias, float* C,
                            int M, int N, int K, int G,
                            long sAg, long sWg, long sCg)
{
    constexpr int SMEM = 3 * (128 * 36 + 32 * 136) * 4;   // 107520 B
    cudaFuncSetAttribute(tf32gemm512_kernel<ACT>,
                         cudaFuncAttributeMaxDynamicSharedMemorySize, SMEM);
    dim3 grid(N / 128, M / 128, G);
    tf32gemm512_kernel<ACT><<<grid, 512, SMEM>>>(A, W, bias, C, M, N, K,
                                                 sAg, sWg, sCg);
}

template<int ACT, int SMODE, bool NG, bool DTF>
static void launch_tf64(const float* A, const float* W, const float* bias, float* C,
                        int M, int N, int K, int G,
                        long sAg, long sWg, long sCg,
                        const float* dtw = nullptr, const float* dtb = nullptr,
                        float* DTout = nullptr)
{
    constexpr int SMEM = 3 * (64 * 36 + 32 * 136) * 4 + 2048;   // +dt scratch
    cudaFuncSetAttribute(tf32gemm64_kernel<ACT, SMODE, NG, DTF>,
                         cudaFuncAttributeMaxDynamicSharedMemorySize, SMEM);
    dim3 grid((N + 127) / 128, M / 64, G);
    tf32gemm64_kernel<ACT, SMODE, NG, DTF><<<grid, 256, SMEM>>>(
        A, W, bias, C, M, N, K, sAg, sWg, sCg, dtw, dtb, DTout);
}

extern "C" void kernel_launch(void* const* d_in, const int* in_sizes, int n_in,
                              void* d_out, int out_size)
{
    const float* input_ids = (const float*)d_in[0];
    const float* proj_w    = (const float*)d_in[1];
    const float* proj_b    = (const float*)d_in[2];
    const float* ln0_g     = (const float*)d_in[3];
    const float* ln0_b     = (const float*)d_in[4];
    const float* ln1_g     = (const float*)d_in[5];
    const float* ln1_b     = (const float*)d_in[6];
    const float* ip_w      = (const float*)d_in[7];
    const float* ip_b      = (const float*)d_in[8];
    const float* s_inw     = (const float*)d_in[9];
    const float* s_convw   = (const float*)d_in[10];
    const float* s_convb   = (const float*)d_in[11];
    const float* s_xw      = (const float*)d_in[12];
    const float* s_dtw     = (const float*)d_in[13];
    const float* s_dtb     = (const float*)d_in[14];
    const float* s_alog    = (const float*)d_in[15];
    const float* s_d       = (const float*)d_in[16];
    const float* s_outw    = (const float*)d_in[17];
    const float* op_w      = (const float*)d_in[18];
    const float* op_b      = (const float*)d_in[19];
    const float* ln2_g     = (const float*)d_in[20];
    const float* ln2_b     = (const float*)d_in[21];
    const float* f_w1      = (const float*)d_in[22];
    const float* f_b1      = (const float*)d_in[23];
    const float* f_w2      = (const float*)d_in[24];
    const float* f_b2      = (const float*)d_in[25];
    const float* ln3_g     = (const float*)d_in[26];
    const float* ln3_b     = (const float*)d_in[27];

    float* base = nullptr;
    cudaGetSymbolAddress((void**)&base, g_buf);

    float* X    = base + OFF_X;
    float* LNb  = base + OFF_LN;
    float* B256 = base + OFF_B256;
    float* U    = base + OFF_U;
    float* XZ   = base + OFF_XZ;
    float* XC   = base + OFF_XC;
    float* DBC  = base + OFF_DBC;
    float* DT   = base + OFF_DT;
    float* Y    = base + OFF_Y;
    float* CAT  = base + OFF_CAT;
    float* FF   = base + OFF_FF;

    const int M = (int)MTOK;
    const int CONV_BLOCKS = (int)(2 * MTOK * 64 / 256);
    const int LN_BLOCKS = (int)(MTOK / 8);

    embed_ln_kernel<<<M, 256>>>(input_ids, proj_w, proj_b, ln0_g, ln0_b, X);
    ln_kernel<<<LN_BLOCKS, 256>>>(X, nullptr, ln1_g, ln1_b, LNb);

    for (int l = 0; l < 12; l++) {
        // in-proj -> fused split+reverse into U
        launch_tf64<0, 1, false, false>(LNb, ip_w + (long)l * 256 * 256, ip_b + l * 256, U,
                                        M, 256, 256, 1, 0, 0, 0);
        // xz = u @ inw (batched 2)
        launch_tf32_512<0>(U, s_inw + (long)l * 2 * 128 * 512, nullptr, XZ,
                           M, 512, 128, 2, MTOK * 128, 128 * 512, MTOK * 512);
        // conv + silu
        conv_silu_kernel<<<CONV_BLOCKS, 256>>>(XZ, s_convw + (long)l * 2 * 256 * 4,
                                               s_convb + (long)l * 2 * 256, XC);
        // dbc = xc @ xw (N=40 guarded) + FUSED dt = softplus(dbc[:,:8]@dtw+dtb)
        launch_tf64<0, 0, true, true>(XC, s_xw + (long)l * 2 * 256 * 40, nullptr, DBC,
                                      M, 40, 256, 2, MTOK * 256, 256 * 40, MTOK * 40,
                                      s_dtw + (long)l * 2 * 8 * 256,
                                      s_dtb + (long)l * 2 * 256, DT);
        // selective scan + fused silu(z) gate
        scan_kernel<<<256, 256>>>(DT, XC, DBC, XZ,
                                  s_alog + (long)l * 2 * 256 * 16,
                                  s_d + (long)l * 2 * 256, Y);
        // so = y @ outw -> fused concat+unreverse into CAT
        launch_tf64<0, 2, false, false>(Y, s_outw + (long)l * 2 * 256 * 128, nullptr, CAT,
                                        M, 128, 256, 2, MTOK * 256, 256 * 128, 0);
        // out-proj
        launch_tf64<0, 0, false, false>(CAT, op_w + (long)l * 256 * 256, op_b + l * 256,
                                        B256, M, 256, 256, 1, 0, 0, 0);
        // LN2 (residual)
        ln_kernel<<<LN_BLOCKS, 256>>>(B256, X, ln2_g + l * 256, ln2_b + l * 256, X);
        // ff = gelu(x @ w1 + b1)
        launch_tf32_512<2>(X, f_w1 + (long)l * 256 * 1024, f_b1 + l * 1024, FF,
                           M, 1024, 256, 1, 0, 0, 0);
        // f = ff @ w2 + b2
        launch_tf64<0, 0, false, false>(FF, f_w2 + (long)l * 1024 * 256, f_b2 + l * 256,
                                        B256, M, 256, 1024, 1, 0, 0, 0);
        // LN3 fused with next layer's LN1
        float* dst = (l == 11) ? (float*)d_out : X;
        float* lnb = (l == 11) ? nullptr : LNb;
        const float* g1 = ln1_g + (l + 1 < 12 ? (l + 1) * 256 : 0);
        const float* b1 = ln1_b + (l + 1 < 12 ? (l + 1) * 256 : 0);
        ln3ln1_kernel<<<LN_BLOCKS, 256>>>(B256, X, ln3_g + l * 256, ln3_b + l * 256,
                                          g1, b1, dst, lnb);
    }
}

// round 11
// speedup vs baseline: 1.8595x; 1.0333x over previous
#include <cuda_runtime.h>
#include <math.h>
#include <stdint.h>

constexpr long MTOK  = 16 * 512;     // 8192 tokens

// ---------------------------------------------------------------------------
// Scratch arena
// ---------------------------------------------------------------------------
constexpr long OFF_X    = 0;
constexpr long OFF_LN   = OFF_X    + MTOK * 256;
constexpr long OFF_B256 = OFF_LN   + MTOK * 256;
constexpr long OFF_XZ   = OFF_B256 + MTOK * 256;
constexpr long OFF_XC   = OFF_XZ   + 2 * MTOK * 512;
constexpr long OFF_DBC  = OFF_XC   + 2 * MTOK * 256;
constexpr long OFF_DT   = OFF_DBC  + 2 * MTOK * 40;
constexpr long OFF_Y    = OFF_DT   + 2 * MTOK * 256;
constexpr long OFF_FF   = OFF_Y    + 2 * MTOK * 256;
constexpr long OFF_W2C  = OFF_FF   + MTOK * 1024;
constexpr long TOTAL_F  = OFF_W2C  + 24L * 256 * 256;

__device__ float g_buf[TOTAL_F];

__device__ __forceinline__ uint32_t smem_u32(const void* p)
{
    return (uint32_t)__cvta_generic_to_shared(p);
}

// ---------------------------------------------------------------------------
// Embedding: x = LN(ids @ proj_w + proj_b)  (runs once)
// ---------------------------------------------------------------------------
__global__ void embed_ln_kernel(const float* __restrict__ ids,
                                const float* __restrict__ pw,
                                const float* __restrict__ pb,
                                const float* __restrict__ gam,
                                const float* __restrict__ bet,
                                float* __restrict__ x)
{
    __shared__ float sin[32];
    __shared__ float sred[8];
    int m = blockIdx.x, d = threadIdx.x;
    if (d < 32) sin[d] = ids[(long)m * 32 + d];
    __syncthreads();
    float v = pb[d];
#pragma unroll
    for (int e = 0; e < 32; e++)
        v = fmaf(sin[e], pw[e * 256 + d], v);
    float s = v;
#pragma unroll
    for (int o = 16; o > 0; o >>= 1) s += __shfl_xor_sync(0xffffffffu, s, o);
    if ((d & 31) == 0) sred[d >> 5] = s;
    __syncthreads();
    float mean = 0.f;
#pragma unroll
    for (int i = 0; i < 8; i++) mean += sred[i];
    mean *= (1.f / 256.f);
    float c = v - mean;
    float q = c * c;
#pragma unroll
    for (int o = 16; o > 0; o >>= 1) q += __shfl_xor_sync(0xffffffffu, q, o);
    __syncthreads();
    if ((d & 31) == 0) sred[d >> 5] = q;
    __syncthreads();
    float var = 0.f;
#pragma unroll
    for (int i = 0; i < 8; i++) var += sred[i];
    var *= (1.f / 256.f);
    x[(long)m * 256 + d] = c * rsqrtf(var + 1e-5f) * gam[d] + bet[d];
}

// ---------------------------------------------------------------------------
// Warp-level LN helper on 8 registers
// ---------------------------------------------------------------------------
__device__ __forceinline__ void warp_ln8(float* a,
                                         const float* __restrict__ gam,
                                         const float* __restrict__ bet,
                                         int lane, float* o)
{
    float s = 0.f;
#pragma unroll
    for (int i = 0; i < 8; i++) s += a[i];
#pragma unroll
    for (int off = 16; off > 0; off >>= 1) s += __shfl_xor_sync(0xffffffffu, s, off);
    float mean = s * (1.f / 256.f);
    float q = 0.f;
#pragma unroll
    for (int i = 0; i < 8; i++) {
        float c = a[i] - mean;
        q = fmaf(c, c, q);
    }
#pragma unroll
    for (int off = 16; off > 0; off >>= 1) q += __shfl_xor_sync(0xffffffffu, q, off);
    float inv = rsqrtf(q * (1.f / 256.f) + 1e-5f);
    const float4* gp = (const float4*)(gam + lane * 8);
    const float4* bp = (const float4*)(bet + lane * 8);
    float4 g0 = gp[0], g1 = gp[1], b0 = bp[0], b1 = bp[1];
    o[0] = (a[0] - mean) * inv * g0.x + b0.x;
    o[1] = (a[1] - mean) * inv * g0.y + b0.y;
    o[2] = (a[2] - mean) * inv * g0.z + b0.z;
    o[3] = (a[3] - mean) * inv * g0.w + b0.w;
    o[4] = (a[4] - mean) * inv * g1.x + b1.x;
    o[5] = (a[5] - mean) * inv * g1.y + b1.y;
    o[6] = (a[6] - mean) * inv * g1.z + b1.z;
    o[7] = (a[7] - mean) * inv * g1.w + b1.w;
}

// ---------------------------------------------------------------------------
// Warp-per-token LayerNorm, optional residual.
// ---------------------------------------------------------------------------
__global__ void __launch_bounds__(256)
ln_kernel(const float* __restrict__ in,
          const float* __restrict__ res,
          const float* __restrict__ gam,
          const float* __restrict__ bet,
          float* __restrict__ out)
{
    int w = threadIdx.x >> 5, lane = threadIdx.x & 31;
    long m = (long)blockIdx.x * 8 + w;
    const float4* ip = (const float4*)(in + m * 256);
    float4 v0 = ip[lane * 2];
    float4 v1 = ip[lane * 2 + 1];
    if (res) {
        const float4* rp = (const float4*)(res + m * 256);
        float4 r0 = rp[lane * 2];
        float4 r1 = rp[lane * 2 + 1];
        v0.x += r0.x; v0.y += r0.y; v0.z += r0.z; v0.w += r0.w;
        v1.x += r1.x; v1.y += r1.y; v1.z += r1.z; v1.w += r1.w;
    }
    float a[8] = {v0.x, v0.y, v0.z, v0.w, v1.x, v1.y, v1.z, v1.w};
    float o[8];
    warp_ln8(a, gam, bet, lane, o);
    float4* op = (float4*)(out + m * 256);
    op[lane * 2]     = make_float4(o[0], o[1], o[2], o[3]);
    op[lane * 2 + 1] = make_float4(o[4], o[5], o[6], o[7]);
}

// ---------------------------------------------------------------------------
// Fused LN3 + LN1(next layer)
// ---------------------------------------------------------------------------
__global__ void __launch_bounds__(256)
ln3ln1_kernel(const float* __restrict__ in,
              const float* __restrict__ res,
              const float* __restrict__ g3,
              const float* __restrict__ b3,
              const float* __restrict__ g1,
              const float* __restrict__ b1,
              float* __restrict__ xout,
              float* __restrict__ lnb)
{
    int w = threadIdx.x >> 5, lane = threadIdx.x & 31;
    long m = (long)blockIdx.x * 8 + w;
    const float4* ip = (const float4*)(in + m * 256);
    const float4* rp = (const float4*)(res + m * 256);
    float4 v0 = ip[lane * 2], v1 = ip[lane * 2 + 1];
    float4 r0 = rp[lane * 2], r1 = rp[lane * 2 + 1];
    float a[8] = {v0.x + r0.x, v0.y + r0.y, v0.z + r0.z, v0.w + r0.w,
                  v1.x + r1.x, v1.y + r1.y, v1.z + r1.z, v1.w + r1.w};
    float o[8];
    warp_ln8(a, g3, b3, lane, o);
    float4* xp = (float4*)(xout + m * 256);
    xp[lane * 2]     = make_float4(o[0], o[1], o[2], o[3]);
    xp[lane * 2 + 1] = make_float4(o[4], o[5], o[6], o[7]);
    if (lnb) {
        float o2[8];
        warp_ln8(o, g1, b1, lane, o2);
        float4* lp = (float4*)(lnb + m * 256);
        lp[lane * 2]     = make_float4(o2[0], o2[1], o2[2], o2[3]);
        lp[lane * 2 + 1] = make_float4(o2[4], o2[5], o2[6], o2[7]);
    }
}

// ---------------------------------------------------------------------------
// TF32 GEMM, 256 threads, 128x128 tile, BK=32, 3-stage pipeline, 1 barrier.
// lda runtime (A may be a column slice). AREV: reverse A rows within each
// 512-token batch for group g==1 (bidirectional SSM input).
// ---------------------------------------------------------------------------
template<int ACT, bool AREV>
__global__ void __launch_bounds__(256, 2)
tf128_kernel(const float* __restrict__ A,
             const float* __restrict__ W,
             const float* __restrict__ bias,
             float* __restrict__ C,
             int M, int N, int K, int lda,
             long sAg, long sWg, long sCg)
{
    extern __shared__ uint32_t dyn[];
    constexpr int AW = 128 * 36;
    constexpr int SW = AW + 32 * 136;     // 8960 words / stage

    int g = blockIdx.z;
    A += (long)g * sAg;
    W += (long)g * sWg;
    C += (long)g * sCg;
    bool rev = AREV && (g == 1);

    int tid  = threadIdx.x;
    int warp = tid >> 5;
    int lane = tid & 31;
    int wm = (warp & 1) * 64;
    int wn = (warp >> 1) * 32;
    int gID = lane >> 2;
    int tig = lane & 3;
    int rowBase = blockIdx.y * 128;
    int colBase = blockIdx.x * 128;

    const float* Wbase = W + colBase;

    auto stage = [&](int buf, int k0) {
        uint32_t* As = dyn + buf * SW;
        uint32_t* Bs = dyn + buf * SW + AW;
#pragma unroll
        for (int it = 0; it < 4; it++) {
            int f = tid + it * 256;
            int r = f >> 3, k4 = (f & 7) * 4;
            int m = rowBase + r;
            if (rev) m = (m & ~511) + 511 - (m & 511);
            asm volatile("cp.async.ca.shared.global [%0], [%1], 16;\n"
                         :: "r"(smem_u32(&As[r * 36 + k4])),
                            "l"(A + (long)m * lda + k0 + k4));
        }
#pragma unroll
        for (int it = 0; it < 4; it++) {
            int f = tid + it * 256;
            int kr = f >> 5, n4 = (f & 31) * 4;
            asm volatile("cp.async.ca.shared.global [%0], [%1], 16;\n"
                         :: "r"(smem_u32(&Bs[kr * 136 + n4])),
                            "l"(Wbase + (long)(k0 + kr) * N + n4));
        }
        asm volatile("cp.async.commit_group;\n");
    };

    float acc[4][4][4];
#pragma unroll
    for (int a = 0; a < 4; a++)
#pragma unroll
        for (int b = 0; b < 4; b++)
#pragma unroll
            for (int c = 0; c < 4; c++) acc[a][b][c] = 0.f;

    auto compute = [&](int buf) {
        uint32_t* As = dyn + buf * SW;
        uint32_t* Bs = dyn + buf * SW + AW;
#pragma unroll
        for (int ks = 0; ks < 32; ks += 8) {
            uint32_t bf[4][2];
#pragma unroll
            for (int nt = 0; nt < 4; nt++) {
                int col = wn + nt * 8 + gID;
                bf[nt][0] = Bs[(ks + tig) * 136 + col];
                bf[nt][1] = Bs[(ks + tig + 4) * 136 + col];
            }
#pragma unroll
            for (int mt = 0; mt < 4; mt++) {
                int row = wm + mt * 16 + gID;
                uint32_t a0 = As[row * 36 + ks + tig] + 0x1000u;
                uint32_t a1 = As[(row + 8) * 36 + ks + tig] + 0x1000u;
                uint32_t a2 = As[row * 36 + ks + tig + 4] + 0x1000u;
                uint32_t a3 = As[(row + 8) * 36 + ks + tig + 4] + 0x1000u;
#pragma unroll
                for (int nt = 0; nt < 4; nt++) {
                    asm volatile(
                        "mma.sync.aligned.m16n8k8.row.col.f32.tf32.tf32.f32 "
                        "{%0,%1,%2,%3}, {%4,%5,%6,%7}, {%8,%9}, {%0,%1,%2,%3};\n"
                        : "+f"(acc[mt][nt][0]), "+f"(acc[mt][nt][1]),
                          "+f"(acc[mt][nt][2]), "+f"(acc[mt][nt][3])
                        : "r"(a0), "r"(a1), "r"(a2), "r"(a3),
                          "r"(bf[nt][0]), "r"(bf[nt][1]));
                }
            }
        }
    };

    int nk = K >> 5;
    stage(0, 0);
    if (nk > 1) stage(1, 32);
    for (int ki = 0; ki < nk; ki++) {
        if (ki < nk - 1) asm volatile("cp.async.wait_group 1;\n");
        else             asm volatile("cp.async.wait_group 0;\n");
        __syncthreads();
        int kn = ki + 2;
        if (kn < nk) stage(kn % 3, kn << 5);
        compute(ki % 3);
    }

#pragma unroll
    for (int mt = 0; mt < 4; mt++) {
        int row0 = rowBase + wm + mt * 16 + gID;
#pragma unroll
        for (int nt = 0; nt < 4; nt++) {
            int col = colBase + wn + nt * 8 + tig * 2;
            float b0 = 0.f, b1 = 0.f;
            if (bias) { b0 = bias[col]; b1 = bias[col + 1]; }
            float v[4];
            v[0] = acc[mt][nt][0] + b0;
            v[1] = acc[mt][nt][1] + b1;
            v[2] = acc[mt][nt][2] + b0;
            v[3] = acc[mt][nt][3] + b1;
            if (ACT == 2) {
#pragma unroll
                for (int q = 0; q < 4; q++)
                    v[q] = 0.5f * v[q] * (1.f + erff(v[q] * 0.70710678118654752f));
            }
            *(float2*)&C[(long)row0 * N + col] = make_float2(v[0], v[1]);
            *(float2*)&C[(long)(row0 + 8) * N + col] = make_float2(v[2], v[3]);
        }
    }
}

// ---------------------------------------------------------------------------
// TF32 GEMM, 256 threads, 64x128 tile, BK=32, 3-stage pipeline (plain store).
// NG: guarded N (colBase==0). DTF: fuse dt=softplus(dbc[:,:8]@dtw+dtb).
// ---------------------------------------------------------------------------
template<int ACT, bool NG, bool DTF>
__global__ void __launch_bounds__(256, 2)
tf64_kernel(const float* __restrict__ A,
            const float* __restrict__ W,
            const float* __restrict__ bias,
            float* __restrict__ C,
            int M, int N, int K,
            long sAg, long sWg, long sCg,
            const float* __restrict__ dtw,
            const float* __restrict__ dtb,
            float* __restrict__ DTout)
{
    extern __shared__ uint32_t dyn[];
    constexpr int AW = 64 * 36;
    constexpr int SW = AW + 32 * 136;

    int g = blockIdx.z;
    A += (long)g * sAg;
    W += (long)g * sWg;
    C += (long)g * sCg;
    if (DTF) {
        dtw += (long)g * 2048;
        dtb += (long)g * 256;
        DTout += (long)g * MTOK * 256;
    }

    int tid  = threadIdx.x;
    int warp = tid >> 5;
    int lane = tid & 31;
    int wm = (warp & 1) * 32;
    int wn = (warp >> 1) * 32;
    int gID = lane >> 2;
    int tig = lane & 3;
    int rowBase = blockIdx.y * 64;
    int colBase = blockIdx.x * 128;

    const float* Abase = A + (long)rowBase * K;
    const float* Wbase = W + colBase;

    if (NG) {
#pragma unroll
        for (int s = 0; s < 3; s++) {
            uint32_t* Bs = dyn + s * SW + AW;
            for (int f = tid; f < 1024; f += 256) {
                int kr = f >> 5, n4 = (f & 31) * 4;
                if (n4 + 4 > N)
                    *(uint4*)&Bs[kr * 136 + n4] = make_uint4(0, 0, 0, 0);
            }
        }
        __syncthreads();
    }

    auto stage = [&](int buf, int k0) {
        uint32_t* As = dyn + buf * SW;
        uint32_t* Bs = dyn + buf * SW + AW;
#pragma unroll
        for (int it = 0; it < 2; it++) {
            int f = tid + it * 256;
            int r = f >> 3, k4 = (f & 7) * 4;
            asm volatile("cp.async.ca.shared.global [%0], [%1], 16;\n"
                         :: "r"(smem_u32(&As[r * 36 + k4])),
                            "l"(Abase + (long)r * K + k0 + k4));
        }
#pragma unroll
        for (int it = 0; it < 4; it++) {
            int f = tid + it * 256;
            int kr = f >> 5, n4 = (f & 31) * 4;
            if (!NG || n4 + 4 <= N)
                asm volatile("cp.async.ca.shared.global [%0], [%1], 16;\n"
                             :: "r"(smem_u32(&Bs[kr * 136 + n4])),
                                "l"(Wbase + (long)(k0 + kr) * N + n4));
        }
        asm volatile("cp.async.commit_group;\n");
    };

    float acc[2][4][4];
#pragma unroll
    for (int a = 0; a < 2; a++)
#pragma unroll
        for (int b = 0; b < 4; b++)
#pragma unroll
            for (int c = 0; c < 4; c++) acc[a][b][c] = 0.f;

    auto compute = [&](int buf) {
        uint32_t* As = dyn + buf * SW;
        uint32_t* Bs = dyn + buf * SW + AW;
#pragma unroll
        for (int ks = 0; ks < 32; ks += 8) {
            uint32_t bf[4][2];
#pragma unroll
            for (int nt = 0; nt < 4; nt++) {
                int col = wn + nt * 8 + gID;
                bf[nt][0] = Bs[(ks + tig) * 136 + col];
                bf[nt][1] = Bs[(ks + tig + 4) * 136 + col];
            }
#pragma unroll
            for (int mt = 0; mt < 2; mt++) {
                int row = wm + mt * 16 + gID;
                uint32_t a0 = As[row * 36 + ks + tig] + 0x1000u;
                uint32_t a1 = As[(row + 8) * 36 + ks + tig] + 0x1000u;
                uint32_t a2 = As[row * 36 + ks + tig + 4] + 0x1000u;
                uint32_t a3 = As[(row + 8) * 36 + ks + tig + 4] + 0x1000u;
#pragma unroll
                for (int nt = 0; nt < 4; nt++) {
                    asm volatile(
                        "mma.sync.aligned.m16n8k8.row.col.f32.tf32.tf32.f32 "
                        "{%0,%1,%2,%3}, {%4,%5,%6,%7}, {%8,%9}, {%0,%1,%2,%3};\n"
                        : "+f"(acc[mt][nt][0]), "+f"(acc[mt][nt][1]),
                          "+f"(acc[mt][nt][2]), "+f"(acc[mt][nt][3])
                        : "r"(a0), "r"(a1), "r"(a2), "r"(a3),
                          "r"(bf[nt][0]), "r"(bf[nt][1]));
                }
            }
        }
    };

    int nk = K >> 5;
    stage(0, 0);
    if (nk > 1) stage(1, 32);
    for (int ki = 0; ki < nk; ki++) {
        if (ki < nk - 1) asm volatile("cp.async.wait_group 1;\n");
        else             asm volatile("cp.async.wait_group 0;\n");
        __syncthreads();
        int kn = ki + 2;
        if (kn < nk) stage(kn % 3, kn << 5);
        compute(ki % 3);
    }

#pragma unroll
    for (int mt = 0; mt < 2; mt++) {
        int row0 = rowBase + wm + mt * 16 + gID;
#pragma unroll
        for (int nt = 0; nt < 4; nt++) {
            int col = colBase + wn + nt * 8 + tig * 2;
            if (NG && col >= N) continue;
            float b0 = 0.f, b1 = 0.f;
            if (bias) { b0 = bias[col]; b1 = bias[col + 1]; }
            float v[4];
            v[0] = acc[mt][nt][0] + b0;
            v[1] = acc[mt][nt][1] + b1;
            v[2] = acc[mt][nt][2] + b0;
            v[3] = acc[mt][nt][3] + b1;
            if (ACT == 2) {
#pragma unroll
                for (int q = 0; q < 4; q++)
                    v[q] = 0.5f * v[q] * (1.f + erff(v[q] * 0.70710678118654752f));
            }
            *(float2*)&C[(long)row0 * N + col] = make_float2(v[0], v[1]);
            *(float2*)&C[(long)(row0 + 8) * N + col] = make_float2(v[2], v[3]);
        }
    }

    if (DTF) {
        float* dbs = (float*)(dyn + 3 * SW);   // [64][8]
        if (warp < 2) {
            int col = tig * 2;
#pragma unroll
            for (int mt = 0; mt < 2; mt++) {
#pragma unroll
                for (int h = 0; h < 2; h++) {
                    int rl = wm + mt * 16 + gID + h * 8;
                    dbs[rl * 8 + col]     = acc[mt][0][h * 2];
                    dbs[rl * 8 + col + 1] = acc[mt][0][h * 2 + 1];
                }
            }
        }
        __syncthreads();
        int d = tid;
        float wreg[8];
#pragma unroll
        for (int r = 0; r < 8; r++) wreg[r] = dtw[r * 256 + d];
        float bb = dtb[d];
        float* dto = DTout + (long)rowBase * 256 + d;
        for (int r = 0; r < 64; r++) {
            float s = bb;
#pragma unroll
            for (int j = 0; j < 8; j++) s = fmaf(dbs[r * 8 + j], wreg[j], s);
            s = (s > 20.f) ? s : log1pf(expf(s));
            dto[(long)r * 256] = s;
        }
    }
}

// ---------------------------------------------------------------------------
// Fused out-projection: C = y0 @ Wc[0] + y1[rev] @ Wc[1] + bias  ([M,256])
// Wc: composed [2][256][256]. 64x128 tile, 16 K-slabs (2 groups x 8).
// ---------------------------------------------------------------------------
__global__ void __launch_bounds__(256, 2)
outop_kernel(const float* __restrict__ Y,
             const float* __restrict__ Wc,
             const float* __restrict__ bias,
             float* __restrict__ C)
{
    extern __shared__ uint32_t dyn[];
    constexpr int AW = 64 * 36;
    constexpr int SW = AW + 32 * 136;
    constexpr int N = 256;

    int tid  = threadIdx.x;
    int warp = tid >> 5;
    int lane = tid & 31;
    int wm = (warp & 1) * 32;
    int wn = (warp >> 1) * 32;
    int gID = lane >> 2;
    int tig = lane & 3;
    int rowBase = blockIdx.y * 64;
    int colBase = blockIdx.x * 128;

    auto stage = [&](int buf, int s) {
        int g = s >> 3;
        int k0 = (s & 7) << 5;
        const float* Ab = Y + (long)g * MTOK * 256;
        const float* Wb = Wc + (long)g * 65536 + colBase;
        uint32_t* As = dyn + buf * SW;
        uint32_t* Bs = dyn + buf * SW + AW;
#pragma unroll
        for (int it = 0; it < 2; it++) {
            int f = tid + it * 256;
            int r = f >> 3, k4 = (f & 7) * 4;
            int m = rowBase + r;
            if (g) m = (m & ~511) + 511 - (m & 511);
            asm volatile("cp.async.ca.shared.global [%0], [%1], 16;\n"
                         :: "r"(smem_u32(&As[r * 36 + k4])),
                            "l"(Ab + (long)m * 256 + k0 + k4));
        }
#pragma unroll
        for (int it = 0; it < 4; it++) {
            int f = tid + it * 256;
            int kr = f >> 5, n4 = (f & 31) * 4;
            asm volatile("cp.async.ca.shared.global [%0], [%1], 16;\n"
                         :: "r"(smem_u32(&Bs[kr * 136 + n4])),
                            "l"(Wb + (long)(k0 + kr) * N + n4));
        }
        asm volatile("cp.async.commit_group;\n");
    };

    float acc[2][4][4];
#pragma unroll
    for (int a = 0; a < 2; a++)
#pragma unroll
        for (int b = 0; b < 4; b++)
#pragma unroll
            for (int c = 0; c < 4; c++) acc[a][b][c] = 0.f;

    auto compute = [&](int buf) {
        uint32_t* As = dyn + buf * SW;
        uint32_t* Bs = dyn + buf * SW + AW;
#pragma unroll
        for (int ks = 0; ks < 32; ks += 8) {
            uint32_t bf[4][2];
#pragma unroll
            for (int nt = 0; nt < 4; nt++) {
                int col = wn + nt * 8 + gID;
                bf[nt][0] = Bs[(ks + tig) * 136 + col];
                bf[nt][1] = Bs[(ks + tig + 4) * 136 + col];
            }
#pragma unroll
            for (int mt = 0; mt < 2; mt++) {
                int row = wm + mt * 16 + gID;
                uint32_t a0 = As[row * 36 + ks + tig] + 0x1000u;
                uint32_t a1 = As[(row + 8) * 36 + ks + tig] + 0x1000u;
                uint32_t a2 = As[row * 36 + ks + tig + 4] + 0x1000u;
                uint32_t a3 = As[(row + 8) * 36 + ks + tig + 4] + 0x1000u;
#pragma unroll
                for (int nt = 0; nt < 4; nt++) {
                    asm volatile(
                        "mma.sync.aligned.m16n8k8.row.col.f32.tf32.tf32.f32 "
                        "{%0,%1,%2,%3}, {%4,%5,%6,%7}, {%8,%9}, {%0,%1,%2,%3};\n"
                        : "+f"(acc[mt][nt][0]), "+f"(acc[mt][nt][1]),
                          "+f"(acc[mt][nt][2]), "+f"(acc[mt][nt][3])
                        : "r"(a0), "r"(a1), "r"(a2), "r"(a3),
                          "r"(bf[nt][0]), "r"(bf[nt][1]));
                }
            }
        }
    };

    stage(0, 0);
    stage(1, 1);
    for (int s = 0; s < 16; s++) {
        if (s < 15) asm volatile("cp.async.wait_group 1;\n");
        else        asm volatile("cp.async.wait_group 0;\n");
        __syncthreads();
        int sn = s + 2;
        if (sn < 16) stage(sn % 3, sn);
        compute(s % 3);
    }

#pragma unroll
    for (int mt = 0; mt < 2; mt++) {
        int row0 = rowBase + wm + mt * 16 + gID;
#pragma unroll
        for (int nt = 0; nt < 4; nt++) {
            int col = colBase + wn + nt * 8 + tig * 2;
            float b0 = bias[col], b1 = bias[col + 1];
            *(float2*)&C[(long)row0 * N + col] =
                make_float2(acc[mt][nt][0] + b0, acc[mt][nt][1] + b1);
            *(float2*)&C[(long)(row0 + 8) * N + col] =
                make_float2(acc[mt][nt][2] + b0, acc[mt][nt][3] + b1);
        }
    }
}

// ---------------------------------------------------------------------------
// depthwise causal conv (K=4) + bias + silu; 4 t-outputs per thread
// ---------------------------------------------------------------------------
__global__ void conv_silu_kernel(const float* __restrict__ xz,
                                 const float* __restrict__ convw,
                                 const float* __restrict__ convb,
                                 float* __restrict__ xc)
{
    long i = (long)blockIdx.x * 256 + threadIdx.x;
    if (i >= 2 * MTOK * 64) return;
    int d = (int)(i & 255);
    long q = i >> 8;
    int t0 = (int)(q & 127) * 4;
    int b  = (int)((q >> 7) & 15);
    int g  = (int)(q >> 11);

    const float4 w4 = *(const float4*)(convw + ((long)g * 256 + d) * 4);
    float bias = convb[(long)g * 256 + d];

    long mrow = (long)g * MTOK + (long)b * 512 + t0;
    const float* xp = xz + mrow * 512 + d;
    float xv[7];
#pragma unroll
    for (int j = 0; j < 7; j++) {
        int t = t0 - 3 + j;
        xv[j] = (t >= 0) ? xp[(long)(j - 3) * 512] : 0.f;
    }
    float* op = xc + mrow * 256 + d;
#pragma unroll
    for (int j = 0; j < 4; j++) {
        float acc = bias;
        acc = fmaf(xv[j],     w4.x, acc);
        acc = fmaf(xv[j + 1], w4.y, acc);
        acc = fmaf(xv[j + 2], w4.z, acc);
        acc = fmaf(xv[j + 3], w4.w, acc);
        op[(long)j * 256] = acc / (1.f + __expf(-acc));
    }
}

// ---------------------------------------------------------------------------
// Selective scan, 8 lanes per (g,b,d) group, 2 states per lane, pipelined.
// ---------------------------------------------------------------------------
__global__ void __launch_bounds__(256)
scan_kernel(const float* __restrict__ dt,
            const float* __restrict__ xc,
            const float* __restrict__ dbc,
            const float* __restrict__ xz,
            const float* __restrict__ alog,
            const float* __restrict__ dpar,
            float* __restrict__ y)
{
    int gidx = blockIdx.x * 32 + (threadIdx.x >> 3);
    int li = threadIdx.x & 7;
    int g = gidx >> 12;
    int b = (gidx >> 8) & 15;
    int d = gidx & 255;

    const float2 al = *(const float2*)&alog[((long)(g * 256 + d)) * 16 + li * 2];
    const float L2E = 1.4426950408889634f;
    float A0 = -__expf(al.x) * L2E;
    float A1 = -__expf(al.y) * L2E;
    float dp = dpar[(long)g * 256 + d];

    long mbase = (long)g * MTOK + (long)b * 512;
    const float* dtp = dt + mbase * 256 + d;
    const float* xcp = xc + mbase * 256 + d;
    const float* dbp = dbc + mbase * 40;
    const float* zp  = xz + mbase * 512 + 256 + d;
    float* yp = y + mbase * 256 + d;

    float h0 = 0.f, h1 = 0.f;

    float dtv_n = dtp[0];
    float xv_n  = xcp[0];
    float z_n   = zp[0];
    float2 B_n  = *(const float2*)&dbp[8 + li * 2];
    float2 C_n  = *(const float2*)&dbp[24 + li * 2];

    for (int t = 0; t < 512; t++) {
        float dtv = dtv_n, xv = xv_n, z = z_n;
        float2 Bv = B_n, Cv = C_n;
        long tn = (t + 1 < 512) ? t + 1 : 511;
        dtv_n = dtp[tn * 256];
        xv_n  = xcp[tn * 256];
        z_n   = zp[tn * 512];
        B_n   = *(const float2*)&dbp[tn * 40 + 8 + li * 2];
        C_n   = *(const float2*)&dbp[tn * 40 + 24 + li * 2];

        float dx = dtv * xv;
        h0 = exp2f(dtv * A0) * h0 + dx * Bv.x;
        h1 = exp2f(dtv * A1) * h1 + dx * Bv.y;
        float p = h0 * Cv.x + h1 * Cv.y;
        p += __shfl_xor_sync(0xffffffffu, p, 4);
        p += __shfl_xor_sync(0xffffffffu, p, 2);
        p += __shfl_xor_sync(0xffffffffu, p, 1);
        if (li == 0) {
            float sz = z / (1.f + __expf(-z));
            yp[(long)t * 256] = (p + dp * xv) * sz;
        }
    }
}

// ---------------------------------------------------------------------------
// Launch helpers
// ---------------------------------------------------------------------------
constexpr int SMEM128 = 3 * (128 * 36 + 32 * 136) * 4;        // 107520 B
constexpr int SMEM64  = 3 * (64 * 36 + 32 * 136) * 4 + 2048;  // 81920 B

template<int ACT, bool AREV>
static void launch_tf128(const float* A, const float* W, const float* bias, float* C,
                         int M, int N, int K, int lda, int G,
                         long sAg, long sWg, long sCg)
{
    cudaFuncSetAttribute(tf128_kernel<ACT, AREV>,
                         cudaFuncAttributeMaxDynamicSharedMemorySize, SMEM128);
    dim3 grid(N / 128, M / 128, G);
    tf128_kernel<ACT, AREV><<<grid, 256, SMEM128>>>(A, W, bias, C, M, N, K, lda,
                                                    sAg, sWg, sCg);
}

template<int ACT, bool NG, bool DTF>
static void launch_tf64(const float* A, const float* W, const float* bias, float* C,
                        int M, int N, int K, int G,
                        long sAg, long sWg, long sCg,
                        const float* dtw = nullptr, const float* dtb = nullptr,
                        float* DTout = nullptr)
{
    cudaFuncSetAttribute(tf64_kernel<ACT, NG, DTF>,
                         cudaFuncAttributeMaxDynamicSharedMemorySize, SMEM64);
    dim3 grid((N + 127) / 128, M / 64, G);
    tf64_kernel<ACT, NG, DTF><<<grid, 256, SMEM64>>>(
        A, W, bias, C, M, N, K, sAg, sWg, sCg, dtw, dtb, DTout);
}

extern "C" void kernel_launch(void* const* d_in, const int* in_sizes, int n_in,
                              void* d_out, int out_size)
{
    const float* input_ids = (const float*)d_in[0];
    const float* proj_w    = (const float*)d_in[1];
    const float* proj_b    = (const float*)d_in[2];
    const float* ln0_g     = (const float*)d_in[3];
    const float* ln0_b     = (const float*)d_in[4];
    const float* ln1_g     = (const float*)d_in[5];
    const float* ln1_b     = (const float*)d_in[6];
    const float* ip_w      = (const float*)d_in[7];
    const float* ip_b      = (const float*)d_in[8];
    const float* s_inw     = (const float*)d_in[9];
    const float* s_convw   = (const float*)d_in[10];
    const float* s_convb   = (const float*)d_in[11];
    const float* s_xw      = (const float*)d_in[12];
    const float* s_dtw     = (const float*)d_in[13];
    const float* s_dtb     = (const float*)d_in[14];
    const float* s_alog    = (const float*)d_in[15];
    const float* s_d       = (const float*)d_in[16];
    const float* s_outw    = (const float*)d_in[17];
    const float* op_w      = (const float*)d_in[18];
    const float* op_b      = (const float*)d_in[19];
    const float* ln2_g     = (const float*)d_in[20];
    const float* ln2_b     = (const float*)d_in[21];
    const float* f_w1      = (const float*)d_in[22];
    const float* f_b1      = (const float*)d_in[23];
    const float* f_w2      = (const float*)d_in[24];
    const float* f_b2      = (const float*)d_in[25];
    const float* ln3_g     = (const float*)d_in[26];
    const float* ln3_b     = (const float*)d_in[27];

    float* base = nullptr;
    cudaGetSymbolAddress((void**)&base, g_buf);

    float* X    = base + OFF_X;
    float* LNb  = base + OFF_LN;
    float* B256 = base + OFF_B256;
    float* XZ   = base + OFF_XZ;
    float* XC   = base + OFF_XC;
    float* DBC  = base + OFF_DBC;
    float* DT   = base + OFF_DT;
    float* Y    = base + OFF_Y;
    float* FF   = base + OFF_FF;
    float* W2C  = base + OFF_W2C;

    const int M = (int)MTOK;
    const int CONV_BLOCKS = (int)(2 * MTOK * 64 / 256);
    const int LN_BLOCKS = (int)(MTOK / 8);

    // Precompute composed out-proj weights: W2C[l][g] = outw[l][g] @ opw[l][gpart]
    // (batched: 24 groups of [256,128]@[128,256])
    launch_tf64<0, false, false>(s_outw, op_w, nullptr, W2C,
                                 256, 256, 128, 24, 32768, 32768, 65536);

    embed_ln_kernel<<<M, 256>>>(input_ids, proj_w, proj_b, ln0_g, ln0_b, X);
    ln_kernel<<<LN_BLOCKS, 256>>>(X, nullptr, ln1_g, ln1_b, LNb);

    for (int l = 0; l < 12; l++) {
        // in-proj h = LN1 @ ip_w + ip_b -> B256 (plain)
        launch_tf64<0, false, false>(LNb, ip_w + (long)l * 256 * 256, ip_b + l * 256,
                                     B256, M, 256, 256, 1, 0, 0, 0);
        // xz = h-slice @ inw (group col offset + row reversal for g=1)
        launch_tf128<0, true>(B256, s_inw + (long)l * 2 * 128 * 512, nullptr, XZ,
                              M, 512, 128, 256, 2, 128, 128 * 512, MTOK * 512);
        // conv + silu
        conv_silu_kernel<<<CONV_BLOCKS, 256>>>(XZ, s_convw + (long)l * 2 * 256 * 4,
                                               s_convb + (long)l * 2 * 256, XC);
        // dbc = xc @ xw (N=40 guarded) + fused dt
        launch_tf64<0, true, true>(XC, s_xw + (long)l * 2 * 256 * 40, nullptr, DBC,
                                   M, 40, 256, 2, MTOK * 256, 256 * 40, MTOK * 40,
                                   s_dtw + (long)l * 2 * 8 * 256,
                                   s_dtb + (long)l * 2 * 256, DT);
        // selective scan + fused silu(z) gate
        scan_kernel<<<256, 256>>>(DT, XC, DBC, XZ,
                                  s_alog + (long)l * 2 * 256 * 16,
                                  s_d + (long)l * 2 * 256, Y);
        // fused outw∘opw projection (+op_b) -> B256
        {
            dim3 grid(2, M / 64, 1);
            cudaFuncSetAttribute(outop_kernel,
                                 cudaFuncAttributeMaxDynamicSharedMemorySize, SMEM64);
            outop_kernel<<<grid, 256, SMEM64>>>(Y, W2C + (long)l * 2 * 65536,
                                                op_b + l * 256, B256);
        }
        // LN2 (residual)
        ln_kernel<<<LN_BLOCKS, 256>>>(B256, X, ln2_g + l * 256, ln2_b + l * 256, X);
        // ff = gelu(x @ w1 + b1)
        launch_tf128<2, false>(X, f_w1 + (long)l * 256 * 1024, f_b1 + l * 1024, FF,
                               M, 1024, 256, 256, 1, 0, 0, 0);
        // f = ff @ w2 + b2
        launch_tf64<0, false, false>(FF, f_w2 + (long)l * 1024 * 256, f_b2 + l * 256,
                                     B256, M, 256, 1024, 1, 0, 0, 0);
        // LN3 fused with next layer's LN1
        float* dst = (l == 11) ? (float*)d_out : X;
        float* lnb = (l == 11) ? nullptr : LNb;
        const float* g1 = ln1_g + (l + 1 < 12 ? (l + 1) * 256 : 0);
        const float* b1 = ln1_b + (l + 1 < 12 ? (l + 1) * 256 : 0);
        ln3ln1_kernel<<<LN_BLOCKS, 256>>>(B256, X, ln3_g + l * 256, ln3_b + l * 256,
                                          g1, b1, dst, lnb);
    }
}